// round 1
// baseline (speedup 1.0000x reference)
#include <cuda_runtime.h>
#include <math.h>

// ---------------- problem constants ----------------
#define NB      1024
#define SS      128
#define DD      128
#define HH      4
#define CC      32
#define LL      2
#define M_ROWS  (NB * SS)          // 131072
#define MSZ     (M_ROWS * DD)      // 16777216 floats = 64 MB
#define EPS     1e-5f
#define INV_M   (1.0f / (float)M_ROWS)

// ---------------- scratch (device globals; no allocation allowed) ----------------
__device__ float g_h[MSZ];
__device__ float g_t[MSZ];
__device__ float g_q[MSZ];
__device__ float g_k[MSZ];
__device__ float g_v[MSZ];
__device__ float g_a[MSZ];
__device__ float g_o[MSZ];
__device__ float g_f[MSZ];
__device__ float g_sum[DD];
__device__ float g_sq[DD];

// ---------------- GEMM: C[M,128] = A[M,128] @ W[128,128]^T + bias ----------------
// Block: 128 rows x 128 cols, 256 threads, 8x8 register tile per thread.
// Whole A tile + whole W (transposed) staged in smem with padded strides.
#define AS_STRIDE 130
#define WS_STRIDE 132
#define GEMM_SMEM ((128 * AS_STRIDE + 128 * WS_STRIDE) * 4)

__global__ void gemm_bias_kernel(const float* __restrict__ A,
                                 const float* __restrict__ W,
                                 const float* __restrict__ bias,
                                 float* __restrict__ C) {
    extern __shared__ float sm[];
    float* As = sm;                       // [128][AS_STRIDE]
    float* Ws = sm + 128 * AS_STRIDE;     // k-major: Ws[k*WS_STRIDE + j]

    const int tid = threadIdx.x;
    const long rowBase = (long)blockIdx.x * 128;

    for (int idx = tid; idx < 128 * 128; idx += 256) {
        int r = idx >> 7, k = idx & 127;
        As[r * AS_STRIDE + k] = A[(rowBase + r) * 128 + k];
    }
    for (int idx = tid; idx < 128 * 128; idx += 256) {
        int j = idx >> 7, k = idx & 127;
        Ws[k * WS_STRIDE + j] = W[idx];
    }
    __syncthreads();

    const int tx = tid & 15, ty = tid >> 4;
    const int r0 = ty * 4, c0 = tx * 4;

    float acc[8][8];
#pragma unroll
    for (int i = 0; i < 8; i++)
#pragma unroll
        for (int j = 0; j < 8; j++) acc[i][j] = 0.0f;

#pragma unroll 8
    for (int kk = 0; kk < 128; kk++) {
        float a[8], b[8];
#pragma unroll
        for (int i = 0; i < 4; i++) {
            a[i]     = As[(r0 + i) * AS_STRIDE + kk];
            a[i + 4] = As[(r0 + 64 + i) * AS_STRIDE + kk];
        }
        float4 b0 = *(const float4*)(Ws + kk * WS_STRIDE + c0);
        float4 b1 = *(const float4*)(Ws + kk * WS_STRIDE + 64 + c0);
        b[0] = b0.x; b[1] = b0.y; b[2] = b0.z; b[3] = b0.w;
        b[4] = b1.x; b[5] = b1.y; b[6] = b1.z; b[7] = b1.w;
#pragma unroll
        for (int i = 0; i < 8; i++)
#pragma unroll
            for (int j = 0; j < 8; j++) acc[i][j] += a[i] * b[j];
    }

    float4 bb0 = *(const float4*)(bias + c0);
    float4 bb1 = *(const float4*)(bias + 64 + c0);
#pragma unroll
    for (int i = 0; i < 8; i++) {
        int row = (i < 4) ? (r0 + i) : (r0 + 64 + (i - 4));
        float4 y0, y1;
        y0.x = acc[i][0] + bb0.x; y0.y = acc[i][1] + bb0.y;
        y0.z = acc[i][2] + bb0.z; y0.w = acc[i][3] + bb0.w;
        y1.x = acc[i][4] + bb1.x; y1.y = acc[i][5] + bb1.y;
        y1.z = acc[i][6] + bb1.z; y1.w = acc[i][7] + bb1.w;
        *(float4*)(C + (rowBase + row) * 128 + c0)      = y0;
        *(float4*)(C + (rowBase + row) * 128 + 64 + c0) = y1;
    }
}

// ---------------- BatchNorm over all rows (axis 0,1), per column ----------------
__global__ void bn_zero_kernel() {
    g_sum[threadIdx.x] = 0.0f;
    g_sq[threadIdx.x]  = 0.0f;
}

__global__ void bn_stats_kernel(const float* __restrict__ A) {
    const int c = threadIdx.x;                  // 128 threads: one column each
    const long r0 = (long)blockIdx.x * 128;     // 1024 blocks x 128 rows
    float s = 0.0f, s2 = 0.0f;
    for (int r = 0; r < 128; r++) {
        float v = A[(r0 + r) * 128 + c];
        s += v; s2 += v * v;
    }
    atomicAdd(&g_sum[c], s);
    atomicAdd(&g_sq[c], s2);
}

__global__ void bn_apply_kernel(const float* __restrict__ A,
                                const float* __restrict__ gam,
                                const float* __restrict__ bet,
                                float* __restrict__ Out) {
    __shared__ float sc[128], sh[128];
    const int tid = threadIdx.x;
    if (tid < 128) {
        float m = g_sum[tid] * INV_M;
        float v = g_sq[tid] * INV_M - m * m;
        float s = gam[tid] * rsqrtf(v + EPS);
        sc[tid] = s;
        sh[tid] = bet[tid] - m * s;
    }
    __syncthreads();
    long i = ((long)blockIdx.x * blockDim.x + tid) * 4;
    const long stride = (long)gridDim.x * blockDim.x * 4;
    for (; i < MSZ; i += stride) {
        float4 x = *(const float4*)(A + i);
        int c = (int)(i & 127);
        float4 y;
        y.x = x.x * sc[c]     + sh[c];
        y.y = x.y * sc[c + 1] + sh[c + 1];
        y.z = x.z * sc[c + 2] + sh[c + 2];
        y.w = x.w * sc[c + 3] + sh[c + 3];
        *(float4*)(Out + i) = y;
    }
}

// ---------------- Attention: one block per (n, head), one thread per query row ----------------
#define AL_STRIDE 129
#define ATTN_SMEM ((4096 + 4096 + 128 * AL_STRIDE) * 4)   // 98816 B

__global__ void attn_kernel(const float* __restrict__ q,
                            const float* __restrict__ k,
                            const float* __restrict__ v,
                            const float* __restrict__ mask,
                            float* __restrict__ out) {
    extern __shared__ float sm[];
    float* ks = sm;            // [128][32]
    float* vs = sm + 4096;     // [128][32]
    float* al = sm + 8192;     // [128][AL_STRIDE], also used to stage mask

    const int h = blockIdx.x;
    const int n = blockIdx.y;
    const int s = threadIdx.x;                    // 128 threads
    const long base = (long)n * SS * DD + h * CC; // + row*128 + c

    for (int idx = s; idx < 4096; idx += 128) {
        int t = idx >> 5, c = idx & 31;
        ks[idx] = k[base + (long)t * 128 + c];
        vs[idx] = v[base + (long)t * 128 + c];
    }
    const long mbase = (long)n * SS * SS;
    for (int idx = s; idx < 16384; idx += 128) {
        al[(idx >> 7) * AL_STRIDE + (idx & 127)] = mask[mbase + idx];
    }
    __syncthreads();

    float qr[32];
#pragma unroll
    for (int c = 0; c < 32; c++) qr[c] = q[base + (long)s * 128 + c];

    float* arow = al + s * AL_STRIDE;

    float mx = -1e30f;
    for (int t = 0; t < 128; t++) {
        const float4* k4 = (const float4*)(ks + t * 32);
        float d = 0.0f;
#pragma unroll
        for (int cc = 0; cc < 8; cc++) {
            float4 kv = k4[cc];
            d += qr[cc * 4]     * kv.x;
            d += qr[cc * 4 + 1] * kv.y;
            d += qr[cc * 4 + 2] * kv.z;
            d += qr[cc * 4 + 3] * kv.w;
        }
        float a = d * arow[t];     // alpha = (q.k) * mask
        arow[t] = a;
        mx = fmaxf(mx, a);
    }

    float ssum = 0.0f;
    for (int t = 0; t < 128; t++) {
        float p = __expf(arow[t] - mx);
        arow[t] = p;
        ssum += p;
    }
    const float inv = 1.0f / ssum;

    float acc[32];
#pragma unroll
    for (int c = 0; c < 32; c++) acc[c] = 0.0f;
    for (int t = 0; t < 128; t++) {
        float p = arow[t];
        const float4* v4 = (const float4*)(vs + t * 32);
#pragma unroll
        for (int cc = 0; cc < 8; cc++) {
            float4 vv = v4[cc];
            acc[cc * 4]     += p * vv.x;
            acc[cc * 4 + 1] += p * vv.y;
            acc[cc * 4 + 2] += p * vv.z;
            acc[cc * 4 + 3] += p * vv.w;
        }
    }
#pragma unroll
    for (int c = 0; c < 32; c++) out[base + (long)s * 128 + c] = acc[c] * inv;
}

// ---------------- out = LayerNorm(A + B) per row (D=128), warp per row ----------------
__global__ void add_ln_kernel(const float* __restrict__ A,
                              const float* __restrict__ B,
                              const float* __restrict__ gam,
                              const float* __restrict__ bet,
                              float* __restrict__ Out) {
    const int w = threadIdx.x >> 5, lane = threadIdx.x & 31;
    const long row = (long)blockIdx.x * 8 + w;
    const float* a = A + row * 128;
    const float* b = B + row * 128;

    float x[4];
    float s = 0.0f, s2 = 0.0f;
#pragma unroll
    for (int i = 0; i < 4; i++) {
        int c = lane + 32 * i;
        x[i] = a[c] + b[c];
        s += x[i];
        s2 += x[i] * x[i];
    }
#pragma unroll
    for (int o = 16; o > 0; o >>= 1) {
        s  += __shfl_xor_sync(0xffffffffu, s, o);
        s2 += __shfl_xor_sync(0xffffffffu, s2, o);
    }
    const float m = s * (1.0f / 128.0f);
    const float var = s2 * (1.0f / 128.0f) - m * m;
    const float r = rsqrtf(var + EPS);
#pragma unroll
    for (int i = 0; i < 4; i++) {
        int c = lane + 32 * i;
        Out[row * 128 + c] = (x[i] - m) * r * gam[c] + bet[c];
    }
}

// ---------------- h = A + B ----------------
__global__ void add_kernel(const float* __restrict__ A,
                           const float* __restrict__ B,
                           float* __restrict__ Out) {
    long i = ((long)blockIdx.x * blockDim.x + threadIdx.x) * 4;
    const long stride = (long)gridDim.x * blockDim.x * 4;
    for (; i < MSZ; i += stride) {
        float4 a = *(const float4*)(A + i);
        float4 b = *(const float4*)(B + i);
        float4 y;
        y.x = a.x + b.x; y.y = a.y + b.y; y.z = a.z + b.z; y.w = a.w + b.w;
        *(float4*)(Out + i) = y;
    }
}

// ---------------- gather h[:, 0] -> out[N, D] ----------------
__global__ void gather_kernel(const float* __restrict__ H, float* __restrict__ Out) {
    int i = blockIdx.x * blockDim.x + threadIdx.x;   // 131072 elements
    int n = i >> 7, d = i & 127;
    Out[i] = H[(long)n * SS * DD + d];
}

// ---------------- host orchestration ----------------
extern "C" void kernel_launch(void* const* d_in, const int* in_sizes, int n_in,
                              void* d_out, int out_size) {
    const float* x        = (const float*)d_in[0];
    const float* mask     = (const float*)d_in[1];
    const float* lin_in_W = (const float*)d_in[2];
    const float* lin_in_b = (const float*)d_in[3];
    const float* in_bn_g  = (const float*)d_in[4];
    const float* in_bn_b  = (const float*)d_in[5];
    const float* q_W      = (const float*)d_in[6];
    const float* q_b      = (const float*)d_in[7];
    const float* q_bn_g   = (const float*)d_in[8];
    const float* q_bn_b   = (const float*)d_in[9];
    const float* k_W      = (const float*)d_in[10];
    const float* k_b      = (const float*)d_in[11];
    const float* k_bn_g   = (const float*)d_in[12];
    const float* k_bn_b   = (const float*)d_in[13];
    const float* v_W      = (const float*)d_in[14];
    const float* v_b      = (const float*)d_in[15];
    const float* v_bn_g   = (const float*)d_in[16];
    const float* v_bn_b   = (const float*)d_in[17];
    const float* ln_g     = (const float*)d_in[18];
    const float* ln_b     = (const float*)d_in[19];
    const float* ff_W     = (const float*)d_in[20];
    const float* ff_b     = (const float*)d_in[21];
    const float* ff_bn_g  = (const float*)d_in[22];
    const float* ff_bn_b  = (const float*)d_in[23];
    const float* skip_W   = (const float*)d_in[24];
    const float* skip_b   = (const float*)d_in[25];
    const float* skip_bn_g= (const float*)d_in[26];
    const float* skip_bn_b= (const float*)d_in[27];
    float* out = (float*)d_out;

    cudaFuncSetAttribute(gemm_bias_kernel, cudaFuncAttributeMaxDynamicSharedMemorySize, GEMM_SMEM);
    cudaFuncSetAttribute(attn_kernel, cudaFuncAttributeMaxDynamicSharedMemorySize, ATTN_SMEM);

    float *bh, *bt, *bq, *bk, *bv, *ba, *bo, *bf;
    cudaGetSymbolAddress((void**)&bh, g_h);
    cudaGetSymbolAddress((void**)&bt, g_t);
    cudaGetSymbolAddress((void**)&bq, g_q);
    cudaGetSymbolAddress((void**)&bk, g_k);
    cudaGetSymbolAddress((void**)&bv, g_v);
    cudaGetSymbolAddress((void**)&ba, g_a);
    cudaGetSymbolAddress((void**)&bo, g_o);
    cudaGetSymbolAddress((void**)&bf, g_f);

    const int GEMM_GRID = M_ROWS / 128;   // 1024

    auto runGemm = [&](const float* A, const float* W, const float* bias, float* C) {
        gemm_bias_kernel<<<GEMM_GRID, 256, GEMM_SMEM>>>(A, W, bias, C);
    };
    auto runBN = [&](const float* src, const float* gam, const float* bet, float* dst) {
        bn_zero_kernel<<<1, 128>>>();
        bn_stats_kernel<<<1024, 128>>>(src);
        bn_apply_kernel<<<4096, 256>>>(src, gam, bet, dst);
    };

    // h = BN(x @ lin_in_W^T + b)
    runGemm(x, lin_in_W, lin_in_b, bt);
    runBN(bt, in_bn_g, in_bn_b, bh);

    for (int l = 0; l < LL; l++) {
        const long wOff = (long)l * DD * DD;
        const long vOff = (long)l * DD;

        runGemm(bh, q_W + wOff, q_b + vOff, bt);
        runBN(bt, q_bn_g + vOff, q_bn_b + vOff, bq);
        runGemm(bh, k_W + wOff, k_b + vOff, bt);
        runBN(bt, k_bn_g + vOff, k_bn_b + vOff, bk);
        runGemm(bh, v_W + wOff, v_b + vOff, bt);
        runBN(bt, v_bn_g + vOff, v_bn_b + vOff, bv);

        dim3 agrid(HH, NB);
        attn_kernel<<<agrid, 128, ATTN_SMEM>>>(bq, bk, bv, mask, ba);

        // out = LN(agg + h)
        add_ln_kernel<<<M_ROWS / 8, 256>>>(ba, bh, ln_g + vOff, ln_b + vOff, bo);

        // ff = BN(out @ ff_W^T + b); out2 = LN(out + ff)
        runGemm(bo, ff_W + wOff, ff_b + vOff, bt);
        runBN(bt, ff_bn_g + vOff, ff_bn_b + vOff, bf);
        add_ln_kernel<<<M_ROWS / 8, 256>>>(bo, bf, ln_g + vOff, ln_b + vOff, ba);

        // x_r = BN(h @ skip_W^T + b); h = out2 + x_r
        runGemm(bh, skip_W + wOff, skip_b + vOff, bt);
        runBN(bt, skip_bn_g + vOff, skip_bn_b + vOff, bf);
        add_kernel<<<4096, 256>>>(ba, bf, bh);
    }

    gather_kernel<<<(NB * DD) / 256, 256>>>(bh, out);
}

// round 2
// speedup vs baseline: 1.1296x; 1.1296x over previous
#include <cuda_runtime.h>
#include <math.h>
#include <stdint.h>

// ---------------- problem constants ----------------
#define NB      1024
#define SS      128
#define DD      128
#define HH      4
#define CC      32
#define LL      2
#define M_ROWS  (NB * SS)          // 131072
#define MSZ     (M_ROWS * DD)      // 16777216 floats = 64 MB
#define EPS     1e-5f
#define INV_M   (1.0f / (float)M_ROWS)

// ---------------- scratch (device globals; no allocation allowed) ----------------
__device__ float g_h[MSZ];   // materialized h (layer >=1)
__device__ float g_t[MSZ];   // raw t0 = x@Win^T + b (pre-BN)
__device__ float g_q[MSZ];   // raw q (pre-BN)
__device__ float g_k[MSZ];
__device__ float g_v[MSZ];
__device__ float g_a[MSZ];   // agg / out2
__device__ float g_o[MSZ];   // out (post first LN)
__device__ float g_f[MSZ];   // raw ff / raw skip
__device__ float g_sum[DD];  // BN accumulation (zeroed by finalize)
__device__ float g_sq[DD];
__device__ float g_scb[6][DD];  // BN scale per slot
__device__ float g_shb[6][DD];  // BN shift per slot

// ================= tf32 helpers =================
__device__ __forceinline__ uint32_t f2tf32(float x) {
    uint32_t r;
    asm("cvt.rna.tf32.f32 %0, %1;" : "=r"(r) : "f"(x));
    return r;
}
__device__ __forceinline__ void split_tf32(float x, uint32_t& hi, uint32_t& lo) {
    hi = f2tf32(x);
    lo = f2tf32(x - __uint_as_float(hi));
}
__device__ __forceinline__ void mma_tf32(float c[4],
                                         uint32_t a0, uint32_t a1, uint32_t a2, uint32_t a3,
                                         uint32_t b0, uint32_t b1) {
    asm volatile(
        "mma.sync.aligned.m16n8k8.row.col.f32.tf32.tf32.f32 "
        "{%0,%1,%2,%3}, {%4,%5,%6,%7}, {%8,%9}, {%0,%1,%2,%3};"
        : "+f"(c[0]), "+f"(c[1]), "+f"(c[2]), "+f"(c[3])
        : "r"(a0), "r"(a1), "r"(a2), "r"(a3), "r"(b0), "r"(b1));
}

// ================= GEMM (tensor core, tf32x3) with fused bias + BN stats =================
// C[M,128] = affine(A)[M,128] @ W[128,128]^T + bias ; accumulate column sum/sumsq atomically.
// Block: 128x128 tile, 256 threads (8 warps, 2x4), warp tile 64x32, mma m16n8k8, K=128.
// Smem layout: k permuted within groups of 8 so (k, k+4) are adjacent -> float2 frag loads.
#define ASTR 136
#define GEMM_SMEM ((2 * 128 * ASTR + 256) * 4)   // As + Ws + ssum + ssq = 140288 B

__global__ void gemm_tc_kernel(const float* __restrict__ A,
                               const float* __restrict__ W,
                               const float* __restrict__ bias,
                               const float* __restrict__ scA,
                               const float* __restrict__ shA,
                               float* __restrict__ C) {
    extern __shared__ float sm[];
    float* As   = sm;                    // [128][ASTR] row-major, k permuted
    float* Ws   = sm + 128 * ASTR;       // [128][ASTR] (row j of W), k permuted
    float* ssum = sm + 2 * 128 * ASTR;   // [128]
    float* ssq  = ssum + 128;            // [128]

    const int tid = threadIdx.x;
    const long rowBase = (long)blockIdx.x * 128;

    if (tid < 128) { ssum[tid] = 0.0f; ssq[tid] = 0.0f; }

    // fill A (with optional affine), permuting k: pos = (k & ~7) + 2*(k&3) + ((k>>2)&1)
    for (int idx = tid; idx < 128 * 32; idx += 256) {
        int r = idx >> 5, k0 = (idx & 31) * 4;
        float4 v = *(const float4*)(A + (rowBase + r) * 128 + k0);
        if (scA) {
            float4 s = *(const float4*)(scA + k0);
            float4 t = *(const float4*)(shA + k0);
            v.x = v.x * s.x + t.x; v.y = v.y * s.y + t.y;
            v.z = v.z * s.z + t.z; v.w = v.w * s.w + t.w;
        }
        float* dst = As + r * ASTR + (k0 & ~7) + ((k0 & 4) ? 1 : 0);
        dst[0] = v.x; dst[2] = v.y; dst[4] = v.z; dst[6] = v.w;
    }
    // fill W
    for (int idx = tid; idx < 128 * 32; idx += 256) {
        int j = idx >> 5, k0 = (idx & 31) * 4;
        float4 v = *(const float4*)(W + j * 128 + k0);
        float* dst = Ws + j * ASTR + (k0 & ~7) + ((k0 & 4) ? 1 : 0);
        dst[0] = v.x; dst[2] = v.y; dst[4] = v.z; dst[6] = v.w;
    }
    __syncthreads();

    const int warp = tid >> 5, lane = tid & 31;
    const int wm = warp >> 2, wn = warp & 3;      // 2 x 4 warp grid
    const int grp = lane >> 2, q4 = lane & 3;

    float acc[4][4][4];
#pragma unroll
    for (int mt = 0; mt < 4; mt++)
#pragma unroll
        for (int nt = 0; nt < 4; nt++)
#pragma unroll
            for (int i = 0; i < 4; i++) acc[mt][nt][i] = 0.0f;

    const float* aBase = As + (wm * 64 + grp) * ASTR + q4 * 2;
    const float* bBase = Ws + (wn * 32 + grp) * ASTR + q4 * 2;

#pragma unroll 4
    for (int s = 0; s < 16; s++) {
        const int so = s * 8;
        uint32_t ah[4][4], al[4][4];
#pragma unroll
        for (int mt = 0; mt < 4; mt++) {
            float2 v0 = *(const float2*)(aBase + (mt * 16) * ASTR + so);       // row r0: k, k+4
            float2 v1 = *(const float2*)(aBase + (mt * 16 + 8) * ASTR + so);   // row r0+8
            split_tf32(v0.x, ah[mt][0], al[mt][0]);
            split_tf32(v1.x, ah[mt][1], al[mt][1]);
            split_tf32(v0.y, ah[mt][2], al[mt][2]);
            split_tf32(v1.y, ah[mt][3], al[mt][3]);
        }
        uint32_t bh[4][2], bl[4][2];
#pragma unroll
        for (int nt = 0; nt < 4; nt++) {
            float2 v = *(const float2*)(bBase + (nt * 8) * ASTR + so);
            split_tf32(v.x, bh[nt][0], bl[nt][0]);
            split_tf32(v.y, bh[nt][1], bl[nt][1]);
        }
#pragma unroll
        for (int mt = 0; mt < 4; mt++)
#pragma unroll
            for (int nt = 0; nt < 4; nt++) {
                mma_tf32(acc[mt][nt], ah[mt][0], ah[mt][1], ah[mt][2], ah[mt][3], bh[nt][0], bh[nt][1]);
                mma_tf32(acc[mt][nt], ah[mt][0], ah[mt][1], ah[mt][2], ah[mt][3], bl[nt][0], bl[nt][1]);
                mma_tf32(acc[mt][nt], al[mt][0], al[mt][1], al[mt][2], al[mt][3], bh[nt][0], bh[nt][1]);
            }
    }

    // epilogue: bias, store, per-column stats
#pragma unroll
    for (int nt = 0; nt < 4; nt++) {
        const int c0 = wn * 32 + nt * 8 + q4 * 2;
        const float bb0 = bias[c0], bb1 = bias[c0 + 1];
        float s0 = 0.0f, s1 = 0.0f, qq0 = 0.0f, qq1 = 0.0f;
#pragma unroll
        for (int mt = 0; mt < 4; mt++) {
            const long r0 = rowBase + wm * 64 + mt * 16 + grp;
            const long r1 = r0 + 8;
            float x0 = acc[mt][nt][0] + bb0;
            float x1 = acc[mt][nt][1] + bb1;
            float x2 = acc[mt][nt][2] + bb0;
            float x3 = acc[mt][nt][3] + bb1;
            *(float2*)(C + r0 * 128 + c0) = make_float2(x0, x1);
            *(float2*)(C + r1 * 128 + c0) = make_float2(x2, x3);
            s0 += x0 + x2; s1 += x1 + x3;
            qq0 += x0 * x0 + x2 * x2; qq1 += x1 * x1 + x3 * x3;
        }
#pragma unroll
        for (int off = 4; off <= 16; off <<= 1) {
            s0  += __shfl_xor_sync(0xffffffffu, s0, off);
            s1  += __shfl_xor_sync(0xffffffffu, s1, off);
            qq0 += __shfl_xor_sync(0xffffffffu, qq0, off);
            qq1 += __shfl_xor_sync(0xffffffffu, qq1, off);
        }
        if (grp == 0) {
            atomicAdd(&ssum[c0], s0);  atomicAdd(&ssum[c0 + 1], s1);
            atomicAdd(&ssq[c0], qq0);  atomicAdd(&ssq[c0 + 1], qq1);
        }
    }
    __syncthreads();
    if (tid < 128) {
        atomicAdd(&g_sum[tid], ssum[tid]);
        atomicAdd(&g_sq[tid], ssq[tid]);
    }
}

// ---------------- BN finalize: stats -> (scale, shift), then re-zero stats ----------------
__global__ void bn_finalize_kernel(const float* __restrict__ g,
                                   const float* __restrict__ b,
                                   float* __restrict__ sc,
                                   float* __restrict__ sh) {
    const int c = threadIdx.x;
    float m = g_sum[c] * INV_M;
    float v = g_sq[c] * INV_M - m * m;
    float s = g[c] * rsqrtf(v + EPS);
    sc[c] = s;
    sh[c] = b[c] - m * s;
    g_sum[c] = 0.0f;
    g_sq[c] = 0.0f;
}

// ---------------- Attention (fp32) with fused BN-affine on q/k/v loads ----------------
#define AL_STRIDE 129
#define ATTN_SMEM ((4096 + 4096 + 128 * AL_STRIDE) * 4)   // 98816 B

__global__ void attn_kernel(const float* __restrict__ q,
                            const float* __restrict__ k,
                            const float* __restrict__ v,
                            const float* __restrict__ mask,
                            const float* __restrict__ scQ, const float* __restrict__ shQ,
                            const float* __restrict__ scK, const float* __restrict__ shK,
                            const float* __restrict__ scV, const float* __restrict__ shV,
                            float* __restrict__ out) {
    extern __shared__ float sm[];
    float* ks = sm;            // [128][32]
    float* vs = sm + 4096;     // [128][32]
    float* al = sm + 8192;     // [128][AL_STRIDE]

    const int h = blockIdx.x;
    const int n = blockIdx.y;
    const int s = threadIdx.x;                    // 128 threads
    const long base = (long)n * SS * DD + h * CC;
    const int dBase = h * CC;

    for (int idx = s; idx < 4096; idx += 128) {
        int t = idx >> 5, c = idx & 31;
        int d = dBase + c;
        ks[idx] = k[base + (long)t * 128 + c] * scK[d] + shK[d];
        vs[idx] = v[base + (long)t * 128 + c] * scV[d] + shV[d];
    }
    const long mbase = (long)n * SS * SS;
    for (int idx = s; idx < 16384; idx += 128) {
        al[(idx >> 7) * AL_STRIDE + (idx & 127)] = mask[mbase + idx];
    }
    __syncthreads();

    float qr[32];
#pragma unroll
    for (int c = 0; c < 32; c++) {
        int d = dBase + c;
        qr[c] = q[base + (long)s * 128 + c] * scQ[d] + shQ[d];
    }

    float* arow = al + s * AL_STRIDE;

    float mx = -1e30f;
    for (int t = 0; t < 128; t++) {
        const float4* k4 = (const float4*)(ks + t * 32);
        float d = 0.0f;
#pragma unroll
        for (int cc = 0; cc < 8; cc++) {
            float4 kv = k4[cc];
            d += qr[cc * 4]     * kv.x;
            d += qr[cc * 4 + 1] * kv.y;
            d += qr[cc * 4 + 2] * kv.z;
            d += qr[cc * 4 + 3] * kv.w;
        }
        float a = d * arow[t];     // alpha = (q.k) * mask
        arow[t] = a;
        mx = fmaxf(mx, a);
    }

    float ssum = 0.0f;
    for (int t = 0; t < 128; t++) {
        float p = __expf(arow[t] - mx);
        arow[t] = p;
        ssum += p;
    }
    const float inv = 1.0f / ssum;

    float acc[32];
#pragma unroll
    for (int c = 0; c < 32; c++) acc[c] = 0.0f;
    for (int t = 0; t < 128; t++) {
        float p = arow[t];
        const float4* v4 = (const float4*)(vs + t * 32);
#pragma unroll
        for (int cc = 0; cc < 8; cc++) {
            float4 vv = v4[cc];
            acc[cc * 4]     += p * vv.x;
            acc[cc * 4 + 1] += p * vv.y;
            acc[cc * 4 + 2] += p * vv.z;
            acc[cc * 4 + 3] += p * vv.w;
        }
    }
#pragma unroll
    for (int c = 0; c < 32; c++) out[base + (long)s * 128 + c] = acc[c] * inv;
}

// ---------------- out = LayerNorm(A + affine(B)) per row, warp per row ----------------
__global__ void add_ln_kernel(const float* __restrict__ A,
                              const float* __restrict__ B,
                              const float* __restrict__ scB,
                              const float* __restrict__ shB,
                              const float* __restrict__ gam,
                              const float* __restrict__ bet,
                              float* __restrict__ Out) {
    const int w = threadIdx.x >> 5, lane = threadIdx.x & 31;
    const long row = (long)blockIdx.x * 8 + w;
    const float* a = A + row * 128;
    const float* b = B + row * 128;

    float x[4];
    float s = 0.0f, s2 = 0.0f;
#pragma unroll
    for (int i = 0; i < 4; i++) {
        int c = lane + 32 * i;
        float bv = b[c];
        if (scB) bv = bv * scB[c] + shB[c];
        x[i] = a[c] + bv;
        s += x[i];
        s2 += x[i] * x[i];
    }
#pragma unroll
    for (int o = 16; o > 0; o >>= 1) {
        s  += __shfl_xor_sync(0xffffffffu, s, o);
        s2 += __shfl_xor_sync(0xffffffffu, s2, o);
    }
    const float m = s * (1.0f / 128.0f);
    const float var = s2 * (1.0f / 128.0f) - m * m;
    const float r = rsqrtf(var + EPS);
#pragma unroll
    for (int i = 0; i < 4; i++) {
        int c = lane + 32 * i;
        Out[row * 128 + c] = (x[i] - m) * r * gam[c] + bet[c];
    }
}

// ---------------- h = A + affine(B) ----------------
__global__ void add_affine_kernel(const float* __restrict__ A,
                                  const float* __restrict__ B,
                                  const float* __restrict__ sc,
                                  const float* __restrict__ sh,
                                  float* __restrict__ Out) {
    __shared__ float s_sc[128], s_sh[128];
    const int tid = threadIdx.x;
    if (tid < 128) { s_sc[tid] = sc[tid]; s_sh[tid] = sh[tid]; }
    __syncthreads();
    long i = ((long)blockIdx.x * blockDim.x + tid) * 4;
    const long stride = (long)gridDim.x * blockDim.x * 4;
    for (; i < MSZ; i += stride) {
        float4 a = *(const float4*)(A + i);
        float4 b = *(const float4*)(B + i);
        int c = (int)(i & 127);
        float4 y;
        y.x = a.x + b.x * s_sc[c]     + s_sh[c];
        y.y = a.y + b.y * s_sc[c + 1] + s_sh[c + 1];
        y.z = a.z + b.z * s_sc[c + 2] + s_sh[c + 2];
        y.w = a.w + b.w * s_sc[c + 3] + s_sh[c + 3];
        *(float4*)(Out + i) = y;
    }
}

// ---------------- gather h[:, 0] -> out[N, D] ----------------
__global__ void gather_kernel(const float* __restrict__ H, float* __restrict__ Out) {
    int i = blockIdx.x * blockDim.x + threadIdx.x;   // 131072 elements
    int n = i >> 7, d = i & 127;
    Out[i] = H[(long)n * SS * DD + d];
}

// ---------------- host orchestration ----------------
extern "C" void kernel_launch(void* const* d_in, const int* in_sizes, int n_in,
                              void* d_out, int out_size) {
    const float* x        = (const float*)d_in[0];
    const float* mask     = (const float*)d_in[1];
    const float* lin_in_W = (const float*)d_in[2];
    const float* lin_in_b = (const float*)d_in[3];
    const float* in_bn_g  = (const float*)d_in[4];
    const float* in_bn_b  = (const float*)d_in[5];
    const float* q_W      = (const float*)d_in[6];
    const float* q_b      = (const float*)d_in[7];
    const float* q_bn_g   = (const float*)d_in[8];
    const float* q_bn_b   = (const float*)d_in[9];
    const float* k_W      = (const float*)d_in[10];
    const float* k_b      = (const float*)d_in[11];
    const float* k_bn_g   = (const float*)d_in[12];
    const float* k_bn_b   = (const float*)d_in[13];
    const float* v_W      = (const float*)d_in[14];
    const float* v_b      = (const float*)d_in[15];
    const float* v_bn_g   = (const float*)d_in[16];
    const float* v_bn_b   = (const float*)d_in[17];
    const float* ln_g     = (const float*)d_in[18];
    const float* ln_b     = (const float*)d_in[19];
    const float* ff_W     = (const float*)d_in[20];
    const float* ff_b     = (const float*)d_in[21];
    const float* ff_bn_g  = (const float*)d_in[22];
    const float* ff_bn_b  = (const float*)d_in[23];
    const float* skip_W   = (const float*)d_in[24];
    const float* skip_b   = (const float*)d_in[25];
    const float* skip_bn_g= (const float*)d_in[26];
    const float* skip_bn_b= (const float*)d_in[27];
    float* out = (float*)d_out;

    cudaFuncSetAttribute(gemm_tc_kernel, cudaFuncAttributeMaxDynamicSharedMemorySize, GEMM_SMEM);
    cudaFuncSetAttribute(attn_kernel, cudaFuncAttributeMaxDynamicSharedMemorySize, ATTN_SMEM);

    float *bh, *bt, *bq, *bk, *bv, *ba, *bo, *bf, *bsc, *bsh;
    cudaGetSymbolAddress((void**)&bh, g_h);
    cudaGetSymbolAddress((void**)&bt, g_t);
    cudaGetSymbolAddress((void**)&bq, g_q);
    cudaGetSymbolAddress((void**)&bk, g_k);
    cudaGetSymbolAddress((void**)&bv, g_v);
    cudaGetSymbolAddress((void**)&ba, g_a);
    cudaGetSymbolAddress((void**)&bo, g_o);
    cudaGetSymbolAddress((void**)&bf, g_f);
    cudaGetSymbolAddress((void**)&bsc, g_scb);
    cudaGetSymbolAddress((void**)&bsh, g_shb);

    auto SC = [&](int i) { return bsc + i * DD; };
    auto SH = [&](int i) { return bsh + i * DD; };

    const int GEMM_GRID = M_ROWS / 128;   // 1024

    auto runGemm = [&](const float* A, const float* W, const float* bias,
                       const float* scA, const float* shA, float* C) {
        gemm_tc_kernel<<<GEMM_GRID, 256, GEMM_SMEM>>>(A, W, bias, scA, shA, C);
    };
    auto runFin = [&](const float* g, const float* b, float* sc, float* sh) {
        bn_finalize_kernel<<<1, 128>>>(g, b, sc, sh);
    };

    // t0 = x @ Win^T + b  (stats accumulated), in-BN affine -> slot 0
    runGemm(x, lin_in_W, lin_in_b, 0, 0, bt);
    runFin(in_bn_g, in_bn_b, SC(0), SH(0));

    for (int l = 0; l < LL; l++) {
        const long wOff = (long)l * DD * DD;
        const long vOff = (long)l * DD;
        const float* hp  = (l == 0) ? bt : bh;
        const float* scH = (l == 0) ? SC(0) : 0;
        const float* shH = (l == 0) ? SH(0) : 0;

        runGemm(hp, q_W + wOff, q_b + vOff, scH, shH, bq);
        runFin(q_bn_g + vOff, q_bn_b + vOff, SC(1), SH(1));
        runGemm(hp, k_W + wOff, k_b + vOff, scH, shH, bk);
        runFin(k_bn_g + vOff, k_bn_b + vOff, SC(2), SH(2));
        runGemm(hp, v_W + wOff, v_b + vOff, scH, shH, bv);
        runFin(v_bn_g + vOff, v_bn_b + vOff, SC(3), SH(3));

        dim3 agrid(HH, NB);
        attn_kernel<<<agrid, 128, ATTN_SMEM>>>(bq, bk, bv, mask,
                                               SC(1), SH(1), SC(2), SH(2), SC(3), SH(3), ba);

        // out = LN(agg + h)
        add_ln_kernel<<<M_ROWS / 8, 256>>>(ba, hp, scH, shH, ln_g + vOff, ln_b + vOff, bo);

        // ff = BN(out @ ff_W^T + b); out2 = LN(out + ff)
        runGemm(bo, ff_W + wOff, ff_b + vOff, 0, 0, bf);
        runFin(ff_bn_g + vOff, ff_bn_b + vOff, SC(4), SH(4));
        add_ln_kernel<<<M_ROWS / 8, 256>>>(bo, bf, SC(4), SH(4), ln_g + vOff, ln_b + vOff, ba);

        // x_r = BN(h @ skip_W^T + b); h = out2 + x_r
        runGemm(hp, skip_W + wOff, skip_b + vOff, scH, shH, bf);
        runFin(skip_bn_g + vOff, skip_bn_b + vOff, SC(5), SH(5));
        add_affine_kernel<<<4096, 256>>>(ba, bf, SC(5), SH(5), bh);
    }

    gather_kernel<<<(NB * DD) / 256, 256>>>(bh, out);
}

// round 5
// speedup vs baseline: 1.1958x; 1.0586x over previous
#include <cuda_runtime.h>
#include <cuda_bf16.h>
#include <math.h>
#include <stdint.h>

// ---------------- problem constants ----------------
#define NB      1024
#define SS      128
#define DD      128
#define HH      4
#define CC      32
#define LL      2
#define M_ROWS  (NB * SS)          // 131072
#define MSZ     (M_ROWS * DD)      // 16777216 floats = 64 MB
#define EPS     1e-5f
#define INV_M   (1.0f / (float)M_ROWS)

// ---------------- scratch (device globals; no allocation allowed) ----------------
__device__ float g_h[MSZ];
__device__ float g_t[MSZ];
__device__ float g_q[MSZ];
__device__ float g_k[MSZ];
__device__ float g_v[MSZ];
__device__ float g_a[MSZ];
__device__ float g_o[MSZ];
__device__ float g_f[MSZ];
__device__ float g_sum[DD];
__device__ float g_sq[DD];
__device__ float g_scb[6][DD];
__device__ float g_shb[6][DD];

// ================= helpers =================
__device__ __forceinline__ uint32_t smem_u32(const void* p) {
    uint32_t a;
    asm("{ .reg .u64 t; cvta.to.shared.u64 t, %1; cvt.u32.u64 %0, t; }" : "=r"(a) : "l"(p));
    return a;
}

__device__ __forceinline__ uint32_t packbf(float a, float b) {
    __nv_bfloat162 t = __floats2bfloat162_rn(a, b);
    return *(uint32_t*)&t;
}

#define LDSM_X4(r0, r1, r2, r3, addr) \
    asm volatile("ldmatrix.sync.aligned.m8n8.x4.shared.b16 {%0,%1,%2,%3}, [%4];" \
                 : "=r"(r0), "=r"(r1), "=r"(r2), "=r"(r3) : "r"(addr))

__device__ __forceinline__ void mma_bf16(float c[4],
                                         uint32_t a0, uint32_t a1, uint32_t a2, uint32_t a3,
                                         uint32_t b0, uint32_t b1) {
    asm volatile(
        "mma.sync.aligned.m16n8k16.row.col.f32.bf16.bf16.f32 "
        "{%0,%1,%2,%3}, {%4,%5,%6,%7}, {%8,%9}, {%0,%1,%2,%3};"
        : "+f"(c[0]), "+f"(c[1]), "+f"(c[2]), "+f"(c[3])
        : "r"(a0), "r"(a1), "r"(a2), "r"(a3), "r"(b0), "r"(b1));
}

// ================= GEMM: C = affine(A) @ W^T + bias, bf16x2 split, legacy HMMA =================
// Split hoisted to smem: A_hi/A_lo/W_hi/W_lo bf16 tiles; mainloop = ldmatrix + mma only.
// D = Ahi*Whi + Ahi*Wlo + Alo*Whi (3 passes, fp32 accum; missing Alo*Wlo ~ 2^-16 rel).
#define BSTR 136   // bf16 elems per smem row (272 B): ldmatrix conflict-free
#define TILE_E (128 * BSTR)
#define GEMM_SMEM (4 * TILE_E * 2)   // 139264 B

__global__ void __launch_bounds__(256)
gemm_tc_kernel(const float* __restrict__ A,
               const float* __restrict__ W,
               const float* __restrict__ bias,
               const float* __restrict__ scA,
               const float* __restrict__ shA,
               float* __restrict__ C) {
    extern __shared__ __nv_bfloat16 smem[];
    __nv_bfloat16* AH = smem;
    __nv_bfloat16* AL = smem + TILE_E;
    __nv_bfloat16* WH = smem + 2 * TILE_E;
    __nv_bfloat16* WL = smem + 3 * TILE_E;

    const int tid = threadIdx.x;
    const long rowBase = (long)blockIdx.x * 128;

    // ---- fill A_hi / A_lo (optional fused BN affine) ----
    for (int idx = tid; idx < 4096; idx += 256) {
        int r = idx >> 5, k0 = (idx & 31) * 4;
        float4 v = *(const float4*)(A + (rowBase + r) * 128 + k0);
        if (scA) {
            float4 s = *(const float4*)(scA + k0);
            float4 t = *(const float4*)(shA + k0);
            v.x = v.x * s.x + t.x; v.y = v.y * s.y + t.y;
            v.z = v.z * s.z + t.z; v.w = v.w * s.w + t.w;
        }
        float h0 = __bfloat162float(__float2bfloat16_rn(v.x));
        float h1 = __bfloat162float(__float2bfloat16_rn(v.y));
        float h2 = __bfloat162float(__float2bfloat16_rn(v.z));
        float h3 = __bfloat162float(__float2bfloat16_rn(v.w));
        *(uint2*)(AH + r * BSTR + k0) = make_uint2(packbf(v.x, v.y), packbf(v.z, v.w));
        *(uint2*)(AL + r * BSTR + k0) =
            make_uint2(packbf(v.x - h0, v.y - h1), packbf(v.z - h2, v.w - h3));
    }
    // ---- fill W_hi / W_lo ----
    for (int idx = tid; idx < 4096; idx += 256) {
        int r = idx >> 5, k0 = (idx & 31) * 4;
        float4 v = *(const float4*)(W + r * 128 + k0);
        float h0 = __bfloat162float(__float2bfloat16_rn(v.x));
        float h1 = __bfloat162float(__float2bfloat16_rn(v.y));
        float h2 = __bfloat162float(__float2bfloat16_rn(v.z));
        float h3 = __bfloat162float(__float2bfloat16_rn(v.w));
        *(uint2*)(WH + r * BSTR + k0) = make_uint2(packbf(v.x, v.y), packbf(v.z, v.w));
        *(uint2*)(WL + r * BSTR + k0) =
            make_uint2(packbf(v.x - h0, v.y - h1), packbf(v.z - h2, v.w - h3));
    }
    __syncthreads();

    const int warp = tid >> 5, lane = tid & 31;
    const int wm = warp >> 2, wn = warp & 3;       // 2 x 4 warp grid
    const int m0 = wm * 64, n0 = wn * 32;
    // ldmatrix row/col-half addressing: row = lane&15, half = lane>>4 (8 bf16 = 16B)
    const int lrow = lane & 15, lhalf = (lane >> 4) * 8;

    const uint32_t uAH = smem_u32(AH), uAL = smem_u32(AL);
    const uint32_t uWH = smem_u32(WH), uWL = smem_u32(WL);

    float acc[4][4][4];
#pragma unroll
    for (int mt = 0; mt < 4; mt++)
#pragma unroll
        for (int nt = 0; nt < 4; nt++)
#pragma unroll
            for (int i = 0; i < 4; i++) acc[mt][nt][i] = 0.0f;

#pragma unroll
    for (int ks = 0; ks < 8; ks++) {
        const int kb = ks * 16;
        const uint32_t colOff = (uint32_t)(kb + lhalf) * 2;

        // B_hi fragments: 2 x ldmatrix.x4 cover 32 W rows (4 n-tiles)
        uint32_t bhi[4][2];
#pragma unroll
        for (int g = 0; g < 2; g++) {
            uint32_t r0, r1, r2, r3;
            uint32_t addr = uWH + ((uint32_t)(n0 + g * 16 + lrow) * BSTR) * 2 + colOff;
            LDSM_X4(r0, r1, r2, r3, addr);
            bhi[2 * g][0] = r0; bhi[2 * g][1] = r2;
            bhi[2 * g + 1][0] = r1; bhi[2 * g + 1][1] = r3;
        }
        // A_hi fragments: 4 m-tiles
        uint32_t a[4][4];
#pragma unroll
        for (int mt = 0; mt < 4; mt++) {
            uint32_t addr = uAH + ((uint32_t)(m0 + mt * 16 + lrow) * BSTR) * 2 + colOff;
            LDSM_X4(a[mt][0], a[mt][1], a[mt][2], a[mt][3], addr);
        }
        // pass 1: Ahi * Whi
#pragma unroll
        for (int mt = 0; mt < 4; mt++)
#pragma unroll
            for (int nt = 0; nt < 4; nt++)
                mma_bf16(acc[mt][nt], a[mt][0], a[mt][1], a[mt][2], a[mt][3],
                         bhi[nt][0], bhi[nt][1]);
        // B_lo fragments
        uint32_t blo[4][2];
#pragma unroll
        for (int g = 0; g < 2; g++) {
            uint32_t r0, r1, r2, r3;
            uint32_t addr = uWL + ((uint32_t)(n0 + g * 16 + lrow) * BSTR) * 2 + colOff;
            LDSM_X4(r0, r1, r2, r3, addr);
            blo[2 * g][0] = r0; blo[2 * g][1] = r2;
            blo[2 * g + 1][0] = r1; blo[2 * g + 1][1] = r3;
        }
        // pass 2: Ahi * Wlo
#pragma unroll
        for (int mt = 0; mt < 4; mt++)
#pragma unroll
            for (int nt = 0; nt < 4; nt++)
                mma_bf16(acc[mt][nt], a[mt][0], a[mt][1], a[mt][2], a[mt][3],
                         blo[nt][0], blo[nt][1]);
        // A_lo fragments (reuse regs)
#pragma unroll
        for (int mt = 0; mt < 4; mt++) {
            uint32_t addr = uAL + ((uint32_t)(m0 + mt * 16 + lrow) * BSTR) * 2 + colOff;
            LDSM_X4(a[mt][0], a[mt][1], a[mt][2], a[mt][3], addr);
        }
        // pass 3: Alo * Whi
#pragma unroll
        for (int mt = 0; mt < 4; mt++)
#pragma unroll
            for (int nt = 0; nt < 4; nt++)
                mma_bf16(acc[mt][nt], a[mt][0], a[mt][1], a[mt][2], a[mt][3],
                         bhi[nt][0], bhi[nt][1]);
    }

    // ---- epilogue: bias + store (c0,c1 at row, c2,c3 at row+8) ----
    const int cr = lane >> 2, cc2 = (lane & 3) * 2;
#pragma unroll
    for (int nt = 0; nt < 4; nt++) {
        const int col = n0 + nt * 8 + cc2;
        const float b0 = bias[col], b1 = bias[col + 1];
#pragma unroll
        for (int mt = 0; mt < 4; mt++) {
            const long r0 = rowBase + m0 + mt * 16 + cr;
            *(float2*)(C + r0 * 128 + col) =
                make_float2(acc[mt][nt][0] + b0, acc[mt][nt][1] + b1);
            *(float2*)(C + (r0 + 8) * 128 + col) =
                make_float2(acc[mt][nt][2] + b0, acc[mt][nt][3] + b1);
        }
    }
}

// ---------------- BN stats: per-column sum/sumsq of a [M,128] matrix ----------------
__global__ void bn_stats_kernel(const float* __restrict__ A) {
    __shared__ float ssum[128], ssq[128];
    const int tid = threadIdx.x;
    if (tid < 128) { ssum[tid] = 0.0f; ssq[tid] = 0.0f; }
    __syncthreads();
    const int w = tid >> 5, l = tid & 31;
    const long r0 = (long)blockIdx.x * 128 + w * 16;
    float s0 = 0, s1 = 0, s2 = 0, s3 = 0, q0 = 0, q1 = 0, q2 = 0, q3 = 0;
#pragma unroll 4
    for (int i = 0; i < 16; i++) {
        float4 v = *(const float4*)(A + (r0 + i) * 128 + l * 4);
        s0 += v.x; s1 += v.y; s2 += v.z; s3 += v.w;
        q0 += v.x * v.x; q1 += v.y * v.y; q2 += v.z * v.z; q3 += v.w * v.w;
    }
    atomicAdd(&ssum[l * 4 + 0], s0); atomicAdd(&ssum[l * 4 + 1], s1);
    atomicAdd(&ssum[l * 4 + 2], s2); atomicAdd(&ssum[l * 4 + 3], s3);
    atomicAdd(&ssq[l * 4 + 0], q0);  atomicAdd(&ssq[l * 4 + 1], q1);
    atomicAdd(&ssq[l * 4 + 2], q2);  atomicAdd(&ssq[l * 4 + 3], q3);
    __syncthreads();
    if (tid < 128) {
        atomicAdd(&g_sum[tid], ssum[tid]);
        atomicAdd(&g_sq[tid], ssq[tid]);
    }
}

// ---------------- BN finalize: stats -> (scale, shift), then re-zero stats ----------------
__global__ void bn_finalize_kernel(const float* __restrict__ g,
                                   const float* __restrict__ b,
                                   float* __restrict__ sc,
                                   float* __restrict__ sh) {
    const int c = threadIdx.x;
    float m = g_sum[c] * INV_M;
    float v = g_sq[c] * INV_M - m * m;
    float s = g[c] * rsqrtf(v + EPS);
    sc[c] = s;
    sh[c] = b[c] - m * s;
    g_sum[c] = 0.0f;
    g_sq[c] = 0.0f;
}

// ---------------- Attention (fp32) with fused BN-affine on q/k/v loads ----------------
#define AL_STRIDE 129
#define ATTN_SMEM ((4096 + 4096 + 128 * AL_STRIDE) * 4)   // 98816 B

__global__ void attn_kernel(const float* __restrict__ q,
                            const float* __restrict__ k,
                            const float* __restrict__ v,
                            const float* __restrict__ mask,
                            const float* __restrict__ scQ, const float* __restrict__ shQ,
                            const float* __restrict__ scK, const float* __restrict__ shK,
                            const float* __restrict__ scV, const float* __restrict__ shV,
                            float* __restrict__ out) {
    extern __shared__ float sm[];
    float* ks = sm;            // [128][32]
    float* vs = sm + 4096;     // [128][32]
    float* al = sm + 8192;     // [128][AL_STRIDE]

    const int h = blockIdx.x;
    const int n = blockIdx.y;
    const int s = threadIdx.x;                    // 128 threads
    const long base = (long)n * SS * DD + h * CC;
    const int dBase = h * CC;

    for (int idx = s; idx < 4096; idx += 128) {
        int t = idx >> 5, c = idx & 31;
        int d = dBase + c;
        ks[idx] = k[base + (long)t * 128 + c] * scK[d] + shK[d];
        vs[idx] = v[base + (long)t * 128 + c] * scV[d] + shV[d];
    }
    const long mbase = (long)n * SS * SS;
    for (int idx = s; idx < 16384; idx += 128) {
        al[(idx >> 7) * AL_STRIDE + (idx & 127)] = mask[mbase + idx];
    }
    __syncthreads();

    float qr[32];
#pragma unroll
    for (int c = 0; c < 32; c++) {
        int d = dBase + c;
        qr[c] = q[base + (long)s * 128 + c] * scQ[d] + shQ[d];
    }

    float* arow = al + s * AL_STRIDE;

    float mx = -1e30f;
    for (int t = 0; t < 128; t++) {
        const float4* k4 = (const float4*)(ks + t * 32);
        float d = 0.0f;
#pragma unroll
        for (int cc = 0; cc < 8; cc++) {
            float4 kv = k4[cc];
            d += qr[cc * 4]     * kv.x;
            d += qr[cc * 4 + 1] * kv.y;
            d += qr[cc * 4 + 2] * kv.z;
            d += qr[cc * 4 + 3] * kv.w;
        }
        float a = d * arow[t];
        arow[t] = a;
        mx = fmaxf(mx, a);
    }

    float ssum = 0.0f;
    for (int t = 0; t < 128; t++) {
        float p = __expf(arow[t] - mx);
        arow[t] = p;
        ssum += p;
    }
    const float inv = 1.0f / ssum;

    float acc[32];
#pragma unroll
    for (int c = 0; c < 32; c++) acc[c] = 0.0f;
    for (int t = 0; t < 128; t++) {
        float p = arow[t];
        const float4* v4 = (const float4*)(vs + t * 32);
#pragma unroll
        for (int cc = 0; cc < 8; cc++) {
            float4 vv = v4[cc];
            acc[cc * 4]     += p * vv.x;
            acc[cc * 4 + 1] += p * vv.y;
            acc[cc * 4 + 2] += p * vv.z;
            acc[cc * 4 + 3] += p * vv.w;
        }
    }
#pragma unroll
    for (int c = 0; c < 32; c++) out[base + (long)s * 128 + c] = acc[c] * inv;
}

// ---------------- out = LayerNorm(A + affine(B)) per row, warp per row ----------------
__global__ void add_ln_kernel(const float* __restrict__ A,
                              const float* __restrict__ B,
                              const float* __restrict__ scB,
                              const float* __restrict__ shB,
                              const float* __restrict__ gam,
                              const float* __restrict__ bet,
                              float* __restrict__ Out) {
    const int w = threadIdx.x >> 5, lane = threadIdx.x & 31;
    const long row = (long)blockIdx.x * 8 + w;
    const float* a = A + row * 128;
    const float* b = B + row * 128;

    float x[4];
    float s = 0.0f, s2 = 0.0f;
#pragma unroll
    for (int i = 0; i < 4; i++) {
        int c = lane + 32 * i;
        float bv = b[c];
        if (scB) bv = bv * scB[c] + shB[c];
        x[i] = a[c] + bv;
        s += x[i];
        s2 += x[i] * x[i];
    }
#pragma unroll
    for (int o = 16; o > 0; o >>= 1) {
        s  += __shfl_xor_sync(0xffffffffu, s, o);
        s2 += __shfl_xor_sync(0xffffffffu, s2, o);
    }
    const float m = s * (1.0f / 128.0f);
    const float var = s2 * (1.0f / 128.0f) - m * m;
    const float r = rsqrtf(var + EPS);
#pragma unroll
    for (int i = 0; i < 4; i++) {
        int c = lane + 32 * i;
        Out[row * 128 + c] = (x[i] - m) * r * gam[c] + bet[c];
    }
}

// ---------------- h = A + affine(B) ----------------
__global__ void add_affine_kernel(const float* __restrict__ A,
                                  const float* __restrict__ B,
                                  const float* __restrict__ sc,
                                  const float* __restrict__ sh,
                                  float* __restrict__ Out) {
    __shared__ float s_sc[128], s_sh[128];
    const int tid = threadIdx.x;
    if (tid < 128) { s_sc[tid] = sc[tid]; s_sh[tid] = sh[tid]; }
    __syncthreads();
    long i = ((long)blockIdx.x * blockDim.x + tid) * 4;
    const long stride = (long)gridDim.x * blockDim.x * 4;
    for (; i < MSZ; i += stride) {
        float4 a = *(const float4*)(A + i);
        float4 b = *(const float4*)(B + i);
        int c = (int)(i & 127);
        float4 y;
        y.x = a.x + b.x * s_sc[c]     + s_sh[c];
        y.y = a.y + b.y * s_sc[c + 1] + s_sh[c + 1];
        y.z = a.z + b.z * s_sc[c + 2] + s_sh[c + 2];
        y.w = a.w + b.w * s_sc[c + 3] + s_sh[c + 3];
        *(float4*)(Out + i) = y;
    }
}

// ---------------- gather h[:, 0] -> out[N, D] ----------------
__global__ void gather_kernel(const float* __restrict__ H, float* __restrict__ Out) {
    int i = blockIdx.x * blockDim.x + threadIdx.x;
    int n = i >> 7, d = i & 127;
    Out[i] = H[(long)n * SS * DD + d];
}

// ---------------- host orchestration ----------------
extern "C" void kernel_launch(void* const* d_in, const int* in_sizes, int n_in,
                              void* d_out, int out_size) {
    const float* x        = (const float*)d_in[0];
    const float* mask     = (const float*)d_in[1];
    const float* lin_in_W = (const float*)d_in[2];
    const float* lin_in_b = (const float*)d_in[3];
    const float* in_bn_g  = (const float*)d_in[4];
    const float* in_bn_b  = (const float*)d_in[5];
    const float* q_W      = (const float*)d_in[6];
    const float* q_b      = (const float*)d_in[7];
    const float* q_bn_g   = (const float*)d_in[8];
    const float* q_bn_b   = (const float*)d_in[9];
    const float* k_W      = (const float*)d_in[10];
    const float* k_b      = (const float*)d_in[11];
    const float* k_bn_g   = (const float*)d_in[12];
    const float* k_bn_b   = (const float*)d_in[13];
    const float* v_W      = (const float*)d_in[14];
    const float* v_b      = (const float*)d_in[15];
    const float* v_bn_g   = (const float*)d_in[16];
    const float* v_bn_b   = (const float*)d_in[17];
    const float* ln_g     = (const float*)d_in[18];
    const float* ln_b     = (const float*)d_in[19];
    const float* ff_W     = (const float*)d_in[20];
    const float* ff_b     = (const float*)d_in[21];
    const float* ff_bn_g  = (const float*)d_in[22];
    const float* ff_bn_b  = (const float*)d_in[23];
    const float* skip_W   = (const float*)d_in[24];
    const float* skip_b   = (const float*)d_in[25];
    const float* skip_bn_g= (const float*)d_in[26];
    const float* skip_bn_b= (const float*)d_in[27];
    float* out = (float*)d_out;

    cudaFuncSetAttribute(gemm_tc_kernel, cudaFuncAttributeMaxDynamicSharedMemorySize, GEMM_SMEM);
    cudaFuncSetAttribute(attn_kernel, cudaFuncAttributeMaxDynamicSharedMemorySize, ATTN_SMEM);

    float *bh, *bt, *bq, *bk, *bv, *ba, *bo, *bf, *bsc, *bsh;
    cudaGetSymbolAddress((void**)&bh, g_h);
    cudaGetSymbolAddress((void**)&bt, g_t);
    cudaGetSymbolAddress((void**)&bq, g_q);
    cudaGetSymbolAddress((void**)&bk, g_k);
    cudaGetSymbolAddress((void**)&bv, g_v);
    cudaGetSymbolAddress((void**)&ba, g_a);
    cudaGetSymbolAddress((void**)&bo, g_o);
    cudaGetSymbolAddress((void**)&bf, g_f);
    cudaGetSymbolAddress((void**)&bsc, g_scb);
    cudaGetSymbolAddress((void**)&bsh, g_shb);

    auto SC = [&](int i) { return bsc + i * DD; };
    auto SH = [&](int i) { return bsh + i * DD; };

    const int GEMM_GRID = M_ROWS / 128;   // 1024

    auto runGemm = [&](const float* A, const float* W, const float* bias,
                       const float* scA, const float* shA, float* C) {
        gemm_tc_kernel<<<GEMM_GRID, 256, GEMM_SMEM>>>(A, W, bias, scA, shA, C);
    };
    auto runStats = [&](const float* src) {
        bn_stats_kernel<<<1024, 256>>>(src);
    };
    auto runFin = [&](const float* g, const float* b, float* sc, float* sh) {
        bn_finalize_kernel<<<1, 128>>>(g, b, sc, sh);
    };

    // t0 = x @ Win^T + b ; BN -> (scale, shift) slot 0
    runGemm(x, lin_in_W, lin_in_b, 0, 0, bt);
    runStats(bt);
    runFin(in_bn_g, in_bn_b, SC(0), SH(0));

    for (int l = 0; l < LL; l++) {
        const long wOff = (long)l * DD * DD;
        const long vOff = (long)l * DD;
        const float* hp  = (l == 0) ? bt : bh;
        const float* scH = (l == 0) ? SC(0) : 0;
        const float* shH = (l == 0) ? SH(0) : 0;

        runGemm(hp, q_W + wOff, q_b + vOff, scH, shH, bq);   // l=0: launch 4
        runGemm(hp, k_W + wOff, k_b + vOff, scH, shH, bk);   // l=0: launch 5
        runGemm(hp, v_W + wOff, v_b + vOff, scH, shH, bv);   // l=0: launch 6 (ncu -s 5 target)
        runStats(bq); runFin(q_bn_g + vOff, q_bn_b + vOff, SC(1), SH(1));
        runStats(bk); runFin(k_bn_g + vOff, k_bn_b + vOff, SC(2), SH(2));
        runStats(bv); runFin(v_bn_g + vOff, v_bn_b + vOff, SC(3), SH(3));

        dim3 agrid(HH, NB);
        attn_kernel<<<agrid, 128, ATTN_SMEM>>>(bq, bk, bv, mask,
                                               SC(1), SH(1), SC(2), SH(2), SC(3), SH(3), ba);

        // out = LN(agg + h)
        add_ln_kernel<<<M_ROWS / 8, 256>>>(ba, hp, scH, shH, ln_g + vOff, ln_b + vOff, bo);

        // ff = BN(out @ ff_W^T + b); out2 = LN(out + ff)
        runGemm(bo, ff_W + wOff, ff_b + vOff, 0, 0, bf);
        runStats(bf); runFin(ff_bn_g + vOff, ff_bn_b + vOff, SC(4), SH(4));
        add_ln_kernel<<<M_ROWS / 8, 256>>>(bo, bf, SC(4), SH(4), ln_g + vOff, ln_b + vOff, ba);

        // x_r = BN(h @ skip_W^T + b); h = out2 + x_r
        runGemm(hp, skip_W + wOff, skip_b + vOff, scH, shH, bf);
        runStats(bf); runFin(skip_bn_g + vOff, skip_bn_b + vOff, SC(5), SH(5));
        add_affine_kernel<<<4096, 256>>>(ba, bf, SC(5), SH(5), bh);
    }

    gather_kernel<<<(NB * DD) / 256, 256>>>(bh, out);
}

// round 6
// speedup vs baseline: 1.7857x; 1.4933x over previous
#include <cuda_runtime.h>
#include <cuda_bf16.h>
#include <math.h>
#include <stdint.h>

// ---------------- problem constants ----------------
#define NB      1024
#define SS      128
#define DD      128
#define HH      4
#define CC      32
#define LL      2
#define M_ROWS  (NB * SS)          // 131072
#define MSZ     (M_ROWS * DD)      // 16777216 floats = 64 MB
#define EPS     1e-5f
#define INV_M   (1.0f / (float)M_ROWS)

// ---------------- scratch (device globals; no allocation allowed) ----------------
__device__ float g_h[MSZ];
__device__ float g_t[MSZ];
__device__ float g_q[MSZ];
__device__ float g_k[MSZ];
__device__ float g_v[MSZ];
__device__ float g_a[MSZ];
__device__ float g_o[MSZ];
__device__ float g_f[MSZ];
__device__ float g_stat_sum[6][DD];   // per-GEMM stat slots (zeroed by finalize)
__device__ float g_stat_sq[6][DD];
__device__ float g_scb[6][DD];
__device__ float g_shb[6][DD];

// ================= helpers =================
__device__ __forceinline__ uint32_t smem_u32(const void* p) {
    uint32_t a;
    asm("{ .reg .u64 t; cvta.to.shared.u64 t, %1; cvt.u32.u64 %0, t; }" : "=r"(a) : "l"(p));
    return a;
}

__device__ __forceinline__ uint32_t packbf(float a, float b) {
    __nv_bfloat162 t = __floats2bfloat162_rn(a, b);
    return *(uint32_t*)&t;
}

#define LDSM_X4(r0, r1, r2, r3, addr) \
    asm volatile("ldmatrix.sync.aligned.m8n8.x4.shared.b16 {%0,%1,%2,%3}, [%4];" \
                 : "=r"(r0), "=r"(r1), "=r"(r2), "=r"(r3) : "r"(addr))

__device__ __forceinline__ void mma_bf16(float c[4],
                                         uint32_t a0, uint32_t a1, uint32_t a2, uint32_t a3,
                                         uint32_t b0, uint32_t b1) {
    asm volatile(
        "mma.sync.aligned.m16n8k16.row.col.f32.bf16.bf16.f32 "
        "{%0,%1,%2,%3}, {%4,%5,%6,%7}, {%8,%9}, {%0,%1,%2,%3};"
        : "+f"(c[0]), "+f"(c[1]), "+f"(c[2]), "+f"(c[3])
        : "r"(a0), "r"(a1), "r"(a2), "r"(a3), "r"(b0), "r"(b1));
}

// ================= GEMM v2: 256-row tile, 512 threads, fused BN stats =================
// C = affine(A) @ W^T + bias; D = Ahi*Whi + Ahi*Wlo + Alo*Whi (bf16x2 split, fp32 acc).
// Column sum/sumsq reduced in epilogue into per-GEMM stat slot.
#define BSTR 136                      // bf16 elems per smem row: ldmatrix conflict-free
#define A_TILE_E (256 * BSTR)         // 34816 elems
#define W_TILE_E (128 * BSTR)         // 17408 elems
#define GEMM_SMEM ((2 * A_TILE_E + 2 * W_TILE_E) * 2 + 256 * 4)   // 209920 B

__global__ void __launch_bounds__(512)
gemm_tc_kernel(const float* __restrict__ A,
               const float* __restrict__ W,
               const float* __restrict__ bias,
               const float* __restrict__ scA,
               const float* __restrict__ shA,
               float* __restrict__ statSum,
               float* __restrict__ statSq,
               float* __restrict__ C) {
    extern __shared__ __nv_bfloat16 smem[];
    __nv_bfloat16* AH = smem;
    __nv_bfloat16* AL = smem + A_TILE_E;
    __nv_bfloat16* WH = smem + 2 * A_TILE_E;
    __nv_bfloat16* WL = smem + 2 * A_TILE_E + W_TILE_E;
    float* ssum = (float*)(smem + 2 * A_TILE_E + 2 * W_TILE_E);
    float* ssq  = ssum + 128;

    const int tid = threadIdx.x;
    const long rowBase = (long)blockIdx.x * 256;

    if (tid < 128) { ssum[tid] = 0.0f; ssq[tid] = 0.0f; }

    // ---- fill A_hi / A_lo (256 rows, optional fused BN affine) ----
    for (int idx = tid; idx < 8192; idx += 512) {
        int r = idx >> 5, k0 = (idx & 31) * 4;
        float4 v = *(const float4*)(A + (rowBase + r) * 128 + k0);
        if (scA) {
            float4 s = *(const float4*)(scA + k0);
            float4 t = *(const float4*)(shA + k0);
            v.x = v.x * s.x + t.x; v.y = v.y * s.y + t.y;
            v.z = v.z * s.z + t.z; v.w = v.w * s.w + t.w;
        }
        float h0 = __bfloat162float(__float2bfloat16_rn(v.x));
        float h1 = __bfloat162float(__float2bfloat16_rn(v.y));
        float h2 = __bfloat162float(__float2bfloat16_rn(v.z));
        float h3 = __bfloat162float(__float2bfloat16_rn(v.w));
        *(uint2*)(AH + r * BSTR + k0) = make_uint2(packbf(v.x, v.y), packbf(v.z, v.w));
        *(uint2*)(AL + r * BSTR + k0) =
            make_uint2(packbf(v.x - h0, v.y - h1), packbf(v.z - h2, v.w - h3));
    }
    // ---- fill W_hi / W_lo ----
    for (int idx = tid; idx < 4096; idx += 512) {
        int r = idx >> 5, k0 = (idx & 31) * 4;
        float4 v = *(const float4*)(W + r * 128 + k0);
        float h0 = __bfloat162float(__float2bfloat16_rn(v.x));
        float h1 = __bfloat162float(__float2bfloat16_rn(v.y));
        float h2 = __bfloat162float(__float2bfloat16_rn(v.z));
        float h3 = __bfloat162float(__float2bfloat16_rn(v.w));
        *(uint2*)(WH + r * BSTR + k0) = make_uint2(packbf(v.x, v.y), packbf(v.z, v.w));
        *(uint2*)(WL + r * BSTR + k0) =
            make_uint2(packbf(v.x - h0, v.y - h1), packbf(v.z - h2, v.w - h3));
    }
    __syncthreads();

    const int warp = tid >> 5, lane = tid & 31;
    const int wm = warp >> 2, wn = warp & 3;       // 4 x 4 warp grid
    const int m0 = wm * 64, n0 = wn * 32;
    const int lrow = lane & 15, lhalf = (lane >> 4) * 8;

    const uint32_t uAH = smem_u32(AH), uAL = smem_u32(AL);
    const uint32_t uWH = smem_u32(WH), uWL = smem_u32(WL);

    float acc[4][4][4];
#pragma unroll
    for (int mt = 0; mt < 4; mt++)
#pragma unroll
        for (int nt = 0; nt < 4; nt++)
#pragma unroll
            for (int i = 0; i < 4; i++) acc[mt][nt][i] = 0.0f;

#pragma unroll
    for (int ks = 0; ks < 8; ks++) {
        const uint32_t colOff = (uint32_t)(ks * 16 + lhalf) * 2;

        uint32_t bhi[4][2];
#pragma unroll
        for (int g = 0; g < 2; g++) {
            uint32_t r0, r1, r2, r3;
            uint32_t addr = uWH + ((uint32_t)(n0 + g * 16 + lrow) * BSTR) * 2 + colOff;
            LDSM_X4(r0, r1, r2, r3, addr);
            bhi[2 * g][0] = r0; bhi[2 * g][1] = r2;
            bhi[2 * g + 1][0] = r1; bhi[2 * g + 1][1] = r3;
        }
        uint32_t a[4][4];
#pragma unroll
        for (int mt = 0; mt < 4; mt++) {
            uint32_t addr = uAH + ((uint32_t)(m0 + mt * 16 + lrow) * BSTR) * 2 + colOff;
            LDSM_X4(a[mt][0], a[mt][1], a[mt][2], a[mt][3], addr);
        }
#pragma unroll
        for (int mt = 0; mt < 4; mt++)
#pragma unroll
            for (int nt = 0; nt < 4; nt++)
                mma_bf16(acc[mt][nt], a[mt][0], a[mt][1], a[mt][2], a[mt][3],
                         bhi[nt][0], bhi[nt][1]);
        uint32_t blo[4][2];
#pragma unroll
        for (int g = 0; g < 2; g++) {
            uint32_t r0, r1, r2, r3;
            uint32_t addr = uWL + ((uint32_t)(n0 + g * 16 + lrow) * BSTR) * 2 + colOff;
            LDSM_X4(r0, r1, r2, r3, addr);
            blo[2 * g][0] = r0; blo[2 * g][1] = r2;
            blo[2 * g + 1][0] = r1; blo[2 * g + 1][1] = r3;
        }
#pragma unroll
        for (int mt = 0; mt < 4; mt++)
#pragma unroll
            for (int nt = 0; nt < 4; nt++)
                mma_bf16(acc[mt][nt], a[mt][0], a[mt][1], a[mt][2], a[mt][3],
                         blo[nt][0], blo[nt][1]);
#pragma unroll
        for (int mt = 0; mt < 4; mt++) {
            uint32_t addr = uAL + ((uint32_t)(m0 + mt * 16 + lrow) * BSTR) * 2 + colOff;
            LDSM_X4(a[mt][0], a[mt][1], a[mt][2], a[mt][3], addr);
        }
#pragma unroll
        for (int mt = 0; mt < 4; mt++)
#pragma unroll
            for (int nt = 0; nt < 4; nt++)
                mma_bf16(acc[mt][nt], a[mt][0], a[mt][1], a[mt][2], a[mt][3],
                         bhi[nt][0], bhi[nt][1]);
    }

    // ---- epilogue: bias + store + per-column stats ----
    const int cr = lane >> 2, cc2 = (lane & 3) * 2;
#pragma unroll
    for (int nt = 0; nt < 4; nt++) {
        const int col = n0 + nt * 8 + cc2;
        const float b0 = bias[col], b1 = bias[col + 1];
        float s0 = 0.0f, s1 = 0.0f, q0 = 0.0f, q1 = 0.0f;
#pragma unroll
        for (int mt = 0; mt < 4; mt++) {
            const long r0 = rowBase + m0 + mt * 16 + cr;
            float x0 = acc[mt][nt][0] + b0;
            float x1 = acc[mt][nt][1] + b1;
            float x2 = acc[mt][nt][2] + b0;
            float x3 = acc[mt][nt][3] + b1;
            *(float2*)(C + r0 * 128 + col)       = make_float2(x0, x1);
            *(float2*)(C + (r0 + 8) * 128 + col) = make_float2(x2, x3);
            s0 += x0 + x2; s1 += x1 + x3;
            q0 += x0 * x0 + x2 * x2; q1 += x1 * x1 + x3 * x3;
        }
#pragma unroll
        for (int off = 4; off <= 16; off <<= 1) {
            s0 += __shfl_xor_sync(0xffffffffu, s0, off);
            s1 += __shfl_xor_sync(0xffffffffu, s1, off);
            q0 += __shfl_xor_sync(0xffffffffu, q0, off);
            q1 += __shfl_xor_sync(0xffffffffu, q1, off);
        }
        if (cr == 0) {
            atomicAdd(&ssum[col], s0);  atomicAdd(&ssum[col + 1], s1);
            atomicAdd(&ssq[col], q0);   atomicAdd(&ssq[col + 1], q1);
        }
    }
    __syncthreads();
    if (tid < 128) {
        atomicAdd(&statSum[tid], ssum[tid]);
        atomicAdd(&statSq[tid], ssq[tid]);
    }
}

// ---------------- BN finalize: slot stats -> (scale, shift), then re-zero ----------------
__global__ void bn_finalize_kernel(float* __restrict__ statSum,
                                   float* __restrict__ statSq,
                                   const float* __restrict__ g,
                                   const float* __restrict__ b,
                                   float* __restrict__ sc,
                                   float* __restrict__ sh) {
    const int c = threadIdx.x;
    float m = statSum[c] * INV_M;
    float v = statSq[c] * INV_M - m * m;
    float s = g[c] * rsqrtf(v + EPS);
    sc[c] = s;
    sh[c] = b[c] - m * s;
    statSum[c] = 0.0f;
    statSq[c] = 0.0f;
}

// ---------------- Attention v2: block = (n, head-pair), single-pass softmax ----------------
// alpha = (q.k)*mask; p = exp(alpha) (no max: |alpha| small, masked -> exp(0)=1 = reference).
// Mask staged once per block as bf16 (exact 0/1), row stride 130 -> conflict-free scalar reads.
#define MSTR 130
#define ATTN_SMEM (2 * 8192 * 4 + 128 * MSTR * 2)   // 2 heads (ks+vs) + mask = 98816 B

__global__ void __launch_bounds__(256)
attn_kernel(const float* __restrict__ q,
            const float* __restrict__ k,
            const float* __restrict__ v,
            const float* __restrict__ mask,
            const float* __restrict__ scQ, const float* __restrict__ shQ,
            const float* __restrict__ scK, const float* __restrict__ shK,
            const float* __restrict__ scV, const float* __restrict__ shV,
            float* __restrict__ out) {
    extern __shared__ float sm[];
    const int hp = blockIdx.x;            // head pair 0..1
    const int n  = blockIdx.y;
    const int tid = threadIdx.x;          // 256
    const int hh = tid >> 7;              // head within pair
    const int s  = tid & 127;             // query row

    float* ks = sm + hh * 8192;           // [128][32]
    float* vs = ks + 4096;
    __nv_bfloat16* ms = (__nv_bfloat16*)(sm + 16384);

    const int h = hp * 2 + hh;
    const long base = (long)n * SS * DD + h * CC;
    const int dBase = h * CC;

    // stage k/v (each 128-thread half loads its head's tiles)
    for (int idx = s; idx < 4096; idx += 128) {
        int t = idx >> 5, c = idx & 31;
        int d = dBase + c;
        ks[idx] = k[base + (long)t * 128 + c] * scK[d] + shK[d];
        vs[idx] = v[base + (long)t * 128 + c] * scV[d] + shV[d];
    }
    // stage mask once for both heads (bf16, exact 0/1)
    const long mbase = (long)n * SS * SS;
    for (int idx = tid; idx < 4096; idx += 256) {
        int r = idx >> 5, c4 = (idx & 31) * 4;
        float4 mv = *(const float4*)(mask + mbase + (long)r * 128 + c4);
        uint32_t off = (uint32_t)r * MSTR + c4;
        *(uint32_t*)(ms + off)     = packbf(mv.x, mv.y);
        *(uint32_t*)(ms + off + 2) = packbf(mv.z, mv.w);
    }
    __syncthreads();

    float qr[32];
#pragma unroll
    for (int c = 0; c < 32; c++) {
        int d = dBase + c;
        qr[c] = q[base + (long)s * 128 + c] * scQ[d] + shQ[d];
    }

    const __nv_bfloat16* mrow = ms + (uint32_t)s * MSTR;

    float ssum = 0.0f;
    float acc[32];
#pragma unroll
    for (int c = 0; c < 32; c++) acc[c] = 0.0f;

#pragma unroll 2
    for (int t = 0; t < 128; t++) {
        const float4* k4 = (const float4*)(ks + t * 32);
        float d = 0.0f;
#pragma unroll
        for (int cc = 0; cc < 8; cc++) {
            float4 kv = k4[cc];
            d += qr[cc * 4]     * kv.x;
            d += qr[cc * 4 + 1] * kv.y;
            d += qr[cc * 4 + 2] * kv.z;
            d += qr[cc * 4 + 3] * kv.w;
        }
        float mm = __bfloat162float(mrow[t]);
        float p = __expf(d * mm);
        ssum += p;
        const float4* v4 = (const float4*)(vs + t * 32);
#pragma unroll
        for (int cc = 0; cc < 8; cc++) {
            float4 vv = v4[cc];
            acc[cc * 4]     += p * vv.x;
            acc[cc * 4 + 1] += p * vv.y;
            acc[cc * 4 + 2] += p * vv.z;
            acc[cc * 4 + 3] += p * vv.w;
        }
    }
    const float inv = 1.0f / ssum;
#pragma unroll
    for (int c = 0; c < 32; c++) out[base + (long)s * 128 + c] = acc[c] * inv;
}

// ---------------- out = LayerNorm(A + affine(B)) per row, warp per row ----------------
__global__ void add_ln_kernel(const float* __restrict__ A,
                              const float* __restrict__ B,
                              const float* __restrict__ scB,
                              const float* __restrict__ shB,
                              const float* __restrict__ gam,
                              const float* __restrict__ bet,
                              float* __restrict__ Out) {
    const int w = threadIdx.x >> 5, lane = threadIdx.x & 31;
    const long row = (long)blockIdx.x * 8 + w;
    const float* a = A + row * 128;
    const float* b = B + row * 128;

    float x[4];
    float s = 0.0f, s2 = 0.0f;
#pragma unroll
    for (int i = 0; i < 4; i++) {
        int c = lane + 32 * i;
        float bv = b[c];
        if (scB) bv = bv * scB[c] + shB[c];
        x[i] = a[c] + bv;
        s += x[i];
        s2 += x[i] * x[i];
    }
#pragma unroll
    for (int o = 16; o > 0; o >>= 1) {
        s  += __shfl_xor_sync(0xffffffffu, s, o);
        s2 += __shfl_xor_sync(0xffffffffu, s2, o);
    }
    const float m = s * (1.0f / 128.0f);
    const float var = s2 * (1.0f / 128.0f) - m * m;
    const float r = rsqrtf(var + EPS);
#pragma unroll
    for (int i = 0; i < 4; i++) {
        int c = lane + 32 * i;
        Out[row * 128 + c] = (x[i] - m) * r * gam[c] + bet[c];
    }
}

// ---------------- h = A + affine(B) ----------------
__global__ void add_affine_kernel(const float* __restrict__ A,
                                  const float* __restrict__ B,
                                  const float* __restrict__ sc,
                                  const float* __restrict__ sh,
                                  float* __restrict__ Out) {
    __shared__ float s_sc[128], s_sh[128];
    const int tid = threadIdx.x;
    if (tid < 128) { s_sc[tid] = sc[tid]; s_sh[tid] = sh[tid]; }
    __syncthreads();
    long i = ((long)blockIdx.x * blockDim.x + tid) * 4;
    const long stride = (long)gridDim.x * blockDim.x * 4;
    for (; i < MSZ; i += stride) {
        float4 a = *(const float4*)(A + i);
        float4 b = *(const float4*)(B + i);
        int c = (int)(i & 127);
        float4 y;
        y.x = a.x + b.x * s_sc[c]     + s_sh[c];
        y.y = a.y + b.y * s_sc[c + 1] + s_sh[c + 1];
        y.z = a.z + b.z * s_sc[c + 2] + s_sh[c + 2];
        y.w = a.w + b.w * s_sc[c + 3] + s_sh[c + 3];
        *(float4*)(Out + i) = y;
    }
}

// ---------------- gather h[:, 0] -> out[N, D] ----------------
__global__ void gather_kernel(const float* __restrict__ H, float* __restrict__ Out) {
    int i = blockIdx.x * blockDim.x + threadIdx.x;
    int n = i >> 7, d = i & 127;
    Out[i] = H[(long)n * SS * DD + d];
}

// ---------------- host orchestration ----------------
extern "C" void kernel_launch(void* const* d_in, const int* in_sizes, int n_in,
                              void* d_out, int out_size) {
    const float* x        = (const float*)d_in[0];
    const float* mask     = (const float*)d_in[1];
    const float* lin_in_W = (const float*)d_in[2];
    const float* lin_in_b = (const float*)d_in[3];
    const float* in_bn_g  = (const float*)d_in[4];
    const float* in_bn_b  = (const float*)d_in[5];
    const float* q_W      = (const float*)d_in[6];
    const float* q_b      = (const float*)d_in[7];
    const float* q_bn_g   = (const float*)d_in[8];
    const float* q_bn_b   = (const float*)d_in[9];
    const float* k_W      = (const float*)d_in[10];
    const float* k_b      = (const float*)d_in[11];
    const float* k_bn_g   = (const float*)d_in[12];
    const float* k_bn_b   = (const float*)d_in[13];
    const float* v_W      = (const float*)d_in[14];
    const float* v_b      = (const float*)d_in[15];
    const float* v_bn_g   = (const float*)d_in[16];
    const float* v_bn_b   = (const float*)d_in[17];
    const float* ln_g     = (const float*)d_in[18];
    const float* ln_b     = (const float*)d_in[19];
    const float* ff_W     = (const float*)d_in[20];
    const float* ff_b     = (const float*)d_in[21];
    const float* ff_bn_g  = (const float*)d_in[22];
    const float* ff_bn_b  = (const float*)d_in[23];
    const float* skip_W   = (const float*)d_in[24];
    const float* skip_b   = (const float*)d_in[25];
    const float* skip_bn_g= (const float*)d_in[26];
    const float* skip_bn_b= (const float*)d_in[27];
    float* out = (float*)d_out;

    cudaFuncSetAttribute(gemm_tc_kernel, cudaFuncAttributeMaxDynamicSharedMemorySize, GEMM_SMEM);
    cudaFuncSetAttribute(attn_kernel, cudaFuncAttributeMaxDynamicSharedMemorySize, ATTN_SMEM);

    float *bh, *bt, *bq, *bk, *bv, *ba, *bo, *bf, *bsum, *bsq, *bsc, *bsh;
    cudaGetSymbolAddress((void**)&bh, g_h);
    cudaGetSymbolAddress((void**)&bt, g_t);
    cudaGetSymbolAddress((void**)&bq, g_q);
    cudaGetSymbolAddress((void**)&bk, g_k);
    cudaGetSymbolAddress((void**)&bv, g_v);
    cudaGetSymbolAddress((void**)&ba, g_a);
    cudaGetSymbolAddress((void**)&bo, g_o);
    cudaGetSymbolAddress((void**)&bf, g_f);
    cudaGetSymbolAddress((void**)&bsum, g_stat_sum);
    cudaGetSymbolAddress((void**)&bsq, g_stat_sq);
    cudaGetSymbolAddress((void**)&bsc, g_scb);
    cudaGetSymbolAddress((void**)&bsh, g_shb);

    auto SUM = [&](int i) { return bsum + i * DD; };
    auto SQ  = [&](int i) { return bsq + i * DD; };
    auto SC  = [&](int i) { return bsc + i * DD; };
    auto SH  = [&](int i) { return bsh + i * DD; };

    const int GEMM_GRID = M_ROWS / 256;   // 512

    auto runGemm = [&](const float* A, const float* W, const float* bias,
                       const float* scA, const float* shA, int slot, float* C) {
        gemm_tc_kernel<<<GEMM_GRID, 512, GEMM_SMEM>>>(A, W, bias, scA, shA,
                                                      SUM(slot), SQ(slot), C);
    };
    auto runFin = [&](int slot, const float* g, const float* b) {
        bn_finalize_kernel<<<1, 128>>>(SUM(slot), SQ(slot), g, b, SC(slot), SH(slot));
    };

    // t0 = x @ Win^T + b ; BN stats fused -> slot 0
    runGemm(x, lin_in_W, lin_in_b, 0, 0, 0, bt);          // launch 1
    runFin(0, in_bn_g, in_bn_b);                          // launch 2

    for (int l = 0; l < LL; l++) {
        const long wOff = (long)l * DD * DD;
        const long vOff = (long)l * DD;
        const float* hp  = (l == 0) ? bt : bh;
        const float* scH = (l == 0) ? SC(0) : 0;
        const float* shH = (l == 0) ? SH(0) : 0;

        runGemm(hp, q_W + wOff, q_b + vOff, scH, shH, 1, bq);   // l=0: launch 3
        runFin(1, q_bn_g + vOff, q_bn_b + vOff);                // l=0: launch 4
        runGemm(hp, k_W + wOff, k_b + vOff, scH, shH, 2, bk);   // l=0: launch 5
        runGemm(hp, v_W + wOff, v_b + vOff, scH, shH, 3, bv);   // l=0: launch 6 (ncu target)
        runFin(2, k_bn_g + vOff, k_bn_b + vOff);
        runFin(3, v_bn_g + vOff, v_bn_b + vOff);

        dim3 agrid(HH / 2, NB);
        attn_kernel<<<agrid, 256, ATTN_SMEM>>>(bq, bk, bv, mask,
                                               SC(1), SH(1), SC(2), SH(2), SC(3), SH(3), ba);

        // out = LN(agg + h)
        add_ln_kernel<<<M_ROWS / 8, 256>>>(ba, hp, scH, shH, ln_g + vOff, ln_b + vOff, bo);

        // ff = BN(out @ ff_W^T + b); out2 = LN(out + ff)
        runGemm(bo, ff_W + wOff, ff_b + vOff, 0, 0, 4, bf);
        runFin(4, ff_bn_g + vOff, ff_bn_b + vOff);
        add_ln_kernel<<<M_ROWS / 8, 256>>>(bo, bf, SC(4), SH(4), ln_g + vOff, ln_b + vOff, ba);

        // x_r = BN(h @ skip_W^T + b); h = out2 + x_r
        runGemm(hp, skip_W + wOff, skip_b + vOff, scH, shH, 5, bf);
        runFin(5, skip_bn_g + vOff, skip_bn_b + vOff);
        add_affine_kernel<<<4096, 256>>>(ba, bf, SC(5), SH(5), bh);
    }

    gather_kernel<<<(NB * DD) / 256, 256>>>(bh, out);
}

// round 7
// speedup vs baseline: 2.0065x; 1.1237x over previous
#include <cuda_runtime.h>
#include <cuda_bf16.h>
#include <math.h>
#include <stdint.h>

// ---------------- problem constants ----------------
#define NB      1024
#define SS      128
#define DD      128
#define HH      4
#define CC      32
#define LL      2
#define M_ROWS  (NB * SS)          // 131072
#define MSZ     (M_ROWS * DD)      // 16777216 floats = 64 MB
#define EPS     1e-5f
#define INV_M   (1.0f / (float)M_ROWS)

// ---------------- scratch (device globals; no allocation allowed) ----------------
__device__ float g_h[MSZ];
__device__ float g_t[MSZ];
__device__ float g_q[MSZ];
__device__ float g_k[MSZ];
__device__ float g_v[MSZ];
__device__ float g_a[MSZ];
__device__ float g_o[MSZ];
__device__ float g_f[MSZ];
__device__ float g_stat_sum[6][DD];   // zeroed by finalize after use
__device__ float g_stat_sq[6][DD];
__device__ float g_scb[6][DD];
__device__ float g_shb[6][DD];

// ================= helpers =================
__device__ __forceinline__ uint32_t smem_u32(const void* p) {
    uint32_t a;
    asm("{ .reg .u64 t; cvta.to.shared.u64 t, %1; cvt.u32.u64 %0, t; }" : "=r"(a) : "l"(p));
    return a;
}
__device__ __forceinline__ uint32_t packbf(float a, float b) {
    __nv_bfloat162 t = __floats2bfloat162_rn(a, b);
    return *(uint32_t*)&t;
}

#define LDSM_X4(r0, r1, r2, r3, addr) \
    asm volatile("ldmatrix.sync.aligned.m8n8.x4.shared.b16 {%0,%1,%2,%3}, [%4];" \
                 : "=r"(r0), "=r"(r1), "=r"(r2), "=r"(r3) : "r"(addr))

__device__ __forceinline__ void mma_bf16(float c[4],
                                         uint32_t a0, uint32_t a1, uint32_t a2, uint32_t a3,
                                         uint32_t b0, uint32_t b1) {
    asm volatile(
        "mma.sync.aligned.m16n8k16.row.col.f32.bf16.bf16.f32 "
        "{%0,%1,%2,%3}, {%4,%5,%6,%7}, {%8,%9}, {%0,%1,%2,%3};"
        : "+f"(c[0]), "+f"(c[1]), "+f"(c[2]), "+f"(c[3])
        : "r"(a0), "r"(a1), "r"(a2), "r"(a3), "r"(b0), "r"(b1));
}

// ================= GEMM: up to 3 weight sets share one converted A tile =================
// C_j = affine(A) @ W_j^T + bias_j; bf16x2 split (Ahi*Whi + Ahi*Wlo + Alo*Whi), fp32 acc.
// Per-column sum/sumsq reduced in epilogue via direct global atomics.
#define BSTR 136
#define A_TILE_E (256 * BSTR)
#define W_TILE_E (128 * BSTR)
#define GEMM_SMEM ((2 * A_TILE_E + 2 * W_TILE_E) * 2)   // 208896 B

__global__ void __launch_bounds__(512)
gemm_tc_kernel(const float* __restrict__ A,
               const float* __restrict__ scA, const float* __restrict__ shA,
               const float* W0, const float* W1, const float* W2,
               const float* b0, const float* b1, const float* b2,
               float* C0, float* C1, float* C2,
               float* sum0, float* sum1, float* sum2,
               float* sq0, float* sq1, float* sq2,
               int nW) {
    extern __shared__ __nv_bfloat16 smem[];
    __nv_bfloat16* AH = smem;
    __nv_bfloat16* AL = smem + A_TILE_E;
    __nv_bfloat16* WH = smem + 2 * A_TILE_E;
    __nv_bfloat16* WL = smem + 2 * A_TILE_E + W_TILE_E;

    const float* Wj[3] = {W0, W1, W2};
    const float* bj[3] = {b0, b1, b2};
    float* Cj[3] = {C0, C1, C2};
    float* sumj[3] = {sum0, sum1, sum2};
    float* sqj[3] = {sq0, sq1, sq2};

    const int tid = threadIdx.x;
    const long rowBase = (long)blockIdx.x * 256;

    // ---- fill A_hi / A_lo once ----
    for (int idx = tid; idx < 8192; idx += 512) {
        int r = idx >> 5, k0 = (idx & 31) * 4;
        float4 v = *(const float4*)(A + (rowBase + r) * 128 + k0);
        if (scA) {
            float4 s = *(const float4*)(scA + k0);
            float4 t = *(const float4*)(shA + k0);
            v.x = v.x * s.x + t.x; v.y = v.y * s.y + t.y;
            v.z = v.z * s.z + t.z; v.w = v.w * s.w + t.w;
        }
        float h0 = __bfloat162float(__float2bfloat16_rn(v.x));
        float h1 = __bfloat162float(__float2bfloat16_rn(v.y));
        float h2 = __bfloat162float(__float2bfloat16_rn(v.z));
        float h3 = __bfloat162float(__float2bfloat16_rn(v.w));
        *(uint2*)(AH + r * BSTR + k0) = make_uint2(packbf(v.x, v.y), packbf(v.z, v.w));
        *(uint2*)(AL + r * BSTR + k0) =
            make_uint2(packbf(v.x - h0, v.y - h1), packbf(v.z - h2, v.w - h3));
    }

    const int warp = tid >> 5, lane = tid & 31;
    const int wm = warp >> 2, wn = warp & 3;
    const int m0 = wm * 64, n0 = wn * 32;
    const int lrow = lane & 15, lhalf = (lane >> 4) * 8;
    const int cr = lane >> 2, cc2 = (lane & 3) * 2;

    const uint32_t uAH = smem_u32(AH), uAL = smem_u32(AL);
    const uint32_t uWH = smem_u32(WH), uWL = smem_u32(WL);

    for (int j = 0; j < nW; j++) {
        if (j > 0) __syncthreads();   // previous mainloop done reading W smem
        const float* W = Wj[j];
        for (int idx = tid; idx < 4096; idx += 512) {
            int r = idx >> 5, k0 = (idx & 31) * 4;
            float4 v = *(const float4*)(W + r * 128 + k0);
            float h0 = __bfloat162float(__float2bfloat16_rn(v.x));
            float h1 = __bfloat162float(__float2bfloat16_rn(v.y));
            float h2 = __bfloat162float(__float2bfloat16_rn(v.z));
            float h3 = __bfloat162float(__float2bfloat16_rn(v.w));
            *(uint2*)(WH + r * BSTR + k0) = make_uint2(packbf(v.x, v.y), packbf(v.z, v.w));
            *(uint2*)(WL + r * BSTR + k0) =
                make_uint2(packbf(v.x - h0, v.y - h1), packbf(v.z - h2, v.w - h3));
        }
        __syncthreads();

        float acc[4][4][4];
#pragma unroll
        for (int mt = 0; mt < 4; mt++)
#pragma unroll
            for (int nt = 0; nt < 4; nt++)
#pragma unroll
                for (int i = 0; i < 4; i++) acc[mt][nt][i] = 0.0f;

#pragma unroll
        for (int ks = 0; ks < 8; ks++) {
            const uint32_t colOff = (uint32_t)(ks * 16 + lhalf) * 2;
            uint32_t bhi[4][2];
#pragma unroll
            for (int g = 0; g < 2; g++) {
                uint32_t r0, r1, r2, r3;
                uint32_t addr = uWH + ((uint32_t)(n0 + g * 16 + lrow) * BSTR) * 2 + colOff;
                LDSM_X4(r0, r1, r2, r3, addr);
                bhi[2 * g][0] = r0; bhi[2 * g][1] = r2;
                bhi[2 * g + 1][0] = r1; bhi[2 * g + 1][1] = r3;
            }
            uint32_t a[4][4];
#pragma unroll
            for (int mt = 0; mt < 4; mt++) {
                uint32_t addr = uAH + ((uint32_t)(m0 + mt * 16 + lrow) * BSTR) * 2 + colOff;
                LDSM_X4(a[mt][0], a[mt][1], a[mt][2], a[mt][3], addr);
            }
#pragma unroll
            for (int mt = 0; mt < 4; mt++)
#pragma unroll
                for (int nt = 0; nt < 4; nt++)
                    mma_bf16(acc[mt][nt], a[mt][0], a[mt][1], a[mt][2], a[mt][3],
                             bhi[nt][0], bhi[nt][1]);
            uint32_t blo[4][2];
#pragma unroll
            for (int g = 0; g < 2; g++) {
                uint32_t r0, r1, r2, r3;
                uint32_t addr = uWL + ((uint32_t)(n0 + g * 16 + lrow) * BSTR) * 2 + colOff;
                LDSM_X4(r0, r1, r2, r3, addr);
                blo[2 * g][0] = r0; blo[2 * g][1] = r2;
                blo[2 * g + 1][0] = r1; blo[2 * g + 1][1] = r3;
            }
#pragma unroll
            for (int mt = 0; mt < 4; mt++)
#pragma unroll
                for (int nt = 0; nt < 4; nt++)
                    mma_bf16(acc[mt][nt], a[mt][0], a[mt][1], a[mt][2], a[mt][3],
                             blo[nt][0], blo[nt][1]);
#pragma unroll
            for (int mt = 0; mt < 4; mt++) {
                uint32_t addr = uAL + ((uint32_t)(m0 + mt * 16 + lrow) * BSTR) * 2 + colOff;
                LDSM_X4(a[mt][0], a[mt][1], a[mt][2], a[mt][3], addr);
            }
#pragma unroll
            for (int mt = 0; mt < 4; mt++)
#pragma unroll
                for (int nt = 0; nt < 4; nt++)
                    mma_bf16(acc[mt][nt], a[mt][0], a[mt][1], a[mt][2], a[mt][3],
                             bhi[nt][0], bhi[nt][1]);
        }

        // epilogue: bias + store + direct-global stats
        float* C = Cj[j];
        const float* bias = bj[j];
#pragma unroll
        for (int nt = 0; nt < 4; nt++) {
            const int col = n0 + nt * 8 + cc2;
            const float bb0 = bias[col], bb1 = bias[col + 1];
            float s0 = 0.0f, s1 = 0.0f, q0 = 0.0f, q1 = 0.0f;
#pragma unroll
            for (int mt = 0; mt < 4; mt++) {
                const long r0 = rowBase + m0 + mt * 16 + cr;
                float x0 = acc[mt][nt][0] + bb0;
                float x1 = acc[mt][nt][1] + bb1;
                float x2 = acc[mt][nt][2] + bb0;
                float x3 = acc[mt][nt][3] + bb1;
                *(float2*)(C + r0 * 128 + col)       = make_float2(x0, x1);
                *(float2*)(C + (r0 + 8) * 128 + col) = make_float2(x2, x3);
                s0 += x0 + x2; s1 += x1 + x3;
                q0 += x0 * x0 + x2 * x2; q1 += x1 * x1 + x3 * x3;
            }
#pragma unroll
            for (int off = 4; off <= 16; off <<= 1) {
                s0 += __shfl_xor_sync(0xffffffffu, s0, off);
                s1 += __shfl_xor_sync(0xffffffffu, s1, off);
                q0 += __shfl_xor_sync(0xffffffffu, q0, off);
                q1 += __shfl_xor_sync(0xffffffffu, q1, off);
            }
            if (cr == 0) {
                atomicAdd(&sumj[j][col], s0);  atomicAdd(&sumj[j][col + 1], s1);
                atomicAdd(&sqj[j][col], q0);   atomicAdd(&sqj[j][col + 1], q1);
            }
        }
    }
}

// ---------------- BN finalize ----------------
__global__ void bn_finalize_kernel(float* __restrict__ statSum, float* __restrict__ statSq,
                                   const float* __restrict__ g, const float* __restrict__ b,
                                   float* __restrict__ sc, float* __restrict__ sh) {
    const int c = threadIdx.x;
    float m = statSum[c] * INV_M;
    float v = statSq[c] * INV_M - m * m;
    float s = g[c] * rsqrtf(v + EPS);
    sc[c] = s;
    sh[c] = b[c] - m * s;
    statSum[c] = 0.0f;
    statSq[c] = 0.0f;
}

// finalize 3 contiguous slots in one launch (384 threads)
__global__ void bn_finalize3_kernel(float* __restrict__ sumBase, float* __restrict__ sqBase,
                                    const float* g0, const float* b0,
                                    const float* g1, const float* b1,
                                    const float* g2, const float* b2,
                                    float* __restrict__ scBase, float* __restrict__ shBase) {
    const int slot = threadIdx.x >> 7, c = threadIdx.x & 127;
    const float* g = (slot == 0) ? g0 : (slot == 1) ? g1 : g2;
    const float* b = (slot == 0) ? b0 : (slot == 1) ? b1 : b2;
    float* statSum = sumBase + slot * DD;
    float* statSq  = sqBase + slot * DD;
    float m = statSum[c] * INV_M;
    float v = statSq[c] * INV_M - m * m;
    float s = g[c] * rsqrtf(v + EPS);
    scBase[slot * DD + c] = s;
    shBase[slot * DD + c] = b[c] - m * s;
    statSum[c] = 0.0f;
    statSq[c] = 0.0f;
}

// ================= Attention v3: HMMA with bf16 hi/lo splits =================
// Block = one (n, h), 256 threads (8 warps).
// S = Q*K^T (3-pass split), p = exp(S*mask), O = P*V (3-pass split), out = O / rowsum.
#define QSTR 40
#define PSTR 136
#define AQH  0
#define AQL  5120
#define AKH  10240
#define AKL  15360
#define AVTH 20480
#define AVTL 24832
#define APH  29184
#define APL  46592
#define AEND 64000                         // bf16 elems
#define ATTN_SMEM (AEND * 2 + 512)         // + rowsum[128] floats = 128512 B

__global__ void __launch_bounds__(256)
attn_kernel(const float* __restrict__ q,
            const float* __restrict__ k,
            const float* __restrict__ v,
            const float* __restrict__ mask,
            const float* __restrict__ scQ, const float* __restrict__ shQ,
            const float* __restrict__ scK, const float* __restrict__ shK,
            const float* __restrict__ scV, const float* __restrict__ shV,
            float* __restrict__ out) {
    extern __shared__ __nv_bfloat16 smem[];
    float* rowsum = (float*)(smem + AEND);

    const int h = blockIdx.x;
    const int n = blockIdx.y;
    const int tid = threadIdx.x;
    const long base = (long)n * SS * DD + h * CC;
    const long mbase = (long)n * SS * SS;
    const int dBase = h * CC;

    if (tid < 128) rowsum[tid] = 0.0f;

    // ---- stage Q, K as hi/lo [128][QSTR] ----
    for (int idx = tid; idx < 1024; idx += 256) {
        int r = idx >> 3, c0 = (idx & 7) * 4;
        int d = dBase + c0;
        float4 s4 = *(const float4*)(scQ + d);
        float4 t4 = *(const float4*)(shQ + d);
        float4 x = *(const float4*)(q + base + (long)r * 128 + c0);
        x.x = x.x * s4.x + t4.x; x.y = x.y * s4.y + t4.y;
        x.z = x.z * s4.z + t4.z; x.w = x.w * s4.w + t4.w;
        float h0 = __bfloat162float(__float2bfloat16_rn(x.x));
        float h1 = __bfloat162float(__float2bfloat16_rn(x.y));
        float h2 = __bfloat162float(__float2bfloat16_rn(x.z));
        float h3 = __bfloat162float(__float2bfloat16_rn(x.w));
        *(uint2*)(smem + AQH + r * QSTR + c0) = make_uint2(packbf(x.x, x.y), packbf(x.z, x.w));
        *(uint2*)(smem + AQL + r * QSTR + c0) =
            make_uint2(packbf(x.x - h0, x.y - h1), packbf(x.z - h2, x.w - h3));

        s4 = *(const float4*)(scK + d);
        t4 = *(const float4*)(shK + d);
        x = *(const float4*)(k + base + (long)r * 128 + c0);
        x.x = x.x * s4.x + t4.x; x.y = x.y * s4.y + t4.y;
        x.z = x.z * s4.z + t4.z; x.w = x.w * s4.w + t4.w;
        h0 = __bfloat162float(__float2bfloat16_rn(x.x));
        h1 = __bfloat162float(__float2bfloat16_rn(x.y));
        h2 = __bfloat162float(__float2bfloat16_rn(x.z));
        h3 = __bfloat162float(__float2bfloat16_rn(x.w));
        *(uint2*)(smem + AKH + r * QSTR + c0) = make_uint2(packbf(x.x, x.y), packbf(x.z, x.w));
        *(uint2*)(smem + AKL + r * QSTR + c0) =
            make_uint2(packbf(x.x - h0, x.y - h1), packbf(x.z - h2, x.w - h3));
    }
    // ---- stage V transposed: VT[c][t], hi/lo [32][PSTR] ----
    for (int idx = tid; idx < 1024; idx += 256) {
        int r = idx >> 3, c0 = (idx & 7) * 4;   // r = t, c0 = feature
        int d = dBase + c0;
        float4 s4 = *(const float4*)(scV + d);
        float4 t4 = *(const float4*)(shV + d);
        float4 x = *(const float4*)(v + base + (long)r * 128 + c0);
        float val[4];
        val[0] = x.x * s4.x + t4.x; val[1] = x.y * s4.y + t4.y;
        val[2] = x.z * s4.z + t4.z; val[3] = x.w * s4.w + t4.w;
#pragma unroll
        for (int j = 0; j < 4; j++) {
            __nv_bfloat16 hi = __float2bfloat16_rn(val[j]);
            smem[AVTH + (c0 + j) * PSTR + r] = hi;
            smem[AVTL + (c0 + j) * PSTR + r] =
                __float2bfloat16_rn(val[j] - __bfloat162float(hi));
        }
    }
    __syncthreads();

    const int warp = tid >> 5, lane = tid & 31;
    const int lrow = lane & 15, lhalf = (lane >> 4) * 8;
    const int cr = lane >> 2, cc2 = (lane & 3) * 2;

    const uint32_t uQH = smem_u32(smem + AQH), uQL = smem_u32(smem + AQL);
    const uint32_t uKH = smem_u32(smem + AKH), uKL = smem_u32(smem + AKL);

    // ======== S phase: warp grid 2x4, warp tile 64x32, K=32 (2 k-steps) ========
    {
        const int wm = warp >> 2, wn = warp & 3;
        const int m0 = wm * 64, n0 = wn * 32;

        float acc[4][4][4];
#pragma unroll
        for (int mt = 0; mt < 4; mt++)
#pragma unroll
            for (int nt = 0; nt < 4; nt++)
#pragma unroll
                for (int i = 0; i < 4; i++) acc[mt][nt][i] = 0.0f;

#pragma unroll
        for (int ks = 0; ks < 2; ks++) {
            const uint32_t colOff = (uint32_t)(ks * 16 + lhalf) * 2;
            uint32_t bhi[4][2];
#pragma unroll
            for (int g = 0; g < 2; g++) {
                uint32_t r0, r1, r2, r3;
                uint32_t addr = uKH + ((uint32_t)(n0 + g * 16 + lrow) * QSTR) * 2 + colOff;
                LDSM_X4(r0, r1, r2, r3, addr);
                bhi[2 * g][0] = r0; bhi[2 * g][1] = r2;
                bhi[2 * g + 1][0] = r1; bhi[2 * g + 1][1] = r3;
            }
            uint32_t a[4][4];
#pragma unroll
            for (int mt = 0; mt < 4; mt++) {
                uint32_t addr = uQH + ((uint32_t)(m0 + mt * 16 + lrow) * QSTR) * 2 + colOff;
                LDSM_X4(a[mt][0], a[mt][1], a[mt][2], a[mt][3], addr);
            }
#pragma unroll
            for (int mt = 0; mt < 4; mt++)
#pragma unroll
                for (int nt = 0; nt < 4; nt++)
                    mma_bf16(acc[mt][nt], a[mt][0], a[mt][1], a[mt][2], a[mt][3],
                             bhi[nt][0], bhi[nt][1]);
            uint32_t blo[4][2];
#pragma unroll
            for (int g = 0; g < 2; g++) {
                uint32_t r0, r1, r2, r3;
                uint32_t addr = uKL + ((uint32_t)(n0 + g * 16 + lrow) * QSTR) * 2 + colOff;
                LDSM_X4(r0, r1, r2, r3, addr);
                blo[2 * g][0] = r0; blo[2 * g][1] = r2;
                blo[2 * g + 1][0] = r1; blo[2 * g + 1][1] = r3;
            }
#pragma unroll
            for (int mt = 0; mt < 4; mt++)
#pragma unroll
                for (int nt = 0; nt < 4; nt++)
                    mma_bf16(acc[mt][nt], a[mt][0], a[mt][1], a[mt][2], a[mt][3],
                             blo[nt][0], blo[nt][1]);
#pragma unroll
            for (int mt = 0; mt < 4; mt++) {
                uint32_t addr = uQL + ((uint32_t)(m0 + mt * 16 + lrow) * QSTR) * 2 + colOff;
                LDSM_X4(a[mt][0], a[mt][1], a[mt][2], a[mt][3], addr);
            }
#pragma unroll
            for (int mt = 0; mt < 4; mt++)
#pragma unroll
                for (int nt = 0; nt < 4; nt++)
                    mma_bf16(acc[mt][nt], a[mt][0], a[mt][1], a[mt][2], a[mt][3],
                             bhi[nt][0], bhi[nt][1]);
        }

        // epilogue: mask (gmem), exp, row sums, store P hi/lo
#pragma unroll
        for (int mt = 0; mt < 4; mt++) {
            const int row0 = m0 + mt * 16 + cr;
            float s0 = 0.0f, s1 = 0.0f;
#pragma unroll
            for (int nt = 0; nt < 4; nt++) {
                const int col = n0 + nt * 8 + cc2;
                float2 mv0 = *(const float2*)(mask + mbase + (long)row0 * 128 + col);
                float2 mv1 = *(const float2*)(mask + mbase + (long)(row0 + 8) * 128 + col);
                float p00 = __expf(acc[mt][nt][0] * mv0.x);
                float p01 = __expf(acc[mt][nt][1] * mv0.y);
                float p10 = __expf(acc[mt][nt][2] * mv1.x);
                float p11 = __expf(acc[mt][nt][3] * mv1.y);
                s0 += p00 + p01;
                s1 += p10 + p11;
                __nv_bfloat16 h00 = __float2bfloat16_rn(p00);
                __nv_bfloat16 h01 = __float2bfloat16_rn(p01);
                __nv_bfloat16 h10 = __float2bfloat16_rn(p10);
                __nv_bfloat16 h11 = __float2bfloat16_rn(p11);
                *(uint32_t*)(smem + APH + row0 * PSTR + col) =
                    packbf(__bfloat162float(h00), __bfloat162float(h01));
                *(uint32_t*)(smem + APH + (row0 + 8) * PSTR + col) =
                    packbf(__bfloat162float(h10), __bfloat162float(h11));
                *(uint32_t*)(smem + APL + row0 * PSTR + col) =
                    packbf(p00 - __bfloat162float(h00), p01 - __bfloat162float(h01));
                *(uint32_t*)(smem + APL + (row0 + 8) * PSTR + col) =
                    packbf(p10 - __bfloat162float(h10), p11 - __bfloat162float(h11));
            }
            s0 += __shfl_xor_sync(0xffffffffu, s0, 1);
            s0 += __shfl_xor_sync(0xffffffffu, s0, 2);
            s1 += __shfl_xor_sync(0xffffffffu, s1, 1);
            s1 += __shfl_xor_sync(0xffffffffu, s1, 2);
            if ((lane & 3) == 0) {
                atomicAdd(&rowsum[row0], s0);
                atomicAdd(&rowsum[row0 + 8], s1);
            }
        }
    }
    __syncthreads();

    // ======== PV phase: warp grid 8x1, warp tile 16x32, K=128 (8 k-steps) ========
    {
        const int m0 = warp * 16;
        const uint32_t uPH = smem_u32(smem + APH), uPL = smem_u32(smem + APL);
        const uint32_t uVH = smem_u32(smem + AVTH), uVL = smem_u32(smem + AVTL);

        float acc[4][4];
#pragma unroll
        for (int nt = 0; nt < 4; nt++)
#pragma unroll
            for (int i = 0; i < 4; i++) acc[nt][i] = 0.0f;

#pragma unroll
        for (int ks = 0; ks < 8; ks++) {
            const uint32_t colOff = (uint32_t)(ks * 16 + lhalf) * 2;
            uint32_t bhi[4][2];
#pragma unroll
            for (int g = 0; g < 2; g++) {
                uint32_t r0, r1, r2, r3;
                uint32_t addr = uVH + ((uint32_t)(g * 16 + lrow) * PSTR) * 2 + colOff;
                LDSM_X4(r0, r1, r2, r3, addr);
                bhi[2 * g][0] = r0; bhi[2 * g][1] = r2;
                bhi[2 * g + 1][0] = r1; bhi[2 * g + 1][1] = r3;
            }
            uint32_t a[4];
            {
                uint32_t addr = uPH + ((uint32_t)(m0 + lrow) * PSTR) * 2 + colOff;
                LDSM_X4(a[0], a[1], a[2], a[3], addr);
            }
#pragma unroll
            for (int nt = 0; nt < 4; nt++)
                mma_bf16(acc[nt], a[0], a[1], a[2], a[3], bhi[nt][0], bhi[nt][1]);
            uint32_t blo[4][2];
#pragma unroll
            for (int g = 0; g < 2; g++) {
                uint32_t r0, r1, r2, r3;
                uint32_t addr = uVL + ((uint32_t)(g * 16 + lrow) * PSTR) * 2 + colOff;
                LDSM_X4(r0, r1, r2, r3, addr);
                blo[2 * g][0] = r0; blo[2 * g][1] = r2;
                blo[2 * g + 1][0] = r1; blo[2 * g + 1][1] = r3;
            }
#pragma unroll
            for (int nt = 0; nt < 4; nt++)
                mma_bf16(acc[nt], a[0], a[1], a[2], a[3], blo[nt][0], blo[nt][1]);
            {
                uint32_t addr = uPL + ((uint32_t)(m0 + lrow) * PSTR) * 2 + colOff;
                LDSM_X4(a[0], a[1], a[2], a[3], addr);
            }
#pragma unroll
            for (int nt = 0; nt < 4; nt++)
                mma_bf16(acc[nt], a[0], a[1], a[2], a[3], bhi[nt][0], bhi[nt][1]);
        }

        const int row0 = m0 + cr;
        const float inv0 = 1.0f / rowsum[row0];
        const float inv1 = 1.0f / rowsum[row0 + 8];
#pragma unroll
        for (int nt = 0; nt < 4; nt++) {
            const int col = nt * 8 + cc2;
            *(float2*)(out + base + (long)row0 * 128 + col) =
                make_float2(acc[nt][0] * inv0, acc[nt][1] * inv0);
            *(float2*)(out + base + (long)(row0 + 8) * 128 + col) =
                make_float2(acc[nt][2] * inv1, acc[nt][3] * inv1);
        }
    }
}

// ---------------- out = LayerNorm(A + affine(B)) per row, warp per row ----------------
__global__ void add_ln_kernel(const float* __restrict__ A,
                              const float* __restrict__ B,
                              const float* __restrict__ scB,
                              const float* __restrict__ shB,
                              const float* __restrict__ gam,
                              const float* __restrict__ bet,
                              float* __restrict__ Out) {
    const int w = threadIdx.x >> 5, lane = threadIdx.x & 31;
    const long row = (long)blockIdx.x * 8 + w;
    const float* a = A + row * 128;
    const float* b = B + row * 128;

    float x[4];
    float s = 0.0f, s2 = 0.0f;
#pragma unroll
    for (int i = 0; i < 4; i++) {
        int c = lane + 32 * i;
        float bv = b[c];
        if (scB) bv = bv * scB[c] + shB[c];
        x[i] = a[c] + bv;
        s += x[i];
        s2 += x[i] * x[i];
    }
#pragma unroll
    for (int o = 16; o > 0; o >>= 1) {
        s  += __shfl_xor_sync(0xffffffffu, s, o);
        s2 += __shfl_xor_sync(0xffffffffu, s2, o);
    }
    const float m = s * (1.0f / 128.0f);
    const float var = s2 * (1.0f / 128.0f) - m * m;
    const float r = rsqrtf(var + EPS);
#pragma unroll
    for (int i = 0; i < 4; i++) {
        int c = lane + 32 * i;
        Out[row * 128 + c] = (x[i] - m) * r * gam[c] + bet[c];
    }
}

// ---------------- h = A + affine(B) ----------------
__global__ void add_affine_kernel(const float* __restrict__ A,
                                  const float* __restrict__ B,
                                  const float* __restrict__ sc,
                                  const float* __restrict__ sh,
                                  float* __restrict__ Out) {
    __shared__ float s_sc[128], s_sh[128];
    const int tid = threadIdx.x;
    if (tid < 128) { s_sc[tid] = sc[tid]; s_sh[tid] = sh[tid]; }
    __syncthreads();
    long i = ((long)blockIdx.x * blockDim.x + tid) * 4;
    const long stride = (long)gridDim.x * blockDim.x * 4;
    for (; i < MSZ; i += stride) {
        float4 a = *(const float4*)(A + i);
        float4 b = *(const float4*)(B + i);
        int c = (int)(i & 127);
        float4 y;
        y.x = a.x + b.x * s_sc[c]     + s_sh[c];
        y.y = a.y + b.y * s_sc[c + 1] + s_sh[c + 1];
        y.z = a.z + b.z * s_sc[c + 2] + s_sh[c + 2];
        y.w = a.w + b.w * s_sc[c + 3] + s_sh[c + 3];
        *(float4*)(Out + i) = y;
    }
}

// ---------------- gather h[:, 0] -> out[N, D] ----------------
__global__ void gather_kernel(const float* __restrict__ H, float* __restrict__ Out) {
    int i = blockIdx.x * blockDim.x + threadIdx.x;
    int n = i >> 7, d = i & 127;
    Out[i] = H[(long)n * SS * DD + d];
}

// ---------------- host orchestration ----------------
extern "C" void kernel_launch(void* const* d_in, const int* in_sizes, int n_in,
                              void* d_out, int out_size) {
    const float* x        = (const float*)d_in[0];
    const float* mask     = (const float*)d_in[1];
    const float* lin_in_W = (const float*)d_in[2];
    const float* lin_in_b = (const float*)d_in[3];
    const float* in_bn_g  = (const float*)d_in[4];
    const float* in_bn_b  = (const float*)d_in[5];
    const float* q_W      = (const float*)d_in[6];
    const float* q_b      = (const float*)d_in[7];
    const float* q_bn_g   = (const float*)d_in[8];
    const float* q_bn_b   = (const float*)d_in[9];
    const float* k_W      = (const float*)d_in[10];
    const float* k_b      = (const float*)d_in[11];
    const float* k_bn_g   = (const float*)d_in[12];
    const float* k_bn_b   = (const float*)d_in[13];
    const float* v_W      = (const float*)d_in[14];
    const float* v_b      = (const float*)d_in[15];
    const float* v_bn_g   = (const float*)d_in[16];
    const float* v_bn_b   = (const float*)d_in[17];
    const float* ln_g     = (const float*)d_in[18];
    const float* ln_b     = (const float*)d_in[19];
    const float* ff_W     = (const float*)d_in[20];
    const float* ff_b     = (const float*)d_in[21];
    const float* ff_bn_g  = (const float*)d_in[22];
    const float* ff_bn_b  = (const float*)d_in[23];
    const float* skip_W   = (const float*)d_in[24];
    const float* skip_b   = (const float*)d_in[25];
    const float* skip_bn_g= (const float*)d_in[26];
    const float* skip_bn_b= (const float*)d_in[27];
    float* out = (float*)d_out;

    cudaFuncSetAttribute(gemm_tc_kernel, cudaFuncAttributeMaxDynamicSharedMemorySize, GEMM_SMEM);
    cudaFuncSetAttribute(attn_kernel, cudaFuncAttributeMaxDynamicSharedMemorySize, ATTN_SMEM);

    float *bh, *bt, *bq, *bk, *bv, *ba, *bo, *bf, *bsum, *bsq, *bsc, *bsh;
    cudaGetSymbolAddress((void**)&bh, g_h);
    cudaGetSymbolAddress((void**)&bt, g_t);
    cudaGetSymbolAddress((void**)&bq, g_q);
    cudaGetSymbolAddress((void**)&bk, g_k);
    cudaGetSymbolAddress((void**)&bv, g_v);
    cudaGetSymbolAddress((void**)&ba, g_a);
    cudaGetSymbolAddress((void**)&bo, g_o);
    cudaGetSymbolAddress((void**)&bf, g_f);
    cudaGetSymbolAddress((void**)&bsum, g_stat_sum);
    cudaGetSymbolAddress((void**)&bsq, g_stat_sq);
    cudaGetSymbolAddress((void**)&bsc, g_scb);
    cudaGetSymbolAddress((void**)&bsh, g_shb);

    auto SUM = [&](int i) { return bsum + i * DD; };
    auto SQ  = [&](int i) { return bsq + i * DD; };
    auto SC  = [&](int i) { return bsc + i * DD; };
    auto SH  = [&](int i) { return bsh + i * DD; };

    const int GEMM_GRID = M_ROWS / 256;   // 512

    auto runGemm1 = [&](const float* A, const float* W, const float* bias,
                        const float* scA, const float* shA, int slot, float* C) {
        gemm_tc_kernel<<<GEMM_GRID, 512, GEMM_SMEM>>>(
            A, scA, shA, W, W, W, bias, bias, bias, C, C, C,
            SUM(slot), SUM(slot), SUM(slot), SQ(slot), SQ(slot), SQ(slot), 1);
    };
    auto runFin = [&](int slot, const float* g, const float* b) {
        bn_finalize_kernel<<<1, 128>>>(SUM(slot), SQ(slot), g, b, SC(slot), SH(slot));
    };

    // t0 = x @ Win^T + b ; stats -> slot 0
    runGemm1(x, lin_in_W, lin_in_b, 0, 0, 0, bt);
    runFin(0, in_bn_g, in_bn_b);

    for (int l = 0; l < LL; l++) {
        const long wOff = (long)l * DD * DD;
        const long vOff = (long)l * DD;
        const float* hp  = (l == 0) ? bt : bh;
        const float* scH = (l == 0) ? SC(0) : 0;
        const float* shH = (l == 0) ? SH(0) : 0;

        // fused QKV GEMM -> slots 1,2,3
        gemm_tc_kernel<<<GEMM_GRID, 512, GEMM_SMEM>>>(
            hp, scH, shH,
            q_W + wOff, k_W + wOff, v_W + wOff,
            q_b + vOff, k_b + vOff, v_b + vOff,
            bq, bk, bv,
            SUM(1), SUM(2), SUM(3), SQ(1), SQ(2), SQ(3), 3);
        bn_finalize3_kernel<<<1, 384>>>(SUM(1), SQ(1),
                                        q_bn_g + vOff, q_bn_b + vOff,
                                        k_bn_g + vOff, k_bn_b + vOff,
                                        v_bn_g + vOff, v_bn_b + vOff,
                                        SC(1), SH(1));

        dim3 agrid(HH, NB);
        attn_kernel<<<agrid, 256, ATTN_SMEM>>>(bq, bk, bv, mask,
                                               SC(1), SH(1), SC(2), SH(2), SC(3), SH(3), ba);

        add_ln_kernel<<<M_ROWS / 8, 256>>>(ba, hp, scH, shH, ln_g + vOff, ln_b + vOff, bo);

        runGemm1(bo, ff_W + wOff, ff_b + vOff, 0, 0, 4, bf);
        runFin(4, ff_bn_g + vOff, ff_bn_b + vOff);
        add_ln_kernel<<<M_ROWS / 8, 256>>>(bo, bf, SC(4), SH(4), ln_g + vOff, ln_b + vOff, ba);

        runGemm1(hp, skip_W + wOff, skip_b + vOff, scH, shH, 5, bf);
        runFin(5, skip_bn_g + vOff, skip_bn_b + vOff);
        add_affine_kernel<<<4096, 256>>>(ba, bf, SC(5), SH(5), bh);
    }

    gather_kernel<<<(NB * DD) / 256, 256>>>(bh, out);
}

// round 8
// speedup vs baseline: 2.0756x; 1.0344x over previous
#include <cuda_runtime.h>
#include <cuda_bf16.h>
#include <math.h>
#include <stdint.h>

// ---------------- problem constants ----------------
#define NB      1024
#define SS      128
#define DD      128
#define HH      4
#define CC      32
#define LL      2
#define M_ROWS  (NB * SS)          // 131072
#define MSZ     (M_ROWS * DD)      // 16777216 floats = 64 MB
#define EPS     1e-5f
#define INV_M   (1.0f / (float)M_ROWS)

// ---------------- scratch (device globals; no allocation allowed) ----------------
__device__ float g_h[MSZ];
__device__ float g_t[MSZ];
__device__ float g_q[MSZ];
__device__ float g_k[MSZ];
__device__ float g_v[MSZ];
__device__ float g_s[MSZ];
__device__ float g_a[MSZ];
__device__ float g_o[MSZ];
__device__ float g_f[MSZ];
__device__ float g_stat_sum[6][DD];   // zeroed by finalize after use
__device__ float g_stat_sq[6][DD];
__device__ float g_scb[6][DD];
__device__ float g_shb[6][DD];

// ================= helpers =================
__device__ __forceinline__ uint32_t smem_u32(const void* p) {
    uint32_t a;
    asm("{ .reg .u64 t; cvta.to.shared.u64 t, %1; cvt.u32.u64 %0, t; }" : "=r"(a) : "l"(p));
    return a;
}
__device__ __forceinline__ uint32_t packbf(float a, float b) {
    __nv_bfloat162 t = __floats2bfloat162_rn(a, b);
    return *(uint32_t*)&t;
}

#define LDSM_X4(r0, r1, r2, r3, addr) \
    asm volatile("ldmatrix.sync.aligned.m8n8.x4.shared.b16 {%0,%1,%2,%3}, [%4];" \
                 : "=r"(r0), "=r"(r1), "=r"(r2), "=r"(r3) : "r"(addr))

__device__ __forceinline__ void mma_bf16(float c[4],
                                         uint32_t a0, uint32_t a1, uint32_t a2, uint32_t a3,
                                         uint32_t b0, uint32_t b1) {
    asm volatile(
        "mma.sync.aligned.m16n8k16.row.col.f32.bf16.bf16.f32 "
        "{%0,%1,%2,%3}, {%4,%5,%6,%7}, {%8,%9}, {%0,%1,%2,%3};"
        : "+f"(c[0]), "+f"(c[1]), "+f"(c[2]), "+f"(c[3])
        : "r"(a0), "r"(a1), "r"(a2), "r"(a3), "r"(b0), "r"(b1));
}

// ================= GEMM: up to 4 weight sets share one converted A tile =================
#define BSTR 136
#define A_TILE_E (256 * BSTR)
#define W_TILE_E (128 * BSTR)
#define GEMM_SMEM ((2 * A_TILE_E + 2 * W_TILE_E) * 2)   // 208896 B

__global__ void __launch_bounds__(512)
gemm_tc_kernel(const float* __restrict__ A,
               const float* __restrict__ scA, const float* __restrict__ shA,
               const float* W0, const float* W1, const float* W2, const float* W3,
               const float* b0, const float* b1, const float* b2, const float* b3,
               float* C0, float* C1, float* C2, float* C3,
               float* sum0, float* sum1, float* sum2, float* sum3,
               float* sq0, float* sq1, float* sq2, float* sq3,
               int nW) {
    extern __shared__ __nv_bfloat16 smem[];
    __nv_bfloat16* AH = smem;
    __nv_bfloat16* AL = smem + A_TILE_E;
    __nv_bfloat16* WH = smem + 2 * A_TILE_E;
    __nv_bfloat16* WL = smem + 2 * A_TILE_E + W_TILE_E;

    const float* Wj[4] = {W0, W1, W2, W3};
    const float* bj[4] = {b0, b1, b2, b3};
    float* Cj[4] = {C0, C1, C2, C3};
    float* sumj[4] = {sum0, sum1, sum2, sum3};
    float* sqj[4] = {sq0, sq1, sq2, sq3};

    const int tid = threadIdx.x;
    const long rowBase = (long)blockIdx.x * 256;

    // ---- fill A_hi / A_lo once ----
    for (int idx = tid; idx < 8192; idx += 512) {
        int r = idx >> 5, k0 = (idx & 31) * 4;
        float4 v = *(const float4*)(A + (rowBase + r) * 128 + k0);
        if (scA) {
            float4 s = *(const float4*)(scA + k0);
            float4 t = *(const float4*)(shA + k0);
            v.x = v.x * s.x + t.x; v.y = v.y * s.y + t.y;
            v.z = v.z * s.z + t.z; v.w = v.w * s.w + t.w;
        }
        float h0 = __bfloat162float(__float2bfloat16_rn(v.x));
        float h1 = __bfloat162float(__float2bfloat16_rn(v.y));
        float h2 = __bfloat162float(__float2bfloat16_rn(v.z));
        float h3 = __bfloat162float(__float2bfloat16_rn(v.w));
        *(uint2*)(AH + r * BSTR + k0) = make_uint2(packbf(v.x, v.y), packbf(v.z, v.w));
        *(uint2*)(AL + r * BSTR + k0) =
            make_uint2(packbf(v.x - h0, v.y - h1), packbf(v.z - h2, v.w - h3));
    }

    const int warp = tid >> 5, lane = tid & 31;
    const int wm = warp >> 2, wn = warp & 3;
    const int m0 = wm * 64, n0 = wn * 32;
    const int lrow = lane & 15, lhalf = (lane >> 4) * 8;
    const int cr = lane >> 2, cc2 = (lane & 3) * 2;

    const uint32_t uAH = smem_u32(AH), uAL = smem_u32(AL);
    const uint32_t uWH = smem_u32(WH), uWL = smem_u32(WL);

    for (int j = 0; j < nW; j++) {
        if (j > 0) __syncthreads();
        const float* W = Wj[j];
        for (int idx = tid; idx < 4096; idx += 512) {
            int r = idx >> 5, k0 = (idx & 31) * 4;
            float4 v = *(const float4*)(W + r * 128 + k0);
            float h0 = __bfloat162float(__float2bfloat16_rn(v.x));
            float h1 = __bfloat162float(__float2bfloat16_rn(v.y));
            float h2 = __bfloat162float(__float2bfloat16_rn(v.z));
            float h3 = __bfloat162float(__float2bfloat16_rn(v.w));
            *(uint2*)(WH + r * BSTR + k0) = make_uint2(packbf(v.x, v.y), packbf(v.z, v.w));
            *(uint2*)(WL + r * BSTR + k0) =
                make_uint2(packbf(v.x - h0, v.y - h1), packbf(v.z - h2, v.w - h3));
        }
        __syncthreads();

        float acc[4][4][4];
#pragma unroll
        for (int mt = 0; mt < 4; mt++)
#pragma unroll
            for (int nt = 0; nt < 4; nt++)
#pragma unroll
                for (int i = 0; i < 4; i++) acc[mt][nt][i] = 0.0f;

#pragma unroll
        for (int ks = 0; ks < 8; ks++) {
            const uint32_t colOff = (uint32_t)(ks * 16 + lhalf) * 2;
            uint32_t bhi[4][2];
#pragma unroll
            for (int g = 0; g < 2; g++) {
                uint32_t r0, r1, r2, r3;
                uint32_t addr = uWH + ((uint32_t)(n0 + g * 16 + lrow) * BSTR) * 2 + colOff;
                LDSM_X4(r0, r1, r2, r3, addr);
                bhi[2 * g][0] = r0; bhi[2 * g][1] = r2;
                bhi[2 * g + 1][0] = r1; bhi[2 * g + 1][1] = r3;
            }
            uint32_t a[4][4];
#pragma unroll
            for (int mt = 0; mt < 4; mt++) {
                uint32_t addr = uAH + ((uint32_t)(m0 + mt * 16 + lrow) * BSTR) * 2 + colOff;
                LDSM_X4(a[mt][0], a[mt][1], a[mt][2], a[mt][3], addr);
            }
#pragma unroll
            for (int mt = 0; mt < 4; mt++)
#pragma unroll
                for (int nt = 0; nt < 4; nt++)
                    mma_bf16(acc[mt][nt], a[mt][0], a[mt][1], a[mt][2], a[mt][3],
                             bhi[nt][0], bhi[nt][1]);
            uint32_t blo[4][2];
#pragma unroll
            for (int g = 0; g < 2; g++) {
                uint32_t r0, r1, r2, r3;
                uint32_t addr = uWL + ((uint32_t)(n0 + g * 16 + lrow) * BSTR) * 2 + colOff;
                LDSM_X4(r0, r1, r2, r3, addr);
                blo[2 * g][0] = r0; blo[2 * g][1] = r2;
                blo[2 * g + 1][0] = r1; blo[2 * g + 1][1] = r3;
            }
#pragma unroll
            for (int mt = 0; mt < 4; mt++)
#pragma unroll
                for (int nt = 0; nt < 4; nt++)
                    mma_bf16(acc[mt][nt], a[mt][0], a[mt][1], a[mt][2], a[mt][3],
                             blo[nt][0], blo[nt][1]);
#pragma unroll
            for (int mt = 0; mt < 4; mt++) {
                uint32_t addr = uAL + ((uint32_t)(m0 + mt * 16 + lrow) * BSTR) * 2 + colOff;
                LDSM_X4(a[mt][0], a[mt][1], a[mt][2], a[mt][3], addr);
            }
#pragma unroll
            for (int mt = 0; mt < 4; mt++)
#pragma unroll
                for (int nt = 0; nt < 4; nt++)
                    mma_bf16(acc[mt][nt], a[mt][0], a[mt][1], a[mt][2], a[mt][3],
                             bhi[nt][0], bhi[nt][1]);
        }

        float* C = Cj[j];
        const float* bias = bj[j];
#pragma unroll
        for (int nt = 0; nt < 4; nt++) {
            const int col = n0 + nt * 8 + cc2;
            const float bb0 = bias[col], bb1 = bias[col + 1];
            float s0 = 0.0f, s1 = 0.0f, q0 = 0.0f, q1 = 0.0f;
#pragma unroll
            for (int mt = 0; mt < 4; mt++) {
                const long r0 = rowBase + m0 + mt * 16 + cr;
                float x0 = acc[mt][nt][0] + bb0;
                float x1 = acc[mt][nt][1] + bb1;
                float x2 = acc[mt][nt][2] + bb0;
                float x3 = acc[mt][nt][3] + bb1;
                *(float2*)(C + r0 * 128 + col)       = make_float2(x0, x1);
                *(float2*)(C + (r0 + 8) * 128 + col) = make_float2(x2, x3);
                s0 += x0 + x2; s1 += x1 + x3;
                q0 += x0 * x0 + x2 * x2; q1 += x1 * x1 + x3 * x3;
            }
#pragma unroll
            for (int off = 4; off <= 16; off <<= 1) {
                s0 += __shfl_xor_sync(0xffffffffu, s0, off);
                s1 += __shfl_xor_sync(0xffffffffu, s1, off);
                q0 += __shfl_xor_sync(0xffffffffu, q0, off);
                q1 += __shfl_xor_sync(0xffffffffu, q1, off);
            }
            if (cr == 0) {
                atomicAdd(&sumj[j][col], s0);  atomicAdd(&sumj[j][col + 1], s1);
                atomicAdd(&sqj[j][col], q0);   atomicAdd(&sqj[j][col + 1], q1);
            }
        }
    }
}

// ---------------- BN finalize ----------------
__global__ void bn_finalize_kernel(float* __restrict__ statSum, float* __restrict__ statSq,
                                   const float* __restrict__ g, const float* __restrict__ b,
                                   float* __restrict__ sc, float* __restrict__ sh) {
    const int c = threadIdx.x;
    float m = statSum[c] * INV_M;
    float v = statSq[c] * INV_M - m * m;
    float s = g[c] * rsqrtf(v + EPS);
    sc[c] = s;
    sh[c] = b[c] - m * s;
    statSum[c] = 0.0f;
    statSq[c] = 0.0f;
}

__global__ void bn_finalize3_kernel(float* __restrict__ sumBase, float* __restrict__ sqBase,
                                    const float* g0, const float* b0,
                                    const float* g1, const float* b1,
                                    const float* g2, const float* b2,
                                    float* __restrict__ scBase, float* __restrict__ shBase) {
    const int slot = threadIdx.x >> 7, c = threadIdx.x & 127;
    const float* g = (slot == 0) ? g0 : (slot == 1) ? g1 : g2;
    const float* b = (slot == 0) ? b0 : (slot == 1) ? b1 : b2;
    float* statSum = sumBase + slot * DD;
    float* statSq  = sqBase + slot * DD;
    float m = statSum[c] * INV_M;
    float v = statSq[c] * INV_M - m * m;
    float s = g[c] * rsqrtf(v + EPS);
    scBase[slot * DD + c] = s;
    shBase[slot * DD + c] = b[c] - m * s;
    statSum[c] = 0.0f;
    statSq[c] = 0.0f;
}

// ================= Attention v3: HMMA with bf16 hi/lo splits =================
#define QSTR 40
#define PSTR 136
#define AQH  0
#define AQL  5120
#define AKH  10240
#define AKL  15360
#define AVTH 20480
#define AVTL 24832
#define APH  29184
#define APL  46592
#define AEND 64000
#define ATTN_SMEM (AEND * 2 + 512)

__global__ void __launch_bounds__(256)
attn_kernel(const float* __restrict__ q,
            const float* __restrict__ k,
            const float* __restrict__ v,
            const float* __restrict__ mask,
            const float* __restrict__ scQ, const float* __restrict__ shQ,
            const float* __restrict__ scK, const float* __restrict__ shK,
            const float* __restrict__ scV, const float* __restrict__ shV,
            float* __restrict__ out) {
    extern __shared__ __nv_bfloat16 smem[];
    float* rowsum = (float*)(smem + AEND);

    const int h = blockIdx.x;
    const int n = blockIdx.y;
    const int tid = threadIdx.x;
    const long base = (long)n * SS * DD + h * CC;
    const long mbase = (long)n * SS * SS;
    const int dBase = h * CC;

    if (tid < 128) rowsum[tid] = 0.0f;

    for (int idx = tid; idx < 1024; idx += 256) {
        int r = idx >> 3, c0 = (idx & 7) * 4;
        int d = dBase + c0;
        float4 s4 = *(const float4*)(scQ + d);
        float4 t4 = *(const float4*)(shQ + d);
        float4 x = *(const float4*)(q + base + (long)r * 128 + c0);
        x.x = x.x * s4.x + t4.x; x.y = x.y * s4.y + t4.y;
        x.z = x.z * s4.z + t4.z; x.w = x.w * s4.w + t4.w;
        float h0 = __bfloat162float(__float2bfloat16_rn(x.x));
        float h1 = __bfloat162float(__float2bfloat16_rn(x.y));
        float h2 = __bfloat162float(__float2bfloat16_rn(x.z));
        float h3 = __bfloat162float(__float2bfloat16_rn(x.w));
        *(uint2*)(smem + AQH + r * QSTR + c0) = make_uint2(packbf(x.x, x.y), packbf(x.z, x.w));
        *(uint2*)(smem + AQL + r * QSTR + c0) =
            make_uint2(packbf(x.x - h0, x.y - h1), packbf(x.z - h2, x.w - h3));

        s4 = *(const float4*)(scK + d);
        t4 = *(const float4*)(shK + d);
        x = *(const float4*)(k + base + (long)r * 128 + c0);
        x.x = x.x * s4.x + t4.x; x.y = x.y * s4.y + t4.y;
        x.z = x.z * s4.z + t4.z; x.w = x.w * s4.w + t4.w;
        h0 = __bfloat162float(__float2bfloat16_rn(x.x));
        h1 = __bfloat162float(__float2bfloat16_rn(x.y));
        h2 = __bfloat162float(__float2bfloat16_rn(x.z));
        h3 = __bfloat162float(__float2bfloat16_rn(x.w));
        *(uint2*)(smem + AKH + r * QSTR + c0) = make_uint2(packbf(x.x, x.y), packbf(x.z, x.w));
        *(uint2*)(smem + AKL + r * QSTR + c0) =
            make_uint2(packbf(x.x - h0, x.y - h1), packbf(x.z - h2, x.w - h3));
    }
    for (int idx = tid; idx < 1024; idx += 256) {
        int r = idx >> 3, c0 = (idx & 7) * 4;
        int d = dBase + c0;
        float4 s4 = *(const float4*)(scV + d);
        float4 t4 = *(const float4*)(shV + d);
        float4 x = *(const float4*)(v + base + (long)r * 128 + c0);
        float val[4];
        val[0] = x.x * s4.x + t4.x; val[1] = x.y * s4.y + t4.y;
        val[2] = x.z * s4.z + t4.z; val[3] = x.w * s4.w + t4.w;
#pragma unroll
        for (int j = 0; j < 4; j++) {
            __nv_bfloat16 hi = __float2bfloat16_rn(val[j]);
            smem[AVTH + (c0 + j) * PSTR + r] = hi;
            smem[AVTL + (c0 + j) * PSTR + r] =
                __float2bfloat16_rn(val[j] - __bfloat162float(hi));
        }
    }
    __syncthreads();

    const int warp = tid >> 5, lane = tid & 31;
    const int lrow = lane & 15, lhalf = (lane >> 4) * 8;
    const int cr = lane >> 2, cc2 = (lane & 3) * 2;

    const uint32_t uQH = smem_u32(smem + AQH), uQL = smem_u32(smem + AQL);
    const uint32_t uKH = smem_u32(smem + AKH), uKL = smem_u32(smem + AKL);

    {
        const int wm = warp >> 2, wn = warp & 3;
        const int m0 = wm * 64, n0 = wn * 32;

        float acc[4][4][4];
#pragma unroll
        for (int mt = 0; mt < 4; mt++)
#pragma unroll
            for (int nt = 0; nt < 4; nt++)
#pragma unroll
                for (int i = 0; i < 4; i++) acc[mt][nt][i] = 0.0f;

#pragma unroll
        for (int ks = 0; ks < 2; ks++) {
            const uint32_t colOff = (uint32_t)(ks * 16 + lhalf) * 2;
            uint32_t bhi[4][2];
#pragma unroll
            for (int g = 0; g < 2; g++) {
                uint32_t r0, r1, r2, r3;
                uint32_t addr = uKH + ((uint32_t)(n0 + g * 16 + lrow) * QSTR) * 2 + colOff;
                LDSM_X4(r0, r1, r2, r3, addr);
                bhi[2 * g][0] = r0; bhi[2 * g][1] = r2;
                bhi[2 * g + 1][0] = r1; bhi[2 * g + 1][1] = r3;
            }
            uint32_t a[4][4];
#pragma unroll
            for (int mt = 0; mt < 4; mt++) {
                uint32_t addr = uQH + ((uint32_t)(m0 + mt * 16 + lrow) * QSTR) * 2 + colOff;
                LDSM_X4(a[mt][0], a[mt][1], a[mt][2], a[mt][3], addr);
            }
#pragma unroll
            for (int mt = 0; mt < 4; mt++)
#pragma unroll
                for (int nt = 0; nt < 4; nt++)
                    mma_bf16(acc[mt][nt], a[mt][0], a[mt][1], a[mt][2], a[mt][3],
                             bhi[nt][0], bhi[nt][1]);
            uint32_t blo[4][2];
#pragma unroll
            for (int g = 0; g < 2; g++) {
                uint32_t r0, r1, r2, r3;
                uint32_t addr = uKL + ((uint32_t)(n0 + g * 16 + lrow) * QSTR) * 2 + colOff;
                LDSM_X4(r0, r1, r2, r3, addr);
                blo[2 * g][0] = r0; blo[2 * g][1] = r2;
                blo[2 * g + 1][0] = r1; blo[2 * g + 1][1] = r3;
            }
#pragma unroll
            for (int mt = 0; mt < 4; mt++)
#pragma unroll
                for (int nt = 0; nt < 4; nt++)
                    mma_bf16(acc[mt][nt], a[mt][0], a[mt][1], a[mt][2], a[mt][3],
                             blo[nt][0], blo[nt][1]);
#pragma unroll
            for (int mt = 0; mt < 4; mt++) {
                uint32_t addr = uQL + ((uint32_t)(m0 + mt * 16 + lrow) * QSTR) * 2 + colOff;
                LDSM_X4(a[mt][0], a[mt][1], a[mt][2], a[mt][3], addr);
            }
#pragma unroll
            for (int mt = 0; mt < 4; mt++)
#pragma unroll
                for (int nt = 0; nt < 4; nt++)
                    mma_bf16(acc[mt][nt], a[mt][0], a[mt][1], a[mt][2], a[mt][3],
                             bhi[nt][0], bhi[nt][1]);
        }

#pragma unroll
        for (int mt = 0; mt < 4; mt++) {
            const int row0 = m0 + mt * 16 + cr;
            float s0 = 0.0f, s1 = 0.0f;
#pragma unroll
            for (int nt = 0; nt < 4; nt++) {
                const int col = n0 + nt * 8 + cc2;
                float2 mv0 = *(const float2*)(mask + mbase + (long)row0 * 128 + col);
                float2 mv1 = *(const float2*)(mask + mbase + (long)(row0 + 8) * 128 + col);
                float p00 = __expf(acc[mt][nt][0] * mv0.x);
                float p01 = __expf(acc[mt][nt][1] * mv0.y);
                float p10 = __expf(acc[mt][nt][2] * mv1.x);
                float p11 = __expf(acc[mt][nt][3] * mv1.y);
                s0 += p00 + p01;
                s1 += p10 + p11;
                __nv_bfloat16 h00 = __float2bfloat16_rn(p00);
                __nv_bfloat16 h01 = __float2bfloat16_rn(p01);
                __nv_bfloat16 h10 = __float2bfloat16_rn(p10);
                __nv_bfloat16 h11 = __float2bfloat16_rn(p11);
                *(uint32_t*)(smem + APH + row0 * PSTR + col) =
                    packbf(__bfloat162float(h00), __bfloat162float(h01));
                *(uint32_t*)(smem + APH + (row0 + 8) * PSTR + col) =
                    packbf(__bfloat162float(h10), __bfloat162float(h11));
                *(uint32_t*)(smem + APL + row0 * PSTR + col) =
                    packbf(p00 - __bfloat162float(h00), p01 - __bfloat162float(h01));
                *(uint32_t*)(smem + APL + (row0 + 8) * PSTR + col) =
                    packbf(p10 - __bfloat162float(h10), p11 - __bfloat162float(h11));
            }
            s0 += __shfl_xor_sync(0xffffffffu, s0, 1);
            s0 += __shfl_xor_sync(0xffffffffu, s0, 2);
            s1 += __shfl_xor_sync(0xffffffffu, s1, 1);
            s1 += __shfl_xor_sync(0xffffffffu, s1, 2);
            if ((lane & 3) == 0) {
                atomicAdd(&rowsum[row0], s0);
                atomicAdd(&rowsum[row0 + 8], s1);
            }
        }
    }
    __syncthreads();

    {
        const int m0 = warp * 16;
        const uint32_t uPH = smem_u32(smem + APH), uPL = smem_u32(smem + APL);
        const uint32_t uVH = smem_u32(smem + AVTH), uVL = smem_u32(smem + AVTL);

        float acc[4][4];
#pragma unroll
        for (int nt = 0; nt < 4; nt++)
#pragma unroll
            for (int i = 0; i < 4; i++) acc[nt][i] = 0.0f;

#pragma unroll
        for (int ks = 0; ks < 8; ks++) {
            const uint32_t colOff = (uint32_t)(ks * 16 + lhalf) * 2;
            uint32_t bhi[4][2];
#pragma unroll
            for (int g = 0; g < 2; g++) {
                uint32_t r0, r1, r2, r3;
                uint32_t addr = uVH + ((uint32_t)(g * 16 + lrow) * PSTR) * 2 + colOff;
                LDSM_X4(r0, r1, r2, r3, addr);
                bhi[2 * g][0] = r0; bhi[2 * g][1] = r2;
                bhi[2 * g + 1][0] = r1; bhi[2 * g + 1][1] = r3;
            }
            uint32_t a[4];
            {
                uint32_t addr = uPH + ((uint32_t)(m0 + lrow) * PSTR) * 2 + colOff;
                LDSM_X4(a[0], a[1], a[2], a[3], addr);
            }
#pragma unroll
            for (int nt = 0; nt < 4; nt++)
                mma_bf16(acc[nt], a[0], a[1], a[2], a[3], bhi[nt][0], bhi[nt][1]);
            uint32_t blo[4][2];
#pragma unroll
            for (int g = 0; g < 2; g++) {
                uint32_t r0, r1, r2, r3;
                uint32_t addr = uVL + ((uint32_t)(g * 16 + lrow) * PSTR) * 2 + colOff;
                LDSM_X4(r0, r1, r2, r3, addr);
                blo[2 * g][0] = r0; blo[2 * g][1] = r2;
                blo[2 * g + 1][0] = r1; blo[2 * g + 1][1] = r3;
            }
#pragma unroll
            for (int nt = 0; nt < 4; nt++)
                mma_bf16(acc[nt], a[0], a[1], a[2], a[3], blo[nt][0], blo[nt][1]);
            {
                uint32_t addr = uPL + ((uint32_t)(m0 + lrow) * PSTR) * 2 + colOff;
                LDSM_X4(a[0], a[1], a[2], a[3], addr);
            }
#pragma unroll
            for (int nt = 0; nt < 4; nt++)
                mma_bf16(acc[nt], a[0], a[1], a[2], a[3], bhi[nt][0], bhi[nt][1]);
        }

        const int row0 = m0 + cr;
        const float inv0 = 1.0f / rowsum[row0];
        const float inv1 = 1.0f / rowsum[row0 + 8];
#pragma unroll
        for (int nt = 0; nt < 4; nt++) {
            const int col = nt * 8 + cc2;
            *(float2*)(out + base + (long)row0 * 128 + col) =
                make_float2(acc[nt][0] * inv0, acc[nt][1] * inv0);
            *(float2*)(out + base + (long)(row0 + 8) * 128 + col) =
                make_float2(acc[nt][2] * inv1, acc[nt][3] * inv1);
        }
    }
}

// ---------------- out = LayerNorm(A + affine(B)) per row, warp per row ----------------
__global__ void add_ln_kernel(const float* __restrict__ A,
                              const float* __restrict__ B,
                              const float* __restrict__ scB,
                              const float* __restrict__ shB,
                              const float* __restrict__ gam,
                              const float* __restrict__ bet,
                              float* __restrict__ Out) {
    const int w = threadIdx.x >> 5, lane = threadIdx.x & 31;
    const long row = (long)blockIdx.x * 8 + w;
    const float* a = A + row * 128;
    const float* b = B + row * 128;

    float x[4];
    float s = 0.0f, s2 = 0.0f;
#pragma unroll
    for (int i = 0; i < 4; i++) {
        int c = lane + 32 * i;
        float bv = b[c];
        if (scB) bv = bv * scB[c] + shB[c];
        x[i] = a[c] + bv;
        s += x[i];
        s2 += x[i] * x[i];
    }
#pragma unroll
    for (int o = 16; o > 0; o >>= 1) {
        s  += __shfl_xor_sync(0xffffffffu, s, o);
        s2 += __shfl_xor_sync(0xffffffffu, s2, o);
    }
    const float m = s * (1.0f / 128.0f);
    const float var = s2 * (1.0f / 128.0f) - m * m;
    const float r = rsqrtf(var + EPS);
#pragma unroll
    for (int i = 0; i < 4; i++) {
        int c = lane + 32 * i;
        Out[row * 128 + c] = (x[i] - m) * r * gam[c] + bet[c];
    }
}

// ---------------- h = LN(O + affine4(F)) + affine5(S), warp per row ----------------
__global__ void ln_add_affine_kernel(const float* __restrict__ O,
                                     const float* __restrict__ F,
                                     const float* __restrict__ sc4,
                                     const float* __restrict__ sh4,
                                     const float* __restrict__ Sk,
                                     const float* __restrict__ sc5,
                                     const float* __restrict__ sh5,
                                     const float* __restrict__ gam,
                                     const float* __restrict__ bet,
                                     float* __restrict__ Out) {
    const int w = threadIdx.x >> 5, lane = threadIdx.x & 31;
    const long row = (long)blockIdx.x * 8 + w;
    const float* o = O + row * 128;
    const float* f = F + row * 128;
    const float* sk = Sk + row * 128;

    float x[4];
    float s = 0.0f, s2 = 0.0f;
#pragma unroll
    for (int i = 0; i < 4; i++) {
        int c = lane + 32 * i;
        x[i] = o[c] + f[c] * sc4[c] + sh4[c];
        s += x[i];
        s2 += x[i] * x[i];
    }
#pragma unroll
    for (int off = 16; off > 0; off >>= 1) {
        s  += __shfl_xor_sync(0xffffffffu, s, off);
        s2 += __shfl_xor_sync(0xffffffffu, s2, off);
    }
    const float m = s * (1.0f / 128.0f);
    const float var = s2 * (1.0f / 128.0f) - m * m;
    const float r = rsqrtf(var + EPS);
#pragma unroll
    for (int i = 0; i < 4; i++) {
        int c = lane + 32 * i;
        Out[row * 128 + c] = (x[i] - m) * r * gam[c] + bet[c] + sk[c] * sc5[c] + sh5[c];
    }
}

// ---------------- gather h[:, 0] -> out[N, D] ----------------
__global__ void gather_kernel(const float* __restrict__ H, float* __restrict__ Out) {
    int i = blockIdx.x * blockDim.x + threadIdx.x;
    int n = i >> 7, d = i & 127;
    Out[i] = H[(long)n * SS * DD + d];
}

// ---------------- host orchestration ----------------
extern "C" void kernel_launch(void* const* d_in, const int* in_sizes, int n_in,
                              void* d_out, int out_size) {
    const float* x        = (const float*)d_in[0];
    const float* mask     = (const float*)d_in[1];
    const float* lin_in_W = (const float*)d_in[2];
    const float* lin_in_b = (const float*)d_in[3];
    const float* in_bn_g  = (const float*)d_in[4];
    const float* in_bn_b  = (const float*)d_in[5];
    const float* q_W      = (const float*)d_in[6];
    const float* q_b      = (const float*)d_in[7];
    const float* q_bn_g   = (const float*)d_in[8];
    const float* q_bn_b   = (const float*)d_in[9];
    const float* k_W      = (const float*)d_in[10];
    const float* k_b      = (const float*)d_in[11];
    const float* k_bn_g   = (const float*)d_in[12];
    const float* k_bn_b   = (const float*)d_in[13];
    const float* v_W      = (const float*)d_in[14];
    const float* v_b      = (const float*)d_in[15];
    const float* v_bn_g   = (const float*)d_in[16];
    const float* v_bn_b   = (const float*)d_in[17];
    const float* ln_g     = (const float*)d_in[18];
    const float* ln_b     = (const float*)d_in[19];
    const float* ff_W     = (const float*)d_in[20];
    const float* ff_b     = (const float*)d_in[21];
    const float* ff_bn_g  = (const float*)d_in[22];
    const float* ff_bn_b  = (const float*)d_in[23];
    const float* skip_W   = (const float*)d_in[24];
    const float* skip_b   = (const float*)d_in[25];
    const float* skip_bn_g= (const float*)d_in[26];
    const float* skip_bn_b= (const float*)d_in[27];
    float* out = (float*)d_out;

    cudaFuncSetAttribute(gemm_tc_kernel, cudaFuncAttributeMaxDynamicSharedMemorySize, GEMM_SMEM);
    cudaFuncSetAttribute(attn_kernel, cudaFuncAttributeMaxDynamicSharedMemorySize, ATTN_SMEM);

    float *bh, *bt, *bq, *bk, *bv, *bs, *ba, *bo, *bf, *bsum, *bsq, *bsc, *bsh;
    cudaGetSymbolAddress((void**)&bh, g_h);
    cudaGetSymbolAddress((void**)&bt, g_t);
    cudaGetSymbolAddress((void**)&bq, g_q);
    cudaGetSymbolAddress((void**)&bk, g_k);
    cudaGetSymbolAddress((void**)&bv, g_v);
    cudaGetSymbolAddress((void**)&bs, g_s);
    cudaGetSymbolAddress((void**)&ba, g_a);
    cudaGetSymbolAddress((void**)&bo, g_o);
    cudaGetSymbolAddress((void**)&bf, g_f);
    cudaGetSymbolAddress((void**)&bsum, g_stat_sum);
    cudaGetSymbolAddress((void**)&bsq, g_stat_sq);
    cudaGetSymbolAddress((void**)&bsc, g_scb);
    cudaGetSymbolAddress((void**)&bsh, g_shb);

    auto SUM = [&](int i) { return bsum + i * DD; };
    auto SQ  = [&](int i) { return bsq + i * DD; };
    auto SC  = [&](int i) { return bsc + i * DD; };
    auto SH  = [&](int i) { return bsh + i * DD; };

    const int GEMM_GRID = M_ROWS / 256;   // 512

    auto runGemm1 = [&](const float* A, const float* W, const float* bias,
                        const float* scA, const float* shA, int slot, float* C) {
        gemm_tc_kernel<<<GEMM_GRID, 512, GEMM_SMEM>>>(
            A, scA, shA, W, W, W, W, bias, bias, bias, bias, C, C, C, C,
            SUM(slot), SUM(slot), SUM(slot), SUM(slot),
            SQ(slot), SQ(slot), SQ(slot), SQ(slot), 1);
    };
    auto runFin = [&](int slot, const float* g, const float* b) {
        bn_finalize_kernel<<<1, 128>>>(SUM(slot), SQ(slot), g, b, SC(slot), SH(slot));
    };

    // t0 = x @ Win^T + b ; stats -> slot 0
    runGemm1(x, lin_in_W, lin_in_b, 0, 0, 0, bt);         // launch 1
    runFin(0, in_bn_g, in_bn_b);                          // launch 2

    for (int l = 0; l < LL; l++) {
        const long wOff = (long)l * DD * DD;
        const long vOff = (long)l * DD;
        const float* hp  = (l == 0) ? bt : bh;
        const float* scH = (l == 0) ? SC(0) : 0;
        const float* shH = (l == 0) ? SH(0) : 0;

        // fused Q/K/V/skip GEMM -> slots 1,2,3,5
        gemm_tc_kernel<<<GEMM_GRID, 512, GEMM_SMEM>>>(        // l=0: launch 3
            hp, scH, shH,
            q_W + wOff, k_W + wOff, v_W + wOff, skip_W + wOff,
            q_b + vOff, k_b + vOff, v_b + vOff, skip_b + vOff,
            bq, bk, bv, bs,
            SUM(1), SUM(2), SUM(3), SUM(5),
            SQ(1), SQ(2), SQ(3), SQ(5), 4);
        bn_finalize3_kernel<<<1, 384>>>(SUM(1), SQ(1),        // l=0: launch 4
                                        q_bn_g + vOff, q_bn_b + vOff,
                                        k_bn_g + vOff, k_bn_b + vOff,
                                        v_bn_g + vOff, v_bn_b + vOff,
                                        SC(1), SH(1));
        runFin(5, skip_bn_g + vOff, skip_bn_b + vOff);        // l=0: launch 5

        dim3 agrid(HH, NB);
        attn_kernel<<<agrid, 256, ATTN_SMEM>>>(               // l=0: launch 6 (ncu target)
            bq, bk, bv, mask, SC(1), SH(1), SC(2), SH(2), SC(3), SH(3), ba);

        // out = LN(agg + h)
        add_ln_kernel<<<M_ROWS / 8, 256>>>(ba, hp, scH, shH, ln_g + vOff, ln_b + vOff, bo);

        // ff = out @ ff_W^T + b -> slot 4
        runGemm1(bo, ff_W + wOff, ff_b + vOff, 0, 0, 4, bf);
        runFin(4, ff_bn_g + vOff, ff_bn_b + vOff);

        // h = LN(out + affine4(ff)) + affine5(skip)
        ln_add_affine_kernel<<<M_ROWS / 8, 256>>>(bo, bf, SC(4), SH(4),
                                                  bs, SC(5), SH(5),
                                                  ln_g + vOff, ln_b + vOff, bh);
    }

    gather_kernel<<<(NB * DD) / 256, 256>>>(bh, out);
}

// round 11
// speedup vs baseline: 2.0839x; 1.0040x over previous
#include <cuda_runtime.h>
#include <cuda_bf16.h>
#include <math.h>
#include <stdint.h>

// ---------------- problem constants ----------------
#define NB      1024
#define SS      128
#define DD      128
#define HH      4
#define CC      32
#define LL      2
#define M_ROWS  (NB * SS)
#define MSZ     (M_ROWS * DD)
#define EPS     1e-5f
#define INV_M   (1.0f / (float)M_ROWS)
#define NSLOT   11

// ---------------- scratch ----------------
__device__ float g_h[MSZ];
__device__ float g_t[MSZ];
__device__ float g_q[MSZ];
__device__ float g_k[MSZ];
__device__ float g_v[MSZ];
__device__ float g_s[MSZ];
__device__ float g_a[MSZ];
__device__ float g_o[MSZ];
__device__ float g_f[MSZ];
__device__ float g_stat_sum[NSLOT][DD];
__device__ float g_stat_sq[NSLOT][DD];

// ================= helpers =================
__device__ __forceinline__ uint32_t smem_u32(const void* p) {
    uint32_t a;
    asm("{ .reg .u64 t; cvta.to.shared.u64 t, %1; cvt.u32.u64 %0, t; }" : "=r"(a) : "l"(p));
    return a;
}
__device__ __forceinline__ uint32_t packbf(float a, float b) {
    __nv_bfloat162 t = __floats2bfloat162_rn(a, b);
    return *(uint32_t*)&t;
}
__device__ __forceinline__ void bn_affine(const float* sum, const float* sq,
                                          const float* g, const float* b, int c,
                                          float& sc, float& sh) {
    float m = sum[c] * INV_M;
    float var = sq[c] * INV_M - m * m;
    float s = g[c] * rsqrtf(var + EPS);
    sc = s;
    sh = b[c] - m * s;
}

#define LDSM_X4(r0, r1, r2, r3, addr) \
    asm volatile("ldmatrix.sync.aligned.m8n8.x4.shared.b16 {%0,%1,%2,%3}, [%4];" \
                 : "=r"(r0), "=r"(r1), "=r"(r2), "=r"(r3) : "r"(addr))

__device__ __forceinline__ void mma_bf16(float c[4],
                                         uint32_t a0, uint32_t a1, uint32_t a2, uint32_t a3,
                                         uint32_t b0, uint32_t b1) {
    asm volatile(
        "mma.sync.aligned.m16n8k16.row.col.f32.bf16.bf16.f32 "
        "{%0,%1,%2,%3}, {%4,%5,%6,%7}, {%8,%9}, {%0,%1,%2,%3};"
        : "+f"(c[0]), "+f"(c[1]), "+f"(c[2]), "+f"(c[3])
        : "r"(a0), "r"(a1), "r"(a2), "r"(a3), "r"(b0), "r"(b1));
}

// ---------------- zero all stat slots (start of graph) ----------------
__global__ void zero_stats_kernel() {
    int i = blockIdx.x * blockDim.x + threadIdx.x;
    if (i < NSLOT * DD) {
        ((float*)g_stat_sum)[i] = 0.0f;
        ((float*)g_stat_sq)[i] = 0.0f;
    }
}

// ================= GEMM: up to 4 weight sets share one converted A tile =================
#define BSTR 136
#define A_TILE_E (256 * BSTR)
#define W_TILE_E (128 * BSTR)
#define GEMM_SMEM ((2 * A_TILE_E + 2 * W_TILE_E) * 2 + 1024)

__global__ void __launch_bounds__(512)
gemm_tc_kernel(const float* __restrict__ A,
               const float* __restrict__ sumA, const float* __restrict__ sqA,
               const float* __restrict__ gA, const float* __restrict__ bA,
               const float* W0, const float* W1, const float* W2, const float* W3,
               const float* b0, const float* b1, const float* b2, const float* b3,
               float* C0, float* C1, float* C2, float* C3,
               float* sum0, float* sum1, float* sum2, float* sum3,
               float* sq0, float* sq1, float* sq2, float* sq3,
               int nW) {
    extern __shared__ __nv_bfloat16 smem[];
    __nv_bfloat16* AH = smem;
    __nv_bfloat16* AL = smem + A_TILE_E;
    __nv_bfloat16* WH = smem + 2 * A_TILE_E;
    __nv_bfloat16* WL = smem + 2 * A_TILE_E + W_TILE_E;
    float* sAff = (float*)(smem + 2 * A_TILE_E + 2 * W_TILE_E);   // [256]

    const float* Wj[4] = {W0, W1, W2, W3};
    const float* bj[4] = {b0, b1, b2, b3};
    float* Cj[4] = {C0, C1, C2, C3};
    float* sumj[4] = {sum0, sum1, sum2, sum3};
    float* sqj[4] = {sq0, sq1, sq2, sq3};

    const int tid = threadIdx.x;
    const long rowBase = (long)blockIdx.x * 256;

    if (gA && tid < 128) {
        float sc, sh;
        bn_affine(sumA, sqA, gA, bA, tid, sc, sh);
        sAff[tid] = sc;
        sAff[128 + tid] = sh;
    }
    __syncthreads();

    for (int idx = tid; idx < 8192; idx += 512) {
        int r = idx >> 5, k0 = (idx & 31) * 4;
        float4 v = *(const float4*)(A + (rowBase + r) * 128 + k0);
        if (gA) {
            float4 s = *(const float4*)(sAff + k0);
            float4 t = *(const float4*)(sAff + 128 + k0);
            v.x = v.x * s.x + t.x; v.y = v.y * s.y + t.y;
            v.z = v.z * s.z + t.z; v.w = v.w * s.w + t.w;
        }
        float h0 = __bfloat162float(__float2bfloat16_rn(v.x));
        float h1 = __bfloat162float(__float2bfloat16_rn(v.y));
        float h2 = __bfloat162float(__float2bfloat16_rn(v.z));
        float h3 = __bfloat162float(__float2bfloat16_rn(v.w));
        *(uint2*)(AH + r * BSTR + k0) = make_uint2(packbf(v.x, v.y), packbf(v.z, v.w));
        *(uint2*)(AL + r * BSTR + k0) =
            make_uint2(packbf(v.x - h0, v.y - h1), packbf(v.z - h2, v.w - h3));
    }

    const int warp = tid >> 5, lane = tid & 31;
    const int wm = warp >> 2, wn = warp & 3;
    const int m0 = wm * 64, n0 = wn * 32;
    const int lrow = lane & 15, lhalf = (lane >> 4) * 8;
    const int cr = lane >> 2, cc2 = (lane & 3) * 2;

    const uint32_t uAH = smem_u32(AH), uAL = smem_u32(AL);
    const uint32_t uWH = smem_u32(WH), uWL = smem_u32(WL);

    for (int j = 0; j < nW; j++) {
        if (j > 0) __syncthreads();
        const float* W = Wj[j];
        for (int idx = tid; idx < 4096; idx += 512) {
            int r = idx >> 5, k0 = (idx & 31) * 4;
            float4 v = *(const float4*)(W + r * 128 + k0);
            float h0 = __bfloat162float(__float2bfloat16_rn(v.x));
            float h1 = __bfloat162float(__float2bfloat16_rn(v.y));
            float h2 = __bfloat162float(__float2bfloat16_rn(v.z));
            float h3 = __bfloat162float(__float2bfloat16_rn(v.w));
            *(uint2*)(WH + r * BSTR + k0) = make_uint2(packbf(v.x, v.y), packbf(v.z, v.w));
            *(uint2*)(WL + r * BSTR + k0) =
                make_uint2(packbf(v.x - h0, v.y - h1), packbf(v.z - h2, v.w - h3));
        }
        __syncthreads();

        float acc[4][4][4];
#pragma unroll
        for (int mt = 0; mt < 4; mt++)
#pragma unroll
            for (int nt = 0; nt < 4; nt++)
#pragma unroll
                for (int i = 0; i < 4; i++) acc[mt][nt][i] = 0.0f;

#pragma unroll
        for (int ks = 0; ks < 8; ks++) {
            const uint32_t colOff = (uint32_t)(ks * 16 + lhalf) * 2;
            uint32_t bhi[4][2];
#pragma unroll
            for (int g = 0; g < 2; g++) {
                uint32_t r0, r1, r2, r3;
                uint32_t addr = uWH + ((uint32_t)(n0 + g * 16 + lrow) * BSTR) * 2 + colOff;
                LDSM_X4(r0, r1, r2, r3, addr);
                bhi[2 * g][0] = r0; bhi[2 * g][1] = r2;
                bhi[2 * g + 1][0] = r1; bhi[2 * g + 1][1] = r3;
            }
            uint32_t a[4][4];
#pragma unroll
            for (int mt = 0; mt < 4; mt++) {
                uint32_t addr = uAH + ((uint32_t)(m0 + mt * 16 + lrow) * BSTR) * 2 + colOff;
                LDSM_X4(a[mt][0], a[mt][1], a[mt][2], a[mt][3], addr);
            }
#pragma unroll
            for (int mt = 0; mt < 4; mt++)
#pragma unroll
                for (int nt = 0; nt < 4; nt++)
                    mma_bf16(acc[mt][nt], a[mt][0], a[mt][1], a[mt][2], a[mt][3],
                             bhi[nt][0], bhi[nt][1]);
            uint32_t blo[4][2];
#pragma unroll
            for (int g = 0; g < 2; g++) {
                uint32_t r0, r1, r2, r3;
                uint32_t addr = uWL + ((uint32_t)(n0 + g * 16 + lrow) * BSTR) * 2 + colOff;
                LDSM_X4(r0, r1, r2, r3, addr);
                blo[2 * g][0] = r0; blo[2 * g][1] = r2;
                blo[2 * g + 1][0] = r1; blo[2 * g + 1][1] = r3;
            }
#pragma unroll
            for (int mt = 0; mt < 4; mt++)
#pragma unroll
                for (int nt = 0; nt < 4; nt++)
                    mma_bf16(acc[mt][nt], a[mt][0], a[mt][1], a[mt][2], a[mt][3],
                             blo[nt][0], blo[nt][1]);
#pragma unroll
            for (int mt = 0; mt < 4; mt++) {
                uint32_t addr = uAL + ((uint32_t)(m0 + mt * 16 + lrow) * BSTR) * 2 + colOff;
                LDSM_X4(a[mt][0], a[mt][1], a[mt][2], a[mt][3], addr);
            }
#pragma unroll
            for (int mt = 0; mt < 4; mt++)
#pragma unroll
                for (int nt = 0; nt < 4; nt++)
                    mma_bf16(acc[mt][nt], a[mt][0], a[mt][1], a[mt][2], a[mt][3],
                             bhi[nt][0], bhi[nt][1]);
        }

        float* C = Cj[j];
        const float* bias = bj[j];
#pragma unroll
        for (int nt = 0; nt < 4; nt++) {
            const int col = n0 + nt * 8 + cc2;
            const float bb0 = bias[col], bb1 = bias[col + 1];
            float s0 = 0.0f, s1 = 0.0f, q0 = 0.0f, q1 = 0.0f;
#pragma unroll
            for (int mt = 0; mt < 4; mt++) {
                const long r0 = rowBase + m0 + mt * 16 + cr;
                float x0 = acc[mt][nt][0] + bb0;
                float x1 = acc[mt][nt][1] + bb1;
                float x2 = acc[mt][nt][2] + bb0;
                float x3 = acc[mt][nt][3] + bb1;
                *(float2*)(C + r0 * 128 + col)       = make_float2(x0, x1);
                *(float2*)(C + (r0 + 8) * 128 + col) = make_float2(x2, x3);
                s0 += x0 + x2; s1 += x1 + x3;
                q0 += x0 * x0 + x2 * x2; q1 += x1 * x1 + x3 * x3;
            }
#pragma unroll
            for (int off = 4; off <= 16; off <<= 1) {
                s0 += __shfl_xor_sync(0xffffffffu, s0, off);
                s1 += __shfl_xor_sync(0xffffffffu, s1, off);
                q0 += __shfl_xor_sync(0xffffffffu, q0, off);
                q1 += __shfl_xor_sync(0xffffffffu, q1, off);
            }
            if (cr == 0) {
                atomicAdd(&sumj[j][col], s0);  atomicAdd(&sumj[j][col + 1], s1);
                atomicAdd(&sqj[j][col], q0);   atomicAdd(&sqj[j][col + 1], q1);
            }
        }
    }
}

// ================= Attention v3b: P hi/lo (full precision), affines from raw stats =================
#define QSTR 40
#define PSTR 136
#define AQH  0
#define AQL  5120
#define AKH  10240
#define AKL  15360
#define AVTH 20480
#define AVTL 24832
#define APH  29184
#define APL  46592
#define AEND 64000
#define ATTN_SMEM (AEND * 2 + 7 * 128 * 4)   // 131584 B

__global__ void __launch_bounds__(256)
attn_kernel(const float* __restrict__ q,
            const float* __restrict__ k,
            const float* __restrict__ v,
            const float* __restrict__ mask,
            const float* __restrict__ sumQ, const float* __restrict__ sqQ,
            const float* __restrict__ gQ, const float* __restrict__ bQ,
            const float* __restrict__ sumK, const float* __restrict__ sqK,
            const float* __restrict__ gK, const float* __restrict__ bK,
            const float* __restrict__ sumV, const float* __restrict__ sqV,
            const float* __restrict__ gV, const float* __restrict__ bV,
            float* __restrict__ out) {
    extern __shared__ __nv_bfloat16 smem[];
    float* aux = (float*)(smem + AEND);
    float* rowsum = aux;            // [128]
    float* scQ = aux + 128;  float* shQ = aux + 256;
    float* scK = aux + 384;  float* shK = aux + 512;
    float* scV = aux + 640;  float* shV = aux + 768;

    const int h = blockIdx.x;
    const int n = blockIdx.y;
    const int tid = threadIdx.x;
    const long base = (long)n * SS * DD + h * CC;
    const long mbase = (long)n * SS * SS;
    const int dBase = h * CC;

    if (tid < 128) {
        rowsum[tid] = 0.0f;
        bn_affine(sumQ, sqQ, gQ, bQ, tid, scQ[tid], shQ[tid]);
        bn_affine(sumV, sqV, gV, bV, tid, scV[tid], shV[tid]);
    } else {
        int c = tid - 128;
        bn_affine(sumK, sqK, gK, bK, c, scK[c], shK[c]);
    }
    __syncthreads();

    for (int idx = tid; idx < 1024; idx += 256) {
        int r = idx >> 3, c0 = (idx & 7) * 4;
        int d = dBase + c0;
        float4 s4 = *(const float4*)(scQ + d);
        float4 t4 = *(const float4*)(shQ + d);
        float4 x = *(const float4*)(q + base + (long)r * 128 + c0);
        x.x = x.x * s4.x + t4.x; x.y = x.y * s4.y + t4.y;
        x.z = x.z * s4.z + t4.z; x.w = x.w * s4.w + t4.w;
        float h0 = __bfloat162float(__float2bfloat16_rn(x.x));
        float h1 = __bfloat162float(__float2bfloat16_rn(x.y));
        float h2 = __bfloat162float(__float2bfloat16_rn(x.z));
        float h3 = __bfloat162float(__float2bfloat16_rn(x.w));
        *(uint2*)(smem + AQH + r * QSTR + c0) = make_uint2(packbf(x.x, x.y), packbf(x.z, x.w));
        *(uint2*)(smem + AQL + r * QSTR + c0) =
            make_uint2(packbf(x.x - h0, x.y - h1), packbf(x.z - h2, x.w - h3));

        s4 = *(const float4*)(scK + d);
        t4 = *(const float4*)(shK + d);
        x = *(const float4*)(k + base + (long)r * 128 + c0);
        x.x = x.x * s4.x + t4.x; x.y = x.y * s4.y + t4.y;
        x.z = x.z * s4.z + t4.z; x.w = x.w * s4.w + t4.w;
        h0 = __bfloat162float(__float2bfloat16_rn(x.x));
        h1 = __bfloat162float(__float2bfloat16_rn(x.y));
        h2 = __bfloat162float(__float2bfloat16_rn(x.z));
        h3 = __bfloat162float(__float2bfloat16_rn(x.w));
        *(uint2*)(smem + AKH + r * QSTR + c0) = make_uint2(packbf(x.x, x.y), packbf(x.z, x.w));
        *(uint2*)(smem + AKL + r * QSTR + c0) =
            make_uint2(packbf(x.x - h0, x.y - h1), packbf(x.z - h2, x.w - h3));
    }
    for (int idx = tid; idx < 1024; idx += 256) {
        int r = idx >> 3, c0 = (idx & 7) * 4;
        int d = dBase + c0;
        float4 s4 = *(const float4*)(scV + d);
        float4 t4 = *(const float4*)(shV + d);
        float4 x = *(const float4*)(v + base + (long)r * 128 + c0);
        float val[4];
        val[0] = x.x * s4.x + t4.x; val[1] = x.y * s4.y + t4.y;
        val[2] = x.z * s4.z + t4.z; val[3] = x.w * s4.w + t4.w;
#pragma unroll
        for (int j = 0; j < 4; j++) {
            __nv_bfloat16 hi = __float2bfloat16_rn(val[j]);
            smem[AVTH + (c0 + j) * PSTR + r] = hi;
            smem[AVTL + (c0 + j) * PSTR + r] =
                __float2bfloat16_rn(val[j] - __bfloat162float(hi));
        }
    }
    __syncthreads();

    const int warp = tid >> 5, lane = tid & 31;
    const int lrow = lane & 15, lhalf = (lane >> 4) * 8;
    const int cr = lane >> 2, cc2 = (lane & 3) * 2;

    const uint32_t uQH = smem_u32(smem + AQH), uQL = smem_u32(smem + AQL);
    const uint32_t uKH = smem_u32(smem + AKH), uKL = smem_u32(smem + AKL);

    // ======== S phase ========
    {
        const int wm = warp >> 2, wn = warp & 3;
        const int m0 = wm * 64, n0 = wn * 32;

        float acc[4][4][4];
#pragma unroll
        for (int mt = 0; mt < 4; mt++)
#pragma unroll
            for (int nt = 0; nt < 4; nt++)
#pragma unroll
                for (int i = 0; i < 4; i++) acc[mt][nt][i] = 0.0f;

#pragma unroll
        for (int ks = 0; ks < 2; ks++) {
            const uint32_t colOff = (uint32_t)(ks * 16 + lhalf) * 2;
            uint32_t bhi[4][2];
#pragma unroll
            for (int g = 0; g < 2; g++) {
                uint32_t r0, r1, r2, r3;
                uint32_t addr = uKH + ((uint32_t)(n0 + g * 16 + lrow) * QSTR) * 2 + colOff;
                LDSM_X4(r0, r1, r2, r3, addr);
                bhi[2 * g][0] = r0; bhi[2 * g][1] = r2;
                bhi[2 * g + 1][0] = r1; bhi[2 * g + 1][1] = r3;
            }
            uint32_t a[4][4];
#pragma unroll
            for (int mt = 0; mt < 4; mt++) {
                uint32_t addr = uQH + ((uint32_t)(m0 + mt * 16 + lrow) * QSTR) * 2 + colOff;
                LDSM_X4(a[mt][0], a[mt][1], a[mt][2], a[mt][3], addr);
            }
#pragma unroll
            for (int mt = 0; mt < 4; mt++)
#pragma unroll
                for (int nt = 0; nt < 4; nt++)
                    mma_bf16(acc[mt][nt], a[mt][0], a[mt][1], a[mt][2], a[mt][3],
                             bhi[nt][0], bhi[nt][1]);
            uint32_t blo[4][2];
#pragma unroll
            for (int g = 0; g < 2; g++) {
                uint32_t r0, r1, r2, r3;
                uint32_t addr = uKL + ((uint32_t)(n0 + g * 16 + lrow) * QSTR) * 2 + colOff;
                LDSM_X4(r0, r1, r2, r3, addr);
                blo[2 * g][0] = r0; blo[2 * g][1] = r2;
                blo[2 * g + 1][0] = r1; blo[2 * g + 1][1] = r3;
            }
#pragma unroll
            for (int mt = 0; mt < 4; mt++)
#pragma unroll
                for (int nt = 0; nt < 4; nt++)
                    mma_bf16(acc[mt][nt], a[mt][0], a[mt][1], a[mt][2], a[mt][3],
                             blo[nt][0], blo[nt][1]);
#pragma unroll
            for (int mt = 0; mt < 4; mt++) {
                uint32_t addr = uQL + ((uint32_t)(m0 + mt * 16 + lrow) * QSTR) * 2 + colOff;
                LDSM_X4(a[mt][0], a[mt][1], a[mt][2], a[mt][3], addr);
            }
#pragma unroll
            for (int mt = 0; mt < 4; mt++)
#pragma unroll
                for (int nt = 0; nt < 4; nt++)
                    mma_bf16(acc[mt][nt], a[mt][0], a[mt][1], a[mt][2], a[mt][3],
                             bhi[nt][0], bhi[nt][1]);
        }

        // epilogue: mask (gmem), exp, row sums, store P hi/lo
#pragma unroll
        for (int mt = 0; mt < 4; mt++) {
            const int row0 = m0 + mt * 16 + cr;
            float s0 = 0.0f, s1 = 0.0f;
#pragma unroll
            for (int nt = 0; nt < 4; nt++) {
                const int col = n0 + nt * 8 + cc2;
                float2 mv0 = *(const float2*)(mask + mbase + (long)row0 * 128 + col);
                float2 mv1 = *(const float2*)(mask + mbase + (long)(row0 + 8) * 128 + col);
                float p00 = __expf(acc[mt][nt][0] * mv0.x);
                float p01 = __expf(acc[mt][nt][1] * mv0.y);
                float p10 = __expf(acc[mt][nt][2] * mv1.x);
                float p11 = __expf(acc[mt][nt][3] * mv1.y);
                s0 += p00 + p01;
                s1 += p10 + p11;
                __nv_bfloat16 h00 = __float2bfloat16_rn(p00);
                __nv_bfloat16 h01 = __float2bfloat16_rn(p01);
                __nv_bfloat16 h10 = __float2bfloat16_rn(p10);
                __nv_bfloat16 h11 = __float2bfloat16_rn(p11);
                *(uint32_t*)(smem + APH + row0 * PSTR + col) =
                    packbf(__bfloat162float(h00), __bfloat162float(h01));
                *(uint32_t*)(smem + APH + (row0 + 8) * PSTR + col) =
                    packbf(__bfloat162float(h10), __bfloat162float(h11));
                *(uint32_t*)(smem + APL + row0 * PSTR + col) =
                    packbf(p00 - __bfloat162float(h00), p01 - __bfloat162float(h01));
                *(uint32_t*)(smem + APL + (row0 + 8) * PSTR + col) =
                    packbf(p10 - __bfloat162float(h10), p11 - __bfloat162float(h11));
            }
            s0 += __shfl_xor_sync(0xffffffffu, s0, 1);
            s0 += __shfl_xor_sync(0xffffffffu, s0, 2);
            s1 += __shfl_xor_sync(0xffffffffu, s1, 1);
            s1 += __shfl_xor_sync(0xffffffffu, s1, 2);
            if ((lane & 3) == 0) {
                atomicAdd(&rowsum[row0], s0);
                atomicAdd(&rowsum[row0 + 8], s1);
            }
        }
    }
    __syncthreads();

    // ======== PV phase: 3 passes (Phi*Vhi + Phi*Vlo + Plo*Vhi) ========
    {
        const int m0 = warp * 16;
        const uint32_t uPH = smem_u32(smem + APH), uPL = smem_u32(smem + APL);
        const uint32_t uVH = smem_u32(smem + AVTH), uVL = smem_u32(smem + AVTL);

        float acc[4][4];
#pragma unroll
        for (int nt = 0; nt < 4; nt++)
#pragma unroll
            for (int i = 0; i < 4; i++) acc[nt][i] = 0.0f;

#pragma unroll
        for (int ks = 0; ks < 8; ks++) {
            const uint32_t colOff = (uint32_t)(ks * 16 + lhalf) * 2;
            uint32_t bhi[4][2];
#pragma unroll
            for (int g = 0; g < 2; g++) {
                uint32_t r0, r1, r2, r3;
                uint32_t addr = uVH + ((uint32_t)(g * 16 + lrow) * PSTR) * 2 + colOff;
                LDSM_X4(r0, r1, r2, r3, addr);
                bhi[2 * g][0] = r0; bhi[2 * g][1] = r2;
                bhi[2 * g + 1][0] = r1; bhi[2 * g + 1][1] = r3;
            }
            uint32_t a[4];
            {
                uint32_t addr = uPH + ((uint32_t)(m0 + lrow) * PSTR) * 2 + colOff;
                LDSM_X4(a[0], a[1], a[2], a[3], addr);
            }
#pragma unroll
            for (int nt = 0; nt < 4; nt++)
                mma_bf16(acc[nt], a[0], a[1], a[2], a[3], bhi[nt][0], bhi[nt][1]);
            uint32_t blo[4][2];
#pragma unroll
            for (int g = 0; g < 2; g++) {
                uint32_t r0, r1, r2, r3;
                uint32_t addr = uVL + ((uint32_t)(g * 16 + lrow) * PSTR) * 2 + colOff;
                LDSM_X4(r0, r1, r2, r3, addr);
                blo[2 * g][0] = r0; blo[2 * g][1] = r2;
                blo[2 * g + 1][0] = r1; blo[2 * g + 1][1] = r3;
            }
#pragma unroll
            for (int nt = 0; nt < 4; nt++)
                mma_bf16(acc[nt], a[0], a[1], a[2], a[3], blo[nt][0], blo[nt][1]);
            {
                uint32_t addr = uPL + ((uint32_t)(m0 + lrow) * PSTR) * 2 + colOff;
                LDSM_X4(a[0], a[1], a[2], a[3], addr);
            }
#pragma unroll
            for (int nt = 0; nt < 4; nt++)
                mma_bf16(acc[nt], a[0], a[1], a[2], a[3], bhi[nt][0], bhi[nt][1]);
        }

        const int row0 = m0 + cr;
        const float inv0 = 1.0f / rowsum[row0];
        const float inv1 = 1.0f / rowsum[row0 + 8];
#pragma unroll
        for (int nt = 0; nt < 4; nt++) {
            const int col = nt * 8 + cc2;
            *(float2*)(out + base + (long)row0 * 128 + col) =
                make_float2(acc[nt][0] * inv0, acc[nt][1] * inv0);
            *(float2*)(out + base + (long)(row0 + 8) * 128 + col) =
                make_float2(acc[nt][2] * inv1, acc[nt][3] * inv1);
        }
    }
}

// ---------------- out = LayerNorm(A + affine(B)) per row (affine from raw stats) ----------------
__global__ void add_ln_kernel(const float* __restrict__ A,
                              const float* __restrict__ B,
                              const float* __restrict__ sumB, const float* __restrict__ sqB,
                              const float* __restrict__ gB, const float* __restrict__ bB,
                              const float* __restrict__ gam,
                              const float* __restrict__ bet,
                              float* __restrict__ Out) {
    __shared__ float sc[128], sh[128];
    const int tid = threadIdx.x;
    if (tid < 128) {
        if (gB) bn_affine(sumB, sqB, gB, bB, tid, sc[tid], sh[tid]);
        else { sc[tid] = 1.0f; sh[tid] = 0.0f; }
    }
    __syncthreads();

    const int w = tid >> 5, lane = tid & 31;
    const long row = (long)blockIdx.x * 8 + w;
    const float* a = A + row * 128;
    const float* b = B + row * 128;

    float x[4];
    float s = 0.0f, s2 = 0.0f;
#pragma unroll
    for (int i = 0; i < 4; i++) {
        int c = lane + 32 * i;
        x[i] = a[c] + b[c] * sc[c] + sh[c];
        s += x[i];
        s2 += x[i] * x[i];
    }
#pragma unroll
    for (int o = 16; o > 0; o >>= 1) {
        s  += __shfl_xor_sync(0xffffffffu, s, o);
        s2 += __shfl_xor_sync(0xffffffffu, s2, o);
    }
    const float m = s * (1.0f / 128.0f);
    const float var = s2 * (1.0f / 128.0f) - m * m;
    const float r = rsqrtf(var + EPS);
#pragma unroll
    for (int i = 0; i < 4; i++) {
        int c = lane + 32 * i;
        Out[row * 128 + c] = (x[i] - m) * r * gam[c] + bet[c];
    }
}

// ---------------- h = LN(O + affine_ff(F)) + affine_sk(S), warp per row ----------------
__global__ void ln_add_affine_kernel(const float* __restrict__ O,
                                     const float* __restrict__ F,
                                     const float* __restrict__ sumF, const float* __restrict__ sqF,
                                     const float* __restrict__ gF, const float* __restrict__ bF,
                                     const float* __restrict__ Sk,
                                     const float* __restrict__ sumS, const float* __restrict__ sqS,
                                     const float* __restrict__ gS, const float* __restrict__ bS,
                                     const float* __restrict__ gam,
                                     const float* __restrict__ bet,
                                     float* __restrict__ Out) {
    __shared__ float sc4[128], sh4[128], sc5[128], sh5[128];
    const int tid = threadIdx.x;
    if (tid < 128) {
        bn_affine(sumF, sqF, gF, bF, tid, sc4[tid], sh4[tid]);
    } else {
        int c = tid - 128;
        bn_affine(sumS, sqS, gS, bS, c, sc5[c], sh5[c]);
    }
    __syncthreads();

    const int w = tid >> 5, lane = tid & 31;
    const long row = (long)blockIdx.x * 8 + w;
    const float* o = O + row * 128;
    const float* f = F + row * 128;
    const float* sk = Sk + row * 128;

    float x[4];
    float s = 0.0f, s2 = 0.0f;
#pragma unroll
    for (int i = 0; i < 4; i++) {
        int c = lane + 32 * i;
        x[i] = o[c] + f[c] * sc4[c] + sh4[c];
        s += x[i];
        s2 += x[i] * x[i];
    }
#pragma unroll
    for (int off = 16; off > 0; off >>= 1) {
        s  += __shfl_xor_sync(0xffffffffu, s, off);
        s2 += __shfl_xor_sync(0xffffffffu, s2, off);
    }
    const float m = s * (1.0f / 128.0f);
    const float var = s2 * (1.0f / 128.0f) - m * m;
    const float r = rsqrtf(var + EPS);
#pragma unroll
    for (int i = 0; i < 4; i++) {
        int c = lane + 32 * i;
        Out[row * 128 + c] = (x[i] - m) * r * gam[c] + bet[c] + sk[c] * sc5[c] + sh5[c];
    }
}

// ---------------- gather h[:, 0] -> out[N, D] ----------------
__global__ void gather_kernel(const float* __restrict__ H, float* __restrict__ Out) {
    int i = blockIdx.x * blockDim.x + threadIdx.x;
    int n = i >> 7, d = i & 127;
    Out[i] = H[(long)n * SS * DD + d];
}

// ---------------- host orchestration ----------------
extern "C" void kernel_launch(void* const* d_in, const int* in_sizes, int n_in,
                              void* d_out, int out_size) {
    const float* x        = (const float*)d_in[0];
    const float* mask     = (const float*)d_in[1];
    const float* lin_in_W = (const float*)d_in[2];
    const float* lin_in_b = (const float*)d_in[3];
    const float* in_bn_g  = (const float*)d_in[4];
    const float* in_bn_b  = (const float*)d_in[5];
    const float* q_W      = (const float*)d_in[6];
    const float* q_b      = (const float*)d_in[7];
    const float* q_bn_g   = (const float*)d_in[8];
    const float* q_bn_b   = (const float*)d_in[9];
    const float* k_W      = (const float*)d_in[10];
    const float* k_b      = (const float*)d_in[11];
    const float* k_bn_g   = (const float*)d_in[12];
    const float* k_bn_b   = (const float*)d_in[13];
    const float* v_W      = (const float*)d_in[14];
    const float* v_b      = (const float*)d_in[15];
    const float* v_bn_g   = (const float*)d_in[16];
    const float* v_bn_b   = (const float*)d_in[17];
    const float* ln_g     = (const float*)d_in[18];
    const float* ln_b     = (const float*)d_in[19];
    const float* ff_W     = (const float*)d_in[20];
    const float* ff_b     = (const float*)d_in[21];
    const float* ff_bn_g  = (const float*)d_in[22];
    const float* ff_bn_b  = (const float*)d_in[23];
    const float* skip_W   = (const float*)d_in[24];
    const float* skip_b   = (const float*)d_in[25];
    const float* skip_bn_g= (const float*)d_in[26];
    const float* skip_bn_b= (const float*)d_in[27];
    float* out = (float*)d_out;

    cudaFuncSetAttribute(gemm_tc_kernel, cudaFuncAttributeMaxDynamicSharedMemorySize, GEMM_SMEM);
    cudaFuncSetAttribute(attn_kernel, cudaFuncAttributeMaxDynamicSharedMemorySize, ATTN_SMEM);

    float *bh, *bt, *bq, *bk, *bv, *bs, *ba, *bo, *bf, *bsum, *bsq;
    cudaGetSymbolAddress((void**)&bh, g_h);
    cudaGetSymbolAddress((void**)&bt, g_t);
    cudaGetSymbolAddress((void**)&bq, g_q);
    cudaGetSymbolAddress((void**)&bk, g_k);
    cudaGetSymbolAddress((void**)&bv, g_v);
    cudaGetSymbolAddress((void**)&bs, g_s);
    cudaGetSymbolAddress((void**)&ba, g_a);
    cudaGetSymbolAddress((void**)&bo, g_o);
    cudaGetSymbolAddress((void**)&bf, g_f);
    cudaGetSymbolAddress((void**)&bsum, g_stat_sum);
    cudaGetSymbolAddress((void**)&bsq, g_stat_sq);

    auto SUM = [&](int i) { return bsum + i * DD; };
    auto SQ  = [&](int i) { return bsq + i * DD; };

    const int GEMM_GRID = M_ROWS / 256;   // 512

    // launch 1: zero all stat slots
    zero_stats_kernel<<<(NSLOT * DD + 255) / 256, 256>>>();

    // launch 2: t0 = x @ Win^T + b ; stats -> slot 0
    gemm_tc_kernel<<<GEMM_GRID, 512, GEMM_SMEM>>>(
        x, 0, 0, 0, 0,
        lin_in_W, lin_in_W, lin_in_W, lin_in_W,
        lin_in_b, lin_in_b, lin_in_b, lin_in_b,
        bt, bt, bt, bt,
        SUM(0), SUM(0), SUM(0), SUM(0), SQ(0), SQ(0), SQ(0), SQ(0), 1);

    for (int l = 0; l < LL; l++) {
        const long wOff = (long)l * DD * DD;
        const long vOff = (long)l * DD;
        const float* hp = (l == 0) ? bt : bh;
        const int sq_ = 1 + l * 5, sk_ = 2 + l * 5, sv_ = 3 + l * 5,
                  ss_ = 4 + l * 5, sf_ = 5 + l * 5;
        const float* hSum = (l == 0) ? SUM(0) : 0;
        const float* hSq  = (l == 0) ? SQ(0) : 0;
        const float* hG   = (l == 0) ? in_bn_g : 0;
        const float* hB   = (l == 0) ? in_bn_b : 0;

        // fused Q/K/V/skip GEMM (launch 3 for l=0)
        gemm_tc_kernel<<<GEMM_GRID, 512, GEMM_SMEM>>>(
            hp, hSum, hSq, hG, hB,
            q_W + wOff, k_W + wOff, v_W + wOff, skip_W + wOff,
            q_b + vOff, k_b + vOff, v_b + vOff, skip_b + vOff,
            bq, bk, bv, bs,
            SUM(sq_), SUM(sk_), SUM(sv_), SUM(ss_),
            SQ(sq_), SQ(sk_), SQ(sv_), SQ(ss_), 4);

        // attention (launch 4 for l=0 — ncu target)
        dim3 agrid(HH, NB);
        attn_kernel<<<agrid, 256, ATTN_SMEM>>>(
            bq, bk, bv, mask,
            SUM(sq_), SQ(sq_), q_bn_g + vOff, q_bn_b + vOff,
            SUM(sk_), SQ(sk_), k_bn_g + vOff, k_bn_b + vOff,
            SUM(sv_), SQ(sv_), v_bn_g + vOff, v_bn_b + vOff,
            ba);

        // out = LN(agg + h)
        add_ln_kernel<<<M_ROWS / 8, 256>>>(ba, hp, hSum, hSq, hG, hB,
                                           ln_g + vOff, ln_b + vOff, bo);

        // ff GEMM -> slot sf_
        gemm_tc_kernel<<<GEMM_GRID, 512, GEMM_SMEM>>>(
            bo, 0, 0, 0, 0,
            ff_W + wOff, ff_W + wOff, ff_W + wOff, ff_W + wOff,
            ff_b + vOff, ff_b + vOff, ff_b + vOff, ff_b + vOff,
            bf, bf, bf, bf,
            SUM(sf_), SUM(sf_), SUM(sf_), SUM(sf_),
            SQ(sf_), SQ(sf_), SQ(sf_), SQ(sf_), 1);

        // h = LN(out + affine_ff(ff)) + affine_skip(skip)
        ln_add_affine_kernel<<<M_ROWS / 8, 256>>>(
            bo, bf, SUM(sf_), SQ(sf_), ff_bn_g + vOff, ff_bn_b + vOff,
            bs, SUM(ss_), SQ(ss_), skip_bn_g + vOff, skip_bn_b + vOff,
            ln_g + vOff, ln_b + vOff, bh);
    }

    gather_kernel<<<(NB * DD) / 256, 256>>>(bh, out);
}

// round 12
// speedup vs baseline: 2.3831x; 1.1436x over previous
#include <cuda_runtime.h>
#include <cuda_bf16.h>
#include <math.h>
#include <stdint.h>

// ---------------- problem constants ----------------
#define NB      1024
#define SS      128
#define DD      128
#define HH      4
#define CC      32
#define LL      2
#define M_ROWS  (NB * SS)
#define MSZ     (M_ROWS * DD)
#define EPS     1e-5f
#define INV_M   (1.0f / (float)M_ROWS)
#define NSLOT   11

// ---------------- scratch ----------------
__device__ float g_h[MSZ];
__device__ float g_t[MSZ];
__device__ float g_q[MSZ];
__device__ float g_k[MSZ];
__device__ float g_v[MSZ];
__device__ float g_s[MSZ];
__device__ float g_a[MSZ];
__device__ float g_o[MSZ];
__device__ float g_f[MSZ];
__device__ float g_stat_sum[NSLOT][DD];
__device__ float g_stat_sq[NSLOT][DD];

// ================= helpers =================
__device__ __forceinline__ uint32_t smem_u32(const void* p) {
    uint32_t a;
    asm("{ .reg .u64 t; cvta.to.shared.u64 t, %1; cvt.u32.u64 %0, t; }" : "=r"(a) : "l"(p));
    return a;
}
__device__ __forceinline__ uint32_t packbf(float a, float b) {
    __nv_bfloat162 t = __floats2bfloat162_rn(a, b);
    return *(uint32_t*)&t;
}
__device__ __forceinline__ void bn_affine(const float* sum, const float* sq,
                                          const float* g, const float* b, int c,
                                          float& sc, float& sh) {
    float m = sum[c] * INV_M;
    float var = sq[c] * INV_M - m * m;
    float s = g[c] * rsqrtf(var + EPS);
    sc = s;
    sh = b[c] - m * s;
}

#define LDSM_X4(r0, r1, r2, r3, addr) \
    asm volatile("ldmatrix.sync.aligned.m8n8.x4.shared.b16 {%0,%1,%2,%3}, [%4];" \
                 : "=r"(r0), "=r"(r1), "=r"(r2), "=r"(r3) : "r"(addr))

__device__ __forceinline__ void mma_bf16(float c[4],
                                         uint32_t a0, uint32_t a1, uint32_t a2, uint32_t a3,
                                         uint32_t b0, uint32_t b1) {
    asm volatile(
        "mma.sync.aligned.m16n8k16.row.col.f32.bf16.bf16.f32 "
        "{%0,%1,%2,%3}, {%4,%5,%6,%7}, {%8,%9}, {%0,%1,%2,%3};"
        : "+f"(c[0]), "+f"(c[1]), "+f"(c[2]), "+f"(c[3])
        : "r"(a0), "r"(a1), "r"(a2), "r"(a3), "r"(b0), "r"(b1));
}

// ---------------- zero all stat slots (start of graph) ----------------
__global__ void zero_stats_kernel() {
    int i = blockIdx.x * blockDim.x + threadIdx.x;
    if (i < NSLOT * DD) {
        ((float*)g_stat_sum)[i] = 0.0f;
        ((float*)g_stat_sq)[i] = 0.0f;
    }
}

// ================= GEMM: up to 4 weight sets share one converted A tile =================
#define BSTR 136
#define A_TILE_E (256 * BSTR)
#define W_TILE_E (128 * BSTR)
#define GEMM_SMEM ((2 * A_TILE_E + 2 * W_TILE_E) * 2 + 1024)

__global__ void __launch_bounds__(512)
gemm_tc_kernel(const float* __restrict__ A,
               const float* __restrict__ sumA, const float* __restrict__ sqA,
               const float* __restrict__ gA, const float* __restrict__ bA,
               const float* W0, const float* W1, const float* W2, const float* W3,
               const float* b0, const float* b1, const float* b2, const float* b3,
               float* C0, float* C1, float* C2, float* C3,
               float* sum0, float* sum1, float* sum2, float* sum3,
               float* sq0, float* sq1, float* sq2, float* sq3,
               int nW) {
    extern __shared__ __nv_bfloat16 smem[];
    __nv_bfloat16* AH = smem;
    __nv_bfloat16* AL = smem + A_TILE_E;
    __nv_bfloat16* WH = smem + 2 * A_TILE_E;
    __nv_bfloat16* WL = smem + 2 * A_TILE_E + W_TILE_E;
    float* sAff = (float*)(smem + 2 * A_TILE_E + 2 * W_TILE_E);   // [256]

    const float* Wj[4] = {W0, W1, W2, W3};
    const float* bj[4] = {b0, b1, b2, b3};
    float* Cj[4] = {C0, C1, C2, C3};
    float* sumj[4] = {sum0, sum1, sum2, sum3};
    float* sqj[4] = {sq0, sq1, sq2, sq3};

    const int tid = threadIdx.x;
    const long rowBase = (long)blockIdx.x * 256;

    if (gA && tid < 128) {
        float sc, sh;
        bn_affine(sumA, sqA, gA, bA, tid, sc, sh);
        sAff[tid] = sc;
        sAff[128 + tid] = sh;
    }
    __syncthreads();

    for (int idx = tid; idx < 8192; idx += 512) {
        int r = idx >> 5, k0 = (idx & 31) * 4;
        float4 v = *(const float4*)(A + (rowBase + r) * 128 + k0);
        if (gA) {
            float4 s = *(const float4*)(sAff + k0);
            float4 t = *(const float4*)(sAff + 128 + k0);
            v.x = v.x * s.x + t.x; v.y = v.y * s.y + t.y;
            v.z = v.z * s.z + t.z; v.w = v.w * s.w + t.w;
        }
        float h0 = __bfloat162float(__float2bfloat16_rn(v.x));
        float h1 = __bfloat162float(__float2bfloat16_rn(v.y));
        float h2 = __bfloat162float(__float2bfloat16_rn(v.z));
        float h3 = __bfloat162float(__float2bfloat16_rn(v.w));
        *(uint2*)(AH + r * BSTR + k0) = make_uint2(packbf(v.x, v.y), packbf(v.z, v.w));
        *(uint2*)(AL + r * BSTR + k0) =
            make_uint2(packbf(v.x - h0, v.y - h1), packbf(v.z - h2, v.w - h3));
    }

    const int warp = tid >> 5, lane = tid & 31;
    const int wm = warp >> 2, wn = warp & 3;
    const int m0 = wm * 64, n0 = wn * 32;
    const int lrow = lane & 15, lhalf = (lane >> 4) * 8;
    const int cr = lane >> 2, cc2 = (lane & 3) * 2;

    const uint32_t uAH = smem_u32(AH), uAL = smem_u32(AL);
    const uint32_t uWH = smem_u32(WH), uWL = smem_u32(WL);

    for (int j = 0; j < nW; j++) {
        if (j > 0) __syncthreads();
        const float* W = Wj[j];
        for (int idx = tid; idx < 4096; idx += 512) {
            int r = idx >> 5, k0 = (idx & 31) * 4;
            float4 v = *(const float4*)(W + r * 128 + k0);
            float h0 = __bfloat162float(__float2bfloat16_rn(v.x));
            float h1 = __bfloat162float(__float2bfloat16_rn(v.y));
            float h2 = __bfloat162float(__float2bfloat16_rn(v.z));
            float h3 = __bfloat162float(__float2bfloat16_rn(v.w));
            *(uint2*)(WH + r * BSTR + k0) = make_uint2(packbf(v.x, v.y), packbf(v.z, v.w));
            *(uint2*)(WL + r * BSTR + k0) =
                make_uint2(packbf(v.x - h0, v.y - h1), packbf(v.z - h2, v.w - h3));
        }
        __syncthreads();

        float acc[4][4][4];
#pragma unroll
        for (int mt = 0; mt < 4; mt++)
#pragma unroll
            for (int nt = 0; nt < 4; nt++)
#pragma unroll
                for (int i = 0; i < 4; i++) acc[mt][nt][i] = 0.0f;

#pragma unroll
        for (int ks = 0; ks < 8; ks++) {
            const uint32_t colOff = (uint32_t)(ks * 16 + lhalf) * 2;
            uint32_t bhi[4][2];
#pragma unroll
            for (int g = 0; g < 2; g++) {
                uint32_t r0, r1, r2, r3;
                uint32_t addr = uWH + ((uint32_t)(n0 + g * 16 + lrow) * BSTR) * 2 + colOff;
                LDSM_X4(r0, r1, r2, r3, addr);
                bhi[2 * g][0] = r0; bhi[2 * g][1] = r2;
                bhi[2 * g + 1][0] = r1; bhi[2 * g + 1][1] = r3;
            }
            uint32_t a[4][4];
#pragma unroll
            for (int mt = 0; mt < 4; mt++) {
                uint32_t addr = uAH + ((uint32_t)(m0 + mt * 16 + lrow) * BSTR) * 2 + colOff;
                LDSM_X4(a[mt][0], a[mt][1], a[mt][2], a[mt][3], addr);
            }
#pragma unroll
            for (int mt = 0; mt < 4; mt++)
#pragma unroll
                for (int nt = 0; nt < 4; nt++)
                    mma_bf16(acc[mt][nt], a[mt][0], a[mt][1], a[mt][2], a[mt][3],
                             bhi[nt][0], bhi[nt][1]);
            uint32_t blo[4][2];
#pragma unroll
            for (int g = 0; g < 2; g++) {
                uint32_t r0, r1, r2, r3;
                uint32_t addr = uWL + ((uint32_t)(n0 + g * 16 + lrow) * BSTR) * 2 + colOff;
                LDSM_X4(r0, r1, r2, r3, addr);
                blo[2 * g][0] = r0; blo[2 * g][1] = r2;
                blo[2 * g + 1][0] = r1; blo[2 * g + 1][1] = r3;
            }
#pragma unroll
            for (int mt = 0; mt < 4; mt++)
#pragma unroll
                for (int nt = 0; nt < 4; nt++)
                    mma_bf16(acc[mt][nt], a[mt][0], a[mt][1], a[mt][2], a[mt][3],
                             blo[nt][0], blo[nt][1]);
#pragma unroll
            for (int mt = 0; mt < 4; mt++) {
                uint32_t addr = uAL + ((uint32_t)(m0 + mt * 16 + lrow) * BSTR) * 2 + colOff;
                LDSM_X4(a[mt][0], a[mt][1], a[mt][2], a[mt][3], addr);
            }
#pragma unroll
            for (int mt = 0; mt < 4; mt++)
#pragma unroll
                for (int nt = 0; nt < 4; nt++)
                    mma_bf16(acc[mt][nt], a[mt][0], a[mt][1], a[mt][2], a[mt][3],
                             bhi[nt][0], bhi[nt][1]);
        }

        float* C = Cj[j];
        const float* bias = bj[j];
#pragma unroll
        for (int nt = 0; nt < 4; nt++) {
            const int col = n0 + nt * 8 + cc2;
            const float bb0 = bias[col], bb1 = bias[col + 1];
            float s0 = 0.0f, s1 = 0.0f, q0 = 0.0f, q1 = 0.0f;
#pragma unroll
            for (int mt = 0; mt < 4; mt++) {
                const long r0 = rowBase + m0 + mt * 16 + cr;
                float x0 = acc[mt][nt][0] + bb0;
                float x1 = acc[mt][nt][1] + bb1;
                float x2 = acc[mt][nt][2] + bb0;
                float x3 = acc[mt][nt][3] + bb1;
                *(float2*)(C + r0 * 128 + col)       = make_float2(x0, x1);
                *(float2*)(C + (r0 + 8) * 128 + col) = make_float2(x2, x3);
                s0 += x0 + x2; s1 += x1 + x3;
                q0 += x0 * x0 + x2 * x2; q1 += x1 * x1 + x3 * x3;
            }
#pragma unroll
            for (int off = 4; off <= 16; off <<= 1) {
                s0 += __shfl_xor_sync(0xffffffffu, s0, off);
                s1 += __shfl_xor_sync(0xffffffffu, s1, off);
                q0 += __shfl_xor_sync(0xffffffffu, q0, off);
                q1 += __shfl_xor_sync(0xffffffffu, q1, off);
            }
            if (cr == 0) {
                atomicAdd(&sumj[j][col], s0);  atomicAdd(&sumj[j][col + 1], s1);
                atomicAdd(&sqj[j][col], q0);   atomicAdd(&sqj[j][col + 1], q1);
            }
        }
    }
}

// ================= Attention v5: P_lo aliases dead Q/K smem -> 2 CTAs/SM =================
// Numerically identical to v3b (P hi/lo, Q/K hi/lo, V hi/lo).
#define QSTR 40
#define PSTR 136
#define AQH  0
#define AQL  5120
#define AKH  10240
#define AKL  15360
#define AVTH 20480
#define AVTL 24832
#define APH  29184
#define APL  0            // aliases Q/K region (dead after S mainloop)
#define AEND 46592
#define ATTN_SMEM (AEND * 2 + 7 * 128 * 4)   // 96768 B -> 2 CTAs/SM

__global__ void __launch_bounds__(256, 2)
attn_kernel(const float* __restrict__ q,
            const float* __restrict__ k,
            const float* __restrict__ v,
            const float* __restrict__ mask,
            const float* __restrict__ sumQ, const float* __restrict__ sqQ,
            const float* __restrict__ gQ, const float* __restrict__ bQ,
            const float* __restrict__ sumK, const float* __restrict__ sqK,
            const float* __restrict__ gK, const float* __restrict__ bK,
            const float* __restrict__ sumV, const float* __restrict__ sqV,
            const float* __restrict__ gV, const float* __restrict__ bV,
            float* __restrict__ out) {
    extern __shared__ __nv_bfloat16 smem[];
    float* aux = (float*)(smem + AEND);
    float* rowsum = aux;            // [128]
    float* scQ = aux + 128;  float* shQ = aux + 256;
    float* scK = aux + 384;  float* shK = aux + 512;
    float* scV = aux + 640;  float* shV = aux + 768;

    const int h = blockIdx.x;
    const int n = blockIdx.y;
    const int tid = threadIdx.x;
    const long base = (long)n * SS * DD + h * CC;
    const long mbase = (long)n * SS * SS;
    const int dBase = h * CC;

    if (tid < 128) {
        rowsum[tid] = 0.0f;
        bn_affine(sumQ, sqQ, gQ, bQ, tid, scQ[tid], shQ[tid]);
        bn_affine(sumV, sqV, gV, bV, tid, scV[tid], shV[tid]);
    } else {
        int c = tid - 128;
        bn_affine(sumK, sqK, gK, bK, c, scK[c], shK[c]);
    }
    __syncthreads();

    for (int idx = tid; idx < 1024; idx += 256) {
        int r = idx >> 3, c0 = (idx & 7) * 4;
        int d = dBase + c0;
        float4 s4 = *(const float4*)(scQ + d);
        float4 t4 = *(const float4*)(shQ + d);
        float4 x = *(const float4*)(q + base + (long)r * 128 + c0);
        x.x = x.x * s4.x + t4.x; x.y = x.y * s4.y + t4.y;
        x.z = x.z * s4.z + t4.z; x.w = x.w * s4.w + t4.w;
        float h0 = __bfloat162float(__float2bfloat16_rn(x.x));
        float h1 = __bfloat162float(__float2bfloat16_rn(x.y));
        float h2 = __bfloat162float(__float2bfloat16_rn(x.z));
        float h3 = __bfloat162float(__float2bfloat16_rn(x.w));
        *(uint2*)(smem + AQH + r * QSTR + c0) = make_uint2(packbf(x.x, x.y), packbf(x.z, x.w));
        *(uint2*)(smem + AQL + r * QSTR + c0) =
            make_uint2(packbf(x.x - h0, x.y - h1), packbf(x.z - h2, x.w - h3));

        s4 = *(const float4*)(scK + d);
        t4 = *(const float4*)(shK + d);
        x = *(const float4*)(k + base + (long)r * 128 + c0);
        x.x = x.x * s4.x + t4.x; x.y = x.y * s4.y + t4.y;
        x.z = x.z * s4.z + t4.z; x.w = x.w * s4.w + t4.w;
        h0 = __bfloat162float(__float2bfloat16_rn(x.x));
        h1 = __bfloat162float(__float2bfloat16_rn(x.y));
        h2 = __bfloat162float(__float2bfloat16_rn(x.z));
        h3 = __bfloat162float(__float2bfloat16_rn(x.w));
        *(uint2*)(smem + AKH + r * QSTR + c0) = make_uint2(packbf(x.x, x.y), packbf(x.z, x.w));
        *(uint2*)(smem + AKL + r * QSTR + c0) =
            make_uint2(packbf(x.x - h0, x.y - h1), packbf(x.z - h2, x.w - h3));
    }
    for (int idx = tid; idx < 1024; idx += 256) {
        int r = idx >> 3, c0 = (idx & 7) * 4;
        int d = dBase + c0;
        float4 s4 = *(const float4*)(scV + d);
        float4 t4 = *(const float4*)(shV + d);
        float4 x = *(const float4*)(v + base + (long)r * 128 + c0);
        float val[4];
        val[0] = x.x * s4.x + t4.x; val[1] = x.y * s4.y + t4.y;
        val[2] = x.z * s4.z + t4.z; val[3] = x.w * s4.w + t4.w;
#pragma unroll
        for (int j = 0; j < 4; j++) {
            __nv_bfloat16 hi = __float2bfloat16_rn(val[j]);
            smem[AVTH + (c0 + j) * PSTR + r] = hi;
            smem[AVTL + (c0 + j) * PSTR + r] =
                __float2bfloat16_rn(val[j] - __bfloat162float(hi));
        }
    }
    __syncthreads();

    const int warp = tid >> 5, lane = tid & 31;
    const int lrow = lane & 15, lhalf = (lane >> 4) * 8;
    const int cr = lane >> 2, cc2 = (lane & 3) * 2;

    const uint32_t uQH = smem_u32(smem + AQH), uQL = smem_u32(smem + AQL);
    const uint32_t uKH = smem_u32(smem + AKH), uKL = smem_u32(smem + AKL);

    // ======== S phase ========
    {
        const int wm = warp >> 2, wn = warp & 3;
        const int m0 = wm * 64, n0 = wn * 32;

        float acc[4][4][4];
#pragma unroll
        for (int mt = 0; mt < 4; mt++)
#pragma unroll
            for (int nt = 0; nt < 4; nt++)
#pragma unroll
                for (int i = 0; i < 4; i++) acc[mt][nt][i] = 0.0f;

#pragma unroll
        for (int ks = 0; ks < 2; ks++) {
            const uint32_t colOff = (uint32_t)(ks * 16 + lhalf) * 2;
            uint32_t bhi[4][2];
#pragma unroll
            for (int g = 0; g < 2; g++) {
                uint32_t r0, r1, r2, r3;
                uint32_t addr = uKH + ((uint32_t)(n0 + g * 16 + lrow) * QSTR) * 2 + colOff;
                LDSM_X4(r0, r1, r2, r3, addr);
                bhi[2 * g][0] = r0; bhi[2 * g][1] = r2;
                bhi[2 * g + 1][0] = r1; bhi[2 * g + 1][1] = r3;
            }
            uint32_t a[4][4];
#pragma unroll
            for (int mt = 0; mt < 4; mt++) {
                uint32_t addr = uQH + ((uint32_t)(m0 + mt * 16 + lrow) * QSTR) * 2 + colOff;
                LDSM_X4(a[mt][0], a[mt][1], a[mt][2], a[mt][3], addr);
            }
#pragma unroll
            for (int mt = 0; mt < 4; mt++)
#pragma unroll
                for (int nt = 0; nt < 4; nt++)
                    mma_bf16(acc[mt][nt], a[mt][0], a[mt][1], a[mt][2], a[mt][3],
                             bhi[nt][0], bhi[nt][1]);
            uint32_t blo[4][2];
#pragma unroll
            for (int g = 0; g < 2; g++) {
                uint32_t r0, r1, r2, r3;
                uint32_t addr = uKL + ((uint32_t)(n0 + g * 16 + lrow) * QSTR) * 2 + colOff;
                LDSM_X4(r0, r1, r2, r3, addr);
                blo[2 * g][0] = r0; blo[2 * g][1] = r2;
                blo[2 * g + 1][0] = r1; blo[2 * g + 1][1] = r3;
            }
#pragma unroll
            for (int mt = 0; mt < 4; mt++)
#pragma unroll
                for (int nt = 0; nt < 4; nt++)
                    mma_bf16(acc[mt][nt], a[mt][0], a[mt][1], a[mt][2], a[mt][3],
                             blo[nt][0], blo[nt][1]);
#pragma unroll
            for (int mt = 0; mt < 4; mt++) {
                uint32_t addr = uQL + ((uint32_t)(m0 + mt * 16 + lrow) * QSTR) * 2 + colOff;
                LDSM_X4(a[mt][0], a[mt][1], a[mt][2], a[mt][3], addr);
            }
#pragma unroll
            for (int mt = 0; mt < 4; mt++)
#pragma unroll
                for (int nt = 0; nt < 4; nt++)
                    mma_bf16(acc[mt][nt], a[mt][0], a[mt][1], a[mt][2], a[mt][3],
                             bhi[nt][0], bhi[nt][1]);
        }

        // ALL warps must finish reading Q/K before P_lo overwrites that region
        __syncthreads();

        // epilogue: mask (gmem), exp, row sums, store P hi/lo (P_lo aliases Q/K)
#pragma unroll
        for (int mt = 0; mt < 4; mt++) {
            const int row0 = m0 + mt * 16 + cr;
            float s0 = 0.0f, s1 = 0.0f;
#pragma unroll
            for (int nt = 0; nt < 4; nt++) {
                const int col = n0 + nt * 8 + cc2;
                float2 mv0 = *(const float2*)(mask + mbase + (long)row0 * 128 + col);
                float2 mv1 = *(const float2*)(mask + mbase + (long)(row0 + 8) * 128 + col);
                float p00 = __expf(acc[mt][nt][0] * mv0.x);
                float p01 = __expf(acc[mt][nt][1] * mv0.y);
                float p10 = __expf(acc[mt][nt][2] * mv1.x);
                float p11 = __expf(acc[mt][nt][3] * mv1.y);
                s0 += p00 + p01;
                s1 += p10 + p11;
                __nv_bfloat16 h00 = __float2bfloat16_rn(p00);
                __nv_bfloat16 h01 = __float2bfloat16_rn(p01);
                __nv_bfloat16 h10 = __float2bfloat16_rn(p10);
                __nv_bfloat16 h11 = __float2bfloat16_rn(p11);
                *(uint32_t*)(smem + APH + row0 * PSTR + col) =
                    packbf(__bfloat162float(h00), __bfloat162float(h01));
                *(uint32_t*)(smem + APH + (row0 + 8) * PSTR + col) =
                    packbf(__bfloat162float(h10), __bfloat162float(h11));
                *(uint32_t*)(smem + APL + row0 * PSTR + col) =
                    packbf(p00 - __bfloat162float(h00), p01 - __bfloat162float(h01));
                *(uint32_t*)(smem + APL + (row0 + 8) * PSTR + col) =
                    packbf(p10 - __bfloat162float(h10), p11 - __bfloat162float(h11));
            }
            s0 += __shfl_xor_sync(0xffffffffu, s0, 1);
            s0 += __shfl_xor_sync(0xffffffffu, s0, 2);
            s1 += __shfl_xor_sync(0xffffffffu, s1, 1);
            s1 += __shfl_xor_sync(0xffffffffu, s1, 2);
            if ((lane & 3) == 0) {
                atomicAdd(&rowsum[row0], s0);
                atomicAdd(&rowsum[row0 + 8], s1);
            }
        }
    }
    __syncthreads();

    // ======== PV phase: 3 passes (Phi*Vhi + Phi*Vlo + Plo*Vhi) ========
    {
        const int m0 = warp * 16;
        const uint32_t uPH = smem_u32(smem + APH), uPL = smem_u32(smem + APL);
        const uint32_t uVH = smem_u32(smem + AVTH), uVL = smem_u32(smem + AVTL);

        float acc[4][4];
#pragma unroll
        for (int nt = 0; nt < 4; nt++)
#pragma unroll
            for (int i = 0; i < 4; i++) acc[nt][i] = 0.0f;

#pragma unroll
        for (int ks = 0; ks < 8; ks++) {
            const uint32_t colOff = (uint32_t)(ks * 16 + lhalf) * 2;
            uint32_t bhi[4][2];
#pragma unroll
            for (int g = 0; g < 2; g++) {
                uint32_t r0, r1, r2, r3;
                uint32_t addr = uVH + ((uint32_t)(g * 16 + lrow) * PSTR) * 2 + colOff;
                LDSM_X4(r0, r1, r2, r3, addr);
                bhi[2 * g][0] = r0; bhi[2 * g][1] = r2;
                bhi[2 * g + 1][0] = r1; bhi[2 * g + 1][1] = r3;
            }
            uint32_t a[4];
            {
                uint32_t addr = uPH + ((uint32_t)(m0 + lrow) * PSTR) * 2 + colOff;
                LDSM_X4(a[0], a[1], a[2], a[3], addr);
            }
#pragma unroll
            for (int nt = 0; nt < 4; nt++)
                mma_bf16(acc[nt], a[0], a[1], a[2], a[3], bhi[nt][0], bhi[nt][1]);
            uint32_t blo[4][2];
#pragma unroll
            for (int g = 0; g < 2; g++) {
                uint32_t r0, r1, r2, r3;
                uint32_t addr = uVL + ((uint32_t)(g * 16 + lrow) * PSTR) * 2 + colOff;
                LDSM_X4(r0, r1, r2, r3, addr);
                blo[2 * g][0] = r0; blo[2 * g][1] = r2;
                blo[2 * g + 1][0] = r1; blo[2 * g + 1][1] = r3;
            }
#pragma unroll
            for (int nt = 0; nt < 4; nt++)
                mma_bf16(acc[nt], a[0], a[1], a[2], a[3], blo[nt][0], blo[nt][1]);
            {
                uint32_t addr = uPL + ((uint32_t)(m0 + lrow) * PSTR) * 2 + colOff;
                LDSM_X4(a[0], a[1], a[2], a[3], addr);
            }
#pragma unroll
            for (int nt = 0; nt < 4; nt++)
                mma_bf16(acc[nt], a[0], a[1], a[2], a[3], bhi[nt][0], bhi[nt][1]);
        }

        const int row0 = m0 + cr;
        const float inv0 = 1.0f / rowsum[row0];
        const float inv1 = 1.0f / rowsum[row0 + 8];
#pragma unroll
        for (int nt = 0; nt < 4; nt++) {
            const int col = nt * 8 + cc2;
            *(float2*)(out + base + (long)row0 * 128 + col) =
                make_float2(acc[nt][0] * inv0, acc[nt][1] * inv0);
            *(float2*)(out + base + (long)(row0 + 8) * 128 + col) =
                make_float2(acc[nt][2] * inv1, acc[nt][3] * inv1);
        }
    }
}

// ---------------- out = LayerNorm(A + affine(B)) per row (affine from raw stats) ----------------
__global__ void add_ln_kernel(const float* __restrict__ A,
                              const float* __restrict__ B,
                              const float* __restrict__ sumB, const float* __restrict__ sqB,
                              const float* __restrict__ gB, const float* __restrict__ bB,
                              const float* __restrict__ gam,
                              const float* __restrict__ bet,
                              float* __restrict__ Out) {
    __shared__ float sc[128], sh[128];
    const int tid = threadIdx.x;
    if (tid < 128) {
        if (gB) bn_affine(sumB, sqB, gB, bB, tid, sc[tid], sh[tid]);
        else { sc[tid] = 1.0f; sh[tid] = 0.0f; }
    }
    __syncthreads();

    const int w = tid >> 5, lane = tid & 31;
    const long row = (long)blockIdx.x * 8 + w;
    const float* a = A + row * 128;
    const float* b = B + row * 128;

    float x[4];
    float s = 0.0f, s2 = 0.0f;
#pragma unroll
    for (int i = 0; i < 4; i++) {
        int c = lane + 32 * i;
        x[i] = a[c] + b[c] * sc[c] + sh[c];
        s += x[i];
        s2 += x[i] * x[i];
    }
#pragma unroll
    for (int o = 16; o > 0; o >>= 1) {
        s  += __shfl_xor_sync(0xffffffffu, s, o);
        s2 += __shfl_xor_sync(0xffffffffu, s2, o);
    }
    const float m = s * (1.0f / 128.0f);
    const float var = s2 * (1.0f / 128.0f) - m * m;
    const float r = rsqrtf(var + EPS);
#pragma unroll
    for (int i = 0; i < 4; i++) {
        int c = lane + 32 * i;
        Out[row * 128 + c] = (x[i] - m) * r * gam[c] + bet[c];
    }
}

// ---------------- h = LN(O + affine_ff(F)) + affine_sk(S), warp per row ----------------
__global__ void ln_add_affine_kernel(const float* __restrict__ O,
                                     const float* __restrict__ F,
                                     const float* __restrict__ sumF, const float* __restrict__ sqF,
                                     const float* __restrict__ gF, const float* __restrict__ bF,
                                     const float* __restrict__ Sk,
                                     const float* __restrict__ sumS, const float* __restrict__ sqS,
                                     const float* __restrict__ gS, const float* __restrict__ bS,
                                     const float* __restrict__ gam,
                                     const float* __restrict__ bet,
                                     float* __restrict__ Out) {
    __shared__ float sc4[128], sh4[128], sc5[128], sh5[128];
    const int tid = threadIdx.x;
    if (tid < 128) {
        bn_affine(sumF, sqF, gF, bF, tid, sc4[tid], sh4[tid]);
    } else {
        int c = tid - 128;
        bn_affine(sumS, sqS, gS, bS, c, sc5[c], sh5[c]);
    }
    __syncthreads();

    const int w = tid >> 5, lane = tid & 31;
    const long row = (long)blockIdx.x * 8 + w;
    const float* o = O + row * 128;
    const float* f = F + row * 128;
    const float* sk = Sk + row * 128;

    float x[4];
    float s = 0.0f, s2 = 0.0f;
#pragma unroll
    for (int i = 0; i < 4; i++) {
        int c = lane + 32 * i;
        x[i] = o[c] + f[c] * sc4[c] + sh4[c];
        s += x[i];
        s2 += x[i] * x[i];
    }
#pragma unroll
    for (int off = 16; off > 0; off >>= 1) {
        s  += __shfl_xor_sync(0xffffffffu, s, off);
        s2 += __shfl_xor_sync(0xffffffffu, s2, off);
    }
    const float m = s * (1.0f / 128.0f);
    const float var = s2 * (1.0f / 128.0f) - m * m;
    const float r = rsqrtf(var + EPS);
#pragma unroll
    for (int i = 0; i < 4; i++) {
        int c = lane + 32 * i;
        Out[row * 128 + c] = (x[i] - m) * r * gam[c] + bet[c] + sk[c] * sc5[c] + sh5[c];
    }
}

// ---------------- gather h[:, 0] -> out[N, D] ----------------
__global__ void gather_kernel(const float* __restrict__ H, float* __restrict__ Out) {
    int i = blockIdx.x * blockDim.x + threadIdx.x;
    int n = i >> 7, d = i & 127;
    Out[i] = H[(long)n * SS * DD + d];
}

// ---------------- host orchestration ----------------
extern "C" void kernel_launch(void* const* d_in, const int* in_sizes, int n_in,
                              void* d_out, int out_size) {
    const float* x        = (const float*)d_in[0];
    const float* mask     = (const float*)d_in[1];
    const float* lin_in_W = (const float*)d_in[2];
    const float* lin_in_b = (const float*)d_in[3];
    const float* in_bn_g  = (const float*)d_in[4];
    const float* in_bn_b  = (const float*)d_in[5];
    const float* q_W      = (const float*)d_in[6];
    const float* q_b      = (const float*)d_in[7];
    const float* q_bn_g   = (const float*)d_in[8];
    const float* q_bn_b   = (const float*)d_in[9];
    const float* k_W      = (const float*)d_in[10];
    const float* k_b      = (const float*)d_in[11];
    const float* k_bn_g   = (const float*)d_in[12];
    const float* k_bn_b   = (const float*)d_in[13];
    const float* v_W      = (const float*)d_in[14];
    const float* v_b      = (const float*)d_in[15];
    const float* v_bn_g   = (const float*)d_in[16];
    const float* v_bn_b   = (const float*)d_in[17];
    const float* ln_g     = (const float*)d_in[18];
    const float* ln_b     = (const float*)d_in[19];
    const float* ff_W     = (const float*)d_in[20];
    const float* ff_b     = (const float*)d_in[21];
    const float* ff_bn_g  = (const float*)d_in[22];
    const float* ff_bn_b  = (const float*)d_in[23];
    const float* skip_W   = (const float*)d_in[24];
    const float* skip_b   = (const float*)d_in[25];
    const float* skip_bn_g= (const float*)d_in[26];
    const float* skip_bn_b= (const float*)d_in[27];
    float* out = (float*)d_out;

    cudaFuncSetAttribute(gemm_tc_kernel, cudaFuncAttributeMaxDynamicSharedMemorySize, GEMM_SMEM);
    cudaFuncSetAttribute(attn_kernel, cudaFuncAttributeMaxDynamicSharedMemorySize, ATTN_SMEM);

    float *bh, *bt, *bq, *bk, *bv, *bs, *ba, *bo, *bf, *bsum, *bsq;
    cudaGetSymbolAddress((void**)&bh, g_h);
    cudaGetSymbolAddress((void**)&bt, g_t);
    cudaGetSymbolAddress((void**)&bq, g_q);
    cudaGetSymbolAddress((void**)&bk, g_k);
    cudaGetSymbolAddress((void**)&bv, g_v);
    cudaGetSymbolAddress((void**)&bs, g_s);
    cudaGetSymbolAddress((void**)&ba, g_a);
    cudaGetSymbolAddress((void**)&bo, g_o);
    cudaGetSymbolAddress((void**)&bf, g_f);
    cudaGetSymbolAddress((void**)&bsum, g_stat_sum);
    cudaGetSymbolAddress((void**)&bsq, g_stat_sq);

    auto SUM = [&](int i) { return bsum + i * DD; };
    auto SQ  = [&](int i) { return bsq + i * DD; };

    const int GEMM_GRID = M_ROWS / 256;   // 512

    // launch 1: zero all stat slots
    zero_stats_kernel<<<(NSLOT * DD + 255) / 256, 256>>>();

    // launch 2: t0 = x @ Win^T + b ; stats -> slot 0
    gemm_tc_kernel<<<GEMM_GRID, 512, GEMM_SMEM>>>(
        x, 0, 0, 0, 0,
        lin_in_W, lin_in_W, lin_in_W, lin_in_W,
        lin_in_b, lin_in_b, lin_in_b, lin_in_b,
        bt, bt, bt, bt,
        SUM(0), SUM(0), SUM(0), SUM(0), SQ(0), SQ(0), SQ(0), SQ(0), 1);

    for (int l = 0; l < LL; l++) {
        const long wOff = (long)l * DD * DD;
        const long vOff = (long)l * DD;
        const float* hp = (l == 0) ? bt : bh;
        const int sq_ = 1 + l * 5, sk_ = 2 + l * 5, sv_ = 3 + l * 5,
                  ss_ = 4 + l * 5, sf_ = 5 + l * 5;
        const float* hSum = (l == 0) ? SUM(0) : 0;
        const float* hSq  = (l == 0) ? SQ(0) : 0;
        const float* hG   = (l == 0) ? in_bn_g : 0;
        const float* hB   = (l == 0) ? in_bn_b : 0;

        // fused Q/K/V/skip GEMM (launch 3 for l=0)
        gemm_tc_kernel<<<GEMM_GRID, 512, GEMM_SMEM>>>(
            hp, hSum, hSq, hG, hB,
            q_W + wOff, k_W + wOff, v_W + wOff, skip_W + wOff,
            q_b + vOff, k_b + vOff, v_b + vOff, skip_b + vOff,
            bq, bk, bv, bs,
            SUM(sq_), SUM(sk_), SUM(sv_), SUM(ss_),
            SQ(sq_), SQ(sk_), SQ(sv_), SQ(ss_), 4);

        // attention (launch 4 for l=0 — ncu target)
        dim3 agrid(HH, NB);
        attn_kernel<<<agrid, 256, ATTN_SMEM>>>(
            bq, bk, bv, mask,
            SUM(sq_), SQ(sq_), q_bn_g + vOff, q_bn_b + vOff,
            SUM(sk_), SQ(sk_), k_bn_g + vOff, k_bn_b + vOff,
            SUM(sv_), SQ(sv_), v_bn_g + vOff, v_bn_b + vOff,
            ba);

        // out = LN(agg + h)
        add_ln_kernel<<<M_ROWS / 8, 256>>>(ba, hp, hSum, hSq, hG, hB,
                                           ln_g + vOff, ln_b + vOff, bo);

        // ff GEMM -> slot sf_
        gemm_tc_kernel<<<GEMM_GRID, 512, GEMM_SMEM>>>(
            bo, 0, 0, 0, 0,
            ff_W + wOff, ff_W + wOff, ff_W + wOff, ff_W + wOff,
            ff_b + vOff, ff_b + vOff, ff_b + vOff, ff_b + vOff,
            bf, bf, bf, bf,
            SUM(sf_), SUM(sf_), SUM(sf_), SUM(sf_),
            SQ(sf_), SQ(sf_), SQ(sf_), SQ(sf_), 1);

        // h = LN(out + affine_ff(ff)) + affine_skip(skip)
        ln_add_affine_kernel<<<M_ROWS / 8, 256>>>(
            bo, bf, SUM(sf_), SQ(sf_), ff_bn_g + vOff, ff_bn_b + vOff,
            bs, SUM(ss_), SQ(ss_), skip_bn_g + vOff, skip_bn_b + vOff,
            ln_g + vOff, ln_b + vOff, bh);
    }

    gather_kernel<<<(NB * DD) / 256, 256>>>(bh, out);
}